// round 4
// baseline (speedup 1.0000x reference)
#include <cuda_runtime.h>
#include <cuda_bf16.h>
#include <cstdint>

#define EMBED 1024
#define NHEAD 16
#define HDIM  64
#define BATCH 2
#define SEQ   2048
#define MROWS (BATCH*SEQ)   // 4096

// ---------------------------------------------------------------------------
// Device-global scratch. bf16 data stored PACKED: u32 = hi_bf16 | lo_bf16<<16,
// value ~= hi + lo (hi = bf16(v), lo = bf16(v - hi)).
// ---------------------------------------------------------------------------
__device__ uint32_t g_x2 [MROWS*EMBED];               // x packed [m][k]
__device__ uint32_t g_w2 [4*EMBED*EMBED];             // W^T packed [4][n][k]
__device__ uint32_t g_q2 [BATCH*NHEAD*SEQ*HDIM];      // Q packed [b,h,s,d] (pre-scaled 0.125)
__device__ uint32_t g_k2 [BATCH*NHEAD*SEQ*HDIM];      // K packed [b,h,s,d]
__device__ uint32_t g_vt2[BATCH*NHEAD*HDIM*SEQ];      // V packed TRANSPOSED [b,h,d,s]
__device__ uint32_t g_c2 [MROWS*EMBED];               // ctx packed [m][e]

// ---------------------------------------------------------------------------
// Helpers
// ---------------------------------------------------------------------------
__device__ __forceinline__ uint32_t prmt(uint32_t a, uint32_t b, uint32_t sel) {
    uint32_t d;
    asm("prmt.b32 %0,%1,%2,%3;" : "=r"(d) : "r"(a), "r"(b), "r"(sel));
    return d;
}
__device__ __forceinline__ uint32_t smem_u32(const void* p) {
    uint32_t a;
    asm("{ .reg .u64 t; cvta.to.shared.u64 t, %1; cvt.u32.u64 %0, t; }"
        : "=r"(a) : "l"(p));
    return a;
}
__device__ __forceinline__ uint32_t pack_hilo(float v) {
    __nv_bfloat16 h = __float2bfloat16(v);
    __nv_bfloat16 l = __float2bfloat16(v - __bfloat162float(h));
    __nv_bfloat162 t(h, l);
    return *reinterpret_cast<uint32_t*>(&t);
}
__device__ __forceinline__ uint32_t pk2(float e0, float e1) {
    uint32_t d;
    asm("cvt.rn.bf16x2.f32 %0, %1, %2;" : "=r"(d) : "f"(e1), "f"(e0));
    return d;
}

#define MMA16816(c, a, b0, b1)                                              \
    asm volatile("mma.sync.aligned.m16n8k16.row.col.f32.bf16.bf16.f32 "     \
        "{%0,%1,%2,%3}, {%4,%5,%6,%7}, {%8,%9}, {%0,%1,%2,%3};"             \
        : "+f"((c)[0]), "+f"((c)[1]), "+f"((c)[2]), "+f"((c)[3])            \
        : "r"((a)[0]), "r"((a)[1]), "r"((a)[2]), "r"((a)[3]),               \
          "r"(b0), "r"(b1))

// ldmatrix x4: matrix_i distributed to all lanes in r_i; per-lane address
// selects: lanes 0-7 -> matrix0 rows, 8-15 -> m1, 16-23 -> m2, 24-31 -> m3.
#define LDSM_X4(r0, r1, r2, r3, addr)                                       \
    asm volatile("ldmatrix.sync.aligned.m8n8.x4.shared.b16 {%0,%1,%2,%3}, [%4];" \
        : "=r"(r0), "=r"(r1), "=r"(r2), "=r"(r3) : "r"(addr))

// ---------------------------------------------------------------------------
// Conversion kernels
// ---------------------------------------------------------------------------
extern "C" __global__ void __launch_bounds__(256)
cvt_x_kernel(const float* __restrict__ src)
{
    int i = (blockIdx.x * 256 + threadIdx.x) * 4;
    float4 v = *reinterpret_cast<const float4*>(src + i);
    uint4 o;
    o.x = pack_hilo(v.x); o.y = pack_hilo(v.y);
    o.z = pack_hilo(v.z); o.w = pack_hilo(v.w);
    *reinterpret_cast<uint4*>(g_x2 + i) = o;
}

extern "C" __global__ void __launch_bounds__(256)
cvt_w_kernel(const float* __restrict__ Wq, const float* __restrict__ Wk,
             const float* __restrict__ Wv, const float* __restrict__ Wo)
{
    __shared__ float t[32][33];
    const float* W = (blockIdx.z == 0) ? Wq : (blockIdx.z == 1) ? Wk :
                     (blockIdx.z == 2) ? Wv : Wo;
    uint32_t* o2 = g_w2 + (size_t)blockIdx.z * EMBED * EMBED;
    int bx = blockIdx.x * 32;  // n base
    int by = blockIdx.y * 32;  // k base
    int tx = threadIdx.x, ty = threadIdx.y;
#pragma unroll
    for (int i = 0; i < 4; i++) {
        int r = ty + i * 8;
        t[r][tx] = W[(size_t)(by + r) * EMBED + bx + tx];
    }
    __syncthreads();
#pragma unroll
    for (int i = 0; i < 4; i++) {
        int r = ty + i * 8;
        o2[(size_t)(bx + r) * EMBED + by + tx] = pack_hilo(t[tx][r]);
    }
}

// ---------------------------------------------------------------------------
// mma.sync split-bf16 GEMM: C[4096,1024] = A @ B^T(+bias)
// 128x128 tile, BK=64, 8 warps (4m x 2n), warp 32x64; ldmatrix fragment loads.
// ---------------------------------------------------------------------------
#define GSMEM_BYTES (4*128*36*4)   // 73728

__device__ __forceinline__ void gemm_mma_body(
    const uint32_t* __restrict__ A2, const uint32_t* __restrict__ B2,
    const float* __restrict__ bias, int mode, float* __restrict__ outf,
    uint32_t* __restrict__ outp, float scale)
{
    extern __shared__ uint32_t sw[];
    uint32_t* Ash = sw;                 // [128][36] u32 words
    uint32_t* Asl = sw + 128*36;
    uint32_t* Bsh = sw + 2*128*36;
    uint32_t* Bsl = sw + 3*128*36;

    const int tid = threadIdx.x;
    const int lane = tid & 31, wid = tid >> 5;
    const int g = lane >> 2, t = lane & 3;
    const int wm = wid & 3, wn = wid >> 2;
    const int m0 = blockIdx.y * 128, n0 = blockIdx.x * 128;

    const uint32_t ash_b = smem_u32(Ash), asl_b = smem_u32(Asl);
    const uint32_t bsh_b = smem_u32(Bsh), bsl_b = smem_u32(Bsl);
    const int grp = lane >> 3, rin = lane & 7;
    const int rowsel = (grp & 1) * 8 + rin;     // row within 16-row tile
    const int khalf = (grp >> 1) * 4;           // word offset for k half

    float acc[2][8][4];
#pragma unroll
    for (int a = 0; a < 2; a++)
#pragma unroll
        for (int b = 0; b < 8; b++)
#pragma unroll
            for (int c = 0; c < 4; c++) acc[a][b][c] = 0.f;

    for (int k0 = 0; k0 < EMBED; k0 += 64) {
#pragma unroll
        for (int i = 0; i < 8; i++) {
            int e4 = i * 256 + tid;
            int r = e4 >> 4, c = (e4 & 15) * 4;
            int w = r * 36 + (c >> 1);
            uint4 va = *reinterpret_cast<const uint4*>(&A2[(size_t)(m0 + r) * EMBED + k0 + c]);
            *reinterpret_cast<uint2*>(&Ash[w]) =
                make_uint2(prmt(va.x, va.y, 0x5410), prmt(va.z, va.w, 0x5410));
            *reinterpret_cast<uint2*>(&Asl[w]) =
                make_uint2(prmt(va.x, va.y, 0x7632), prmt(va.z, va.w, 0x7632));
            uint4 vb = *reinterpret_cast<const uint4*>(&B2[(size_t)(n0 + r) * EMBED + k0 + c]);
            *reinterpret_cast<uint2*>(&Bsh[w]) =
                make_uint2(prmt(vb.x, vb.y, 0x5410), prmt(vb.z, vb.w, 0x5410));
            *reinterpret_cast<uint2*>(&Bsl[w]) =
                make_uint2(prmt(vb.x, vb.y, 0x7632), prmt(vb.z, vb.w, 0x7632));
        }
        __syncthreads();

#pragma unroll
        for (int ks = 0; ks < 4; ks++) {
            uint32_t ah[2][4], al[2][4];
#pragma unroll
            for (int mt = 0; mt < 2; mt++) {
                uint32_t aoff = ((wm * 32 + mt * 16 + rowsel) * 36 + ks * 8 + khalf) * 4;
                LDSM_X4(ah[mt][0], ah[mt][1], ah[mt][2], ah[mt][3], ash_b + aoff);
                LDSM_X4(al[mt][0], al[mt][1], al[mt][2], al[mt][3], asl_b + aoff);
            }
#pragma unroll
            for (int ntp = 0; ntp < 4; ntp++) {
                uint32_t boff = ((wn * 64 + ntp * 16 + rowsel) * 36 + ks * 8 + khalf) * 4;
                uint32_t bh0e, bh0o, bh1e, bh1o, bl0e, bl0o, bl1e, bl1o;
                LDSM_X4(bh0e, bh0o, bh1e, bh1o, bsh_b + boff);
                LDSM_X4(bl0e, bl0o, bl1e, bl1o, bsl_b + boff);
#pragma unroll
                for (int mt = 0; mt < 2; mt++) {
                    MMA16816(acc[mt][2*ntp],   ah[mt], bh0e, bh1e);
                    MMA16816(acc[mt][2*ntp],   ah[mt], bl0e, bl1e);
                    MMA16816(acc[mt][2*ntp],   al[mt], bh0e, bh1e);
                    MMA16816(acc[mt][2*ntp+1], ah[mt], bh0o, bh1o);
                    MMA16816(acc[mt][2*ntp+1], ah[mt], bl0o, bl1o);
                    MMA16816(acc[mt][2*ntp+1], al[mt], bh0o, bh1o);
                }
            }
        }
        __syncthreads();
    }

    // epilogue
#pragma unroll
    for (int mt = 0; mt < 2; mt++) {
#pragma unroll
        for (int nt = 0; nt < 8; nt++) {
            int r0 = m0 + wm * 32 + mt * 16 + g;
            int r1 = r0 + 8;
            int c0 = n0 + wn * 64 + nt * 8 + 2 * t;
            float2 bb = *reinterpret_cast<const float2*>(&bias[c0]);
            float v0 = (acc[mt][nt][0] + bb.x) * scale;
            float v1 = (acc[mt][nt][1] + bb.y) * scale;
            float v2 = (acc[mt][nt][2] + bb.x) * scale;
            float v3 = (acc[mt][nt][3] + bb.y) * scale;
            if (mode == 0) {
                *reinterpret_cast<float2*>(&outf[(size_t)r0 * EMBED + c0]) = make_float2(v0, v1);
                *reinterpret_cast<float2*>(&outf[(size_t)r1 * EMBED + c0]) = make_float2(v2, v3);
            } else if (mode <= 2) {
                int hh = c0 >> 6, d = c0 & 63;
                int b0i = r0 >> 11, s0i = r0 & (SEQ - 1);
                int b1i = r1 >> 11, s1i = r1 & (SEQ - 1);
                *reinterpret_cast<uint2*>(&outp[((size_t)(b0i*NHEAD+hh)*SEQ + s0i)*HDIM + d]) =
                    make_uint2(pack_hilo(v0), pack_hilo(v1));
                *reinterpret_cast<uint2*>(&outp[((size_t)(b1i*NHEAD+hh)*SEQ + s1i)*HDIM + d]) =
                    make_uint2(pack_hilo(v2), pack_hilo(v3));
            } else {
                int hh = c0 >> 6, d = c0 & 63;
                int b0i = r0 >> 11, s0i = r0 & (SEQ - 1);
                int b1i = r1 >> 11, s1i = r1 & (SEQ - 1);
                size_t base0 = (size_t)(b0i*NHEAD+hh)*HDIM*SEQ;
                size_t base1 = (size_t)(b1i*NHEAD+hh)*HDIM*SEQ;
                outp[base0 + (size_t)d * SEQ + s0i]     = pack_hilo(v0);
                outp[base0 + (size_t)(d+1) * SEQ + s0i] = pack_hilo(v1);
                outp[base1 + (size_t)d * SEQ + s1i]     = pack_hilo(v2);
                outp[base1 + (size_t)(d+1) * SEQ + s1i] = pack_hilo(v3);
            }
        }
    }
}

extern "C" __global__ void __launch_bounds__(256, 1)
qkv_mma_kernel(const float* __restrict__ bq, const float* __restrict__ bk,
               const float* __restrict__ bv)
{
    const int z = blockIdx.z;
    const uint32_t* B2 = g_w2 + (size_t)z * EMBED * EMBED;
    const float* bias = (z == 0) ? bq : (z == 1) ? bk : bv;
    uint32_t* outp = (z == 0) ? g_q2 : (z == 1) ? g_k2 : g_vt2;
    int mode = (z == 0) ? 1 : (z == 1) ? 2 : 3;
    float scale = (z == 0) ? 0.125f : 1.0f;
    gemm_mma_body(g_x2, B2, bias, mode, nullptr, outp, scale);
}

extern "C" __global__ void __launch_bounds__(256, 1)
oproj_mma_kernel(const float* __restrict__ bo, float* __restrict__ out)
{
    gemm_mma_body(g_c2, g_w2 + (size_t)3 * EMBED * EMBED, bo, 0, out, nullptr, 1.0f);
}

// ---------------------------------------------------------------------------
// Flash attention on mma.sync, split-bf16, ldmatrix fragment loads.
// 8 warps x m16 q-tiles, TK=128 per iter. Q pre-scaled by 0.125.
// ---------------------------------------------------------------------------
#define AT_KSH 0
#define AT_KSL (128*36)
#define AT_VTH (2*128*36)
#define AT_VTL (2*128*36 + 64*68)
#define AT_MSK (2*128*36 + 2*64*68)
#define ASMEM_WORDS (AT_MSK + 128)
#define ASMEM_BYTES (ASMEM_WORDS*4)

extern "C" __global__ void __launch_bounds__(256, 1)
attn_mma_kernel(const int* __restrict__ mask)
{
    extern __shared__ uint32_t sw[];
    uint32_t* Ksh = sw + AT_KSH;
    uint32_t* Ksl = sw + AT_KSL;
    uint32_t* Vth = sw + AT_VTH;
    uint32_t* Vtl = sw + AT_VTL;
    float*    msk = reinterpret_cast<float*>(sw + AT_MSK);

    const int tid = threadIdx.x, lane = tid & 31, wid = tid >> 5;
    const int g = lane >> 2, t = lane & 3;
    const int b = blockIdx.z, h = blockIdx.y;
    const int q0 = blockIdx.x * 128;
    const int qw = wid * 16;
    const size_t bh = (size_t)(b * NHEAD + h);
    const uint32_t* qb = g_q2 + bh * SEQ * HDIM;
    const uint32_t* kb = g_k2 + bh * SEQ * HDIM;
    const uint32_t* vb = g_vt2 + bh * HDIM * SEQ;
    const int* mb = mask + b * SEQ;

    const uint32_t ksh_b = smem_u32(Ksh), ksl_b = smem_u32(Ksl);
    const uint32_t vth_b = smem_u32(Vth), vtl_b = smem_u32(Vtl);
    const int grp = lane >> 3, rin = lane & 7;
    const int rowsel = (grp & 1) * 8 + rin;
    const int khalf = (grp >> 1) * 4;

    // ---- stage Q split into Ksh/Ksl (temporarily), build register fragments
#pragma unroll
    for (int i = 0; i < 8; i++) {
        int e4 = i * 256 + tid;
        int r = e4 >> 4, c = (e4 & 15) * 4;
        int w = r * 36 + (c >> 1);
        uint4 v = *reinterpret_cast<const uint4*>(&qb[(size_t)(q0 + r) * HDIM + c]);
        *reinterpret_cast<uint2*>(&Ksh[w]) =
            make_uint2(prmt(v.x, v.y, 0x5410), prmt(v.z, v.w, 0x5410));
        *reinterpret_cast<uint2*>(&Ksl[w]) =
            make_uint2(prmt(v.x, v.y, 0x7632), prmt(v.z, v.w, 0x7632));
    }
    __syncthreads();

    uint32_t qh[4][4], ql[4][4];
#pragma unroll
    for (int ks = 0; ks < 4; ks++) {
        uint32_t off = ((qw + rowsel) * 36 + ks * 8 + khalf) * 4;
        LDSM_X4(qh[ks][0], qh[ks][1], qh[ks][2], qh[ks][3], ksh_b + off);
        LDSM_X4(ql[ks][0], ql[ks][1], ql[ks][2], ql[ks][3], ksl_b + off);
    }
    __syncthreads();

    float mrow[2] = {-1e30f, -1e30f};
    float lrow[2] = {0.f, 0.f};
    float o[8][4];
#pragma unroll
    for (int i = 0; i < 8; i++)
#pragma unroll
        for (int j = 0; j < 4; j++) o[i][j] = 0.f;

    for (int s0 = 0; s0 < SEQ; s0 += 128) {
        if (tid < 128) msk[tid] = (float)mb[s0 + tid];
#pragma unroll
        for (int i = 0; i < 8; i++) {
            int e4 = i * 256 + tid;
            int r = e4 >> 4, c = (e4 & 15) * 4;
            int w = r * 36 + (c >> 1);
            uint4 v = *reinterpret_cast<const uint4*>(&kb[(size_t)(s0 + r) * HDIM + c]);
            *reinterpret_cast<uint2*>(&Ksh[w]) =
                make_uint2(prmt(v.x, v.y, 0x5410), prmt(v.z, v.w, 0x5410));
            *reinterpret_cast<uint2*>(&Ksl[w]) =
                make_uint2(prmt(v.x, v.y, 0x7632), prmt(v.z, v.w, 0x7632));
        }
#pragma unroll
        for (int i = 0; i < 8; i++) {
            int e4 = i * 256 + tid;
            int d = e4 >> 5, s = (e4 & 31) * 4;
            int w = d * 68 + (s >> 1);
            uint4 v = *reinterpret_cast<const uint4*>(&vb[(size_t)d * SEQ + s0 + s]);
            *reinterpret_cast<uint2*>(&Vth[w]) =
                make_uint2(prmt(v.x, v.y, 0x5410), prmt(v.z, v.w, 0x5410));
            *reinterpret_cast<uint2*>(&Vtl[w]) =
                make_uint2(prmt(v.x, v.y, 0x7632), prmt(v.z, v.w, 0x7632));
        }
        __syncthreads();

        // ---- S = Q K^T
        float sc[16][4];
#pragma unroll
        for (int nt = 0; nt < 16; nt++)
#pragma unroll
            for (int j = 0; j < 4; j++) sc[nt][j] = 0.f;
#pragma unroll
        for (int ks = 0; ks < 4; ks++) {
#pragma unroll
            for (int ntp = 0; ntp < 8; ntp++) {
                uint32_t off = ((ntp * 16 + rowsel) * 36 + ks * 8 + khalf) * 4;
                uint32_t bh0e, bh0o, bh1e, bh1o, bl0e, bl0o, bl1e, bl1o;
                LDSM_X4(bh0e, bh0o, bh1e, bh1o, ksh_b + off);
                LDSM_X4(bl0e, bl0o, bl1e, bl1o, ksl_b + off);
                MMA16816(sc[2*ntp],   qh[ks], bh0e, bh1e);
                MMA16816(sc[2*ntp],   qh[ks], bl0e, bl1e);
                MMA16816(sc[2*ntp],   ql[ks], bh0e, bh1e);
                MMA16816(sc[2*ntp+1], qh[ks], bh0o, bh1o);
                MMA16816(sc[2*ntp+1], qh[ks], bl0o, bl1o);
                MMA16816(sc[2*ntp+1], ql[ks], bh0o, bh1o);
            }
        }

        // ---- mask
#pragma unroll
        for (int nt = 0; nt < 16; nt++) {
            float2 mv = *reinterpret_cast<float2*>(&msk[nt * 8 + 2 * t]);
            if (mv.x == 0.f) { sc[nt][0] = -1e30f; sc[nt][2] = -1e30f; }
            if (mv.y == 0.f) { sc[nt][1] = -1e30f; sc[nt][3] = -1e30f; }
        }

        // ---- online softmax
        float alpha[2];
#pragma unroll
        for (int rh = 0; rh < 2; rh++) {
            float mt_ = -1e30f;
#pragma unroll
            for (int nt = 0; nt < 16; nt++)
                mt_ = fmaxf(mt_, fmaxf(sc[nt][rh * 2 + 0], sc[nt][rh * 2 + 1]));
            mt_ = fmaxf(mt_, __shfl_xor_sync(0xffffffffu, mt_, 1));
            mt_ = fmaxf(mt_, __shfl_xor_sync(0xffffffffu, mt_, 2));
            float mn = fmaxf(mrow[rh], mt_);
            alpha[rh] = __expf(mrow[rh] - mn);
            float ls = 0.f;
#pragma unroll
            for (int nt = 0; nt < 16; nt++) {
                float p0 = __expf(sc[nt][rh * 2 + 0] - mn);
                float p1 = __expf(sc[nt][rh * 2 + 1] - mn);
                sc[nt][rh * 2 + 0] = p0;
                sc[nt][rh * 2 + 1] = p1;
                ls += p0 + p1;
            }
            ls += __shfl_xor_sync(0xffffffffu, ls, 1);
            ls += __shfl_xor_sync(0xffffffffu, ls, 2);
            lrow[rh] = lrow[rh] * alpha[rh] + ls;
            mrow[rh] = mn;
        }
#pragma unroll
        for (int dt = 0; dt < 8; dt++) {
            o[dt][0] *= alpha[0]; o[dt][1] *= alpha[0];
            o[dt][2] *= alpha[1]; o[dt][3] *= alpha[1];
        }

        // ---- O += P V
#pragma unroll
        for (int j = 0; j < 8; j++) {
            uint32_t ph[4], pl[4];
#pragma unroll
            for (int p = 0; p < 4; p++) {
                int nt = 2 * j + (p >> 1);
                int ix = (p & 1) * 2;
                float e0 = sc[nt][ix], e1 = sc[nt][ix + 1];
                __nv_bfloat16 h0 = __float2bfloat16(e0);
                __nv_bfloat16 h1 = __float2bfloat16(e1);
                __nv_bfloat162 hh(h0, h1);
                ph[p] = *reinterpret_cast<uint32_t*>(&hh);
                pl[p] = pk2(e0 - __bfloat162float(h0), e1 - __bfloat162float(h1));
            }
#pragma unroll
            for (int dtp = 0; dtp < 4; dtp++) {
                uint32_t off = ((dtp * 16 + rowsel) * 68 + j * 8 + khalf) * 4;
                uint32_t vh0e, vh0o, vh1e, vh1o, vl0e, vl0o, vl1e, vl1o;
                LDSM_X4(vh0e, vh0o, vh1e, vh1o, vth_b + off);
                LDSM_X4(vl0e, vl0o, vl1e, vl1o, vtl_b + off);
                MMA16816(o[2*dtp],   ph, vh0e, vh1e);
                MMA16816(o[2*dtp],   pl, vh0e, vh1e);
                MMA16816(o[2*dtp],   ph, vl0e, vl1e);
                MMA16816(o[2*dtp+1], ph, vh0o, vh1o);
                MMA16816(o[2*dtp+1], pl, vh0o, vh1o);
                MMA16816(o[2*dtp+1], ph, vl0o, vl1o);
            }
        }
        __syncthreads();
    }

    // ---- write ctx packed [m][e]
    float inv0 = (lrow[0] > 0.f) ? (1.f / lrow[0]) : 0.f;
    float inv1 = (lrow[1] > 0.f) ? (1.f / lrow[1]) : 0.f;
    int r0 = q0 + qw + g, r1 = r0 + 8;
#pragma unroll
    for (int dt = 0; dt < 8; dt++) {
        int e = h * HDIM + dt * 8 + 2 * t;
        *reinterpret_cast<uint2*>(&g_c2[(size_t)(b * SEQ + r0) * EMBED + e]) =
            make_uint2(pack_hilo(o[dt][0] * inv0), pack_hilo(o[dt][1] * inv0));
        *reinterpret_cast<uint2*>(&g_c2[(size_t)(b * SEQ + r1) * EMBED + e]) =
            make_uint2(pack_hilo(o[dt][2] * inv1), pack_hilo(o[dt][3] * inv1));
    }
}

// ---------------------------------------------------------------------------
extern "C" void kernel_launch(void* const* d_in, const int* in_sizes, int n_in,
                              void* d_out, int out_size)
{
    const float* x    = (const float*)d_in[0];
    const int*   mask = (const int*)d_in[1];
    const float* Wq   = (const float*)d_in[2];
    const float* bq   = (const float*)d_in[3];
    const float* Wk   = (const float*)d_in[4];
    const float* bk   = (const float*)d_in[5];
    const float* Wv   = (const float*)d_in[6];
    const float* bv   = (const float*)d_in[7];
    const float* Wo   = (const float*)d_in[8];
    const float* bo   = (const float*)d_in[9];
    float* out = (float*)d_out;
    (void)in_sizes; (void)n_in; (void)out_size;

    cudaFuncSetAttribute(qkv_mma_kernel,
                         cudaFuncAttributeMaxDynamicSharedMemorySize, GSMEM_BYTES);
    cudaFuncSetAttribute(oproj_mma_kernel,
                         cudaFuncAttributeMaxDynamicSharedMemorySize, GSMEM_BYTES);
    cudaFuncSetAttribute(attn_mma_kernel,
                         cudaFuncAttributeMaxDynamicSharedMemorySize, ASMEM_BYTES);

    cvt_x_kernel<<<(MROWS * EMBED) / 1024, 256>>>(x);
    cvt_w_kernel<<<dim3(32, 32, 4), dim3(32, 8)>>>(Wq, Wk, Wv, Wo);

    dim3 gq(EMBED / 128, MROWS / 128, 3);
    qkv_mma_kernel<<<gq, 256, GSMEM_BYTES>>>(bq, bk, bv);

    dim3 ga(SEQ / 128, NHEAD, BATCH);
    attn_mma_kernel<<<ga, 256, ASMEM_BYTES>>>(mask);

    dim3 go(EMBED / 128, MROWS / 128, 1);
    oproj_mma_kernel<<<go, 256, GSMEM_BYTES>>>(bo, out);
}

// round 5
// speedup vs baseline: 1.1424x; 1.1424x over previous
#include <cuda_runtime.h>
#include <cuda_bf16.h>
#include <cstdint>

#define EMBED 1024
#define NHEAD 16
#define HDIM  64
#define BATCH 2
#define SEQ   2048
#define MROWS (BATCH*SEQ)   // 4096

// ---------------------------------------------------------------------------
// Device-global scratch: hi/lo split stored as SEPARATE bf16 arrays so tiles
// can be staged with raw cp.async (no per-element rearrangement).
// value ~= hi + lo, hi = bf16(v), lo = bf16(v - hi).
// ---------------------------------------------------------------------------
__device__ __nv_bfloat16 g_xh [MROWS*EMBED],          g_xl [MROWS*EMBED];
__device__ __nv_bfloat16 g_wh [4*EMBED*EMBED],        g_wl [4*EMBED*EMBED];
__device__ __nv_bfloat16 g_qh [BATCH*NHEAD*SEQ*HDIM], g_ql [BATCH*NHEAD*SEQ*HDIM];
__device__ __nv_bfloat16 g_kh [BATCH*NHEAD*SEQ*HDIM], g_kl [BATCH*NHEAD*SEQ*HDIM];
__device__ __nv_bfloat16 g_vth[BATCH*NHEAD*HDIM*SEQ], g_vtl[BATCH*NHEAD*HDIM*SEQ];
__device__ __nv_bfloat16 g_ch [MROWS*EMBED],          g_cl [MROWS*EMBED];

// ---------------------------------------------------------------------------
// Helpers
// ---------------------------------------------------------------------------
__device__ __forceinline__ uint32_t smem_u32(const void* p) {
    uint32_t a;
    asm("{ .reg .u64 t; cvta.to.shared.u64 t, %1; cvt.u32.u64 %0, t; }"
        : "=r"(a) : "l"(p));
    return a;
}
__device__ __forceinline__ uint32_t pk2(float e0, float e1) {
    uint32_t d;
    asm("cvt.rn.bf16x2.f32 %0, %1, %2;" : "=r"(d) : "f"(e1), "f"(e0));
    return d;
}

#define MMA16816(c, a, b0, b1)                                              \
    asm volatile("mma.sync.aligned.m16n8k16.row.col.f32.bf16.bf16.f32 "     \
        "{%0,%1,%2,%3}, {%4,%5,%6,%7}, {%8,%9}, {%0,%1,%2,%3};"             \
        : "+f"((c)[0]), "+f"((c)[1]), "+f"((c)[2]), "+f"((c)[3])            \
        : "r"((a)[0]), "r"((a)[1]), "r"((a)[2]), "r"((a)[3]),               \
          "r"(b0), "r"(b1))

#define CP_ASYNC16(dst, src)                                                \
    asm volatile("cp.async.cg.shared.global [%0], [%1], 16;"                \
        :: "r"(dst), "l"(src) : "memory")
#define CP_COMMIT() asm volatile("cp.async.commit_group;" ::: "memory")
#define CP_WAIT(n)  asm volatile("cp.async.wait_group %0;" :: "n"(n) : "memory")

// ---------------------------------------------------------------------------
// Conversion kernels
// ---------------------------------------------------------------------------
extern "C" __global__ void __launch_bounds__(256)
cvt_x_kernel(const float* __restrict__ src)
{
    int i = (blockIdx.x * 256 + threadIdx.x) * 4;
    float4 v = *reinterpret_cast<const float4*>(src + i);
    float vv[4] = {v.x, v.y, v.z, v.w};
    uint32_t hw[2], lw[2];
#pragma unroll
    for (int p = 0; p < 2; p++) {
        float a = vv[2*p], b = vv[2*p+1];
        __nv_bfloat16 ha = __float2bfloat16(a), hb = __float2bfloat16(b);
        __nv_bfloat162 hh(ha, hb);
        hw[p] = *reinterpret_cast<uint32_t*>(&hh);
        lw[p] = pk2(a - __bfloat162float(ha), b - __bfloat162float(hb));
    }
    *reinterpret_cast<uint2*>(g_xh + i) = make_uint2(hw[0], hw[1]);
    *reinterpret_cast<uint2*>(g_xl + i) = make_uint2(lw[0], lw[1]);
}

extern "C" __global__ void __launch_bounds__(256)
cvt_w_kernel(const float* __restrict__ Wq, const float* __restrict__ Wk,
             const float* __restrict__ Wv, const float* __restrict__ Wo)
{
    __shared__ float t[32][33];
    const float* W = (blockIdx.z == 0) ? Wq : (blockIdx.z == 1) ? Wk :
                     (blockIdx.z == 2) ? Wv : Wo;
    __nv_bfloat16* oh = g_wh + (size_t)blockIdx.z * EMBED * EMBED;
    __nv_bfloat16* ol = g_wl + (size_t)blockIdx.z * EMBED * EMBED;
    int bx = blockIdx.x * 32;  // n base
    int by = blockIdx.y * 32;  // k base
    int tx = threadIdx.x, ty = threadIdx.y;
#pragma unroll
    for (int i = 0; i < 4; i++) {
        int r = ty + i * 8;
        t[r][tx] = W[(size_t)(by + r) * EMBED + bx + tx];
    }
    __syncthreads();
#pragma unroll
    for (int i = 0; i < 4; i++) {
        int r = ty + i * 8;
        float v = t[tx][r];
        __nv_bfloat16 h = __float2bfloat16(v);
        size_t o = (size_t)(bx + r) * EMBED + by + tx;
        oh[o] = h;
        ol[o] = __float2bfloat16(v - __bfloat162float(h));
    }
}

// ---------------------------------------------------------------------------
// mma.sync split-bf16 GEMM: C[4096,1024] = A @ B^T(+bias)
// 128x128 tile, BK=64, 8 warps (4m x 2n), warp 32x64. Fragment code = R3.
// Staging: cp.async 16B chunks into double-buffered smem (hi/lo separate).
// ---------------------------------------------------------------------------
#define GW (128*36)                  // words per array per buffer
#define GSMEM2 (2*4*GW*4)            // 147456 B

__device__ __forceinline__ void gemm_stage(
    uint32_t swb, int buf, int tid,
    const __nv_bfloat16* sAh, const __nv_bfloat16* sAl,
    const __nv_bfloat16* sBh, const __nv_bfloat16* sBl, int k0)
{
    const uint32_t dbase = swb + (uint32_t)(buf * 4 * GW) * 4;
#pragma unroll
    for (int j = 0; j < 4; j++) {
        int idx = tid + j * 256;
        int r = idx >> 3, c = idx & 7;
        uint32_t doff = (uint32_t)(r * 36 + c * 4) * 4;
        size_t soff = (size_t)r * EMBED + k0 + c * 8;
        CP_ASYNC16(dbase + doff,               sAh + soff);
        CP_ASYNC16(dbase + (uint32_t)GW*4   + doff, sAl + soff);
        CP_ASYNC16(dbase + (uint32_t)2*GW*4 + doff, sBh + soff);
        CP_ASYNC16(dbase + (uint32_t)3*GW*4 + doff, sBl + soff);
    }
}

__device__ __forceinline__ void gemm_mma_body(
    const __nv_bfloat16* __restrict__ Ah, const __nv_bfloat16* __restrict__ Al,
    const __nv_bfloat16* __restrict__ Bh, const __nv_bfloat16* __restrict__ Bl,
    const float* __restrict__ bias, int mode, float* __restrict__ outf, float scale)
{
    extern __shared__ uint32_t sw[];
    const uint32_t swb = smem_u32(sw);
    const int tid = threadIdx.x;
    const int lane = tid & 31, wid = tid >> 5;
    const int g = lane >> 2, t = lane & 3;
    const int wm = wid & 3, wn = wid >> 2;
    const int m0 = blockIdx.y * 128, n0 = blockIdx.x * 128;

    const __nv_bfloat16* sAh = Ah + (size_t)m0 * EMBED;
    const __nv_bfloat16* sAl = Al + (size_t)m0 * EMBED;
    const __nv_bfloat16* sBh = Bh + (size_t)n0 * EMBED;
    const __nv_bfloat16* sBl = Bl + (size_t)n0 * EMBED;

    float acc[2][8][4];
#pragma unroll
    for (int a = 0; a < 2; a++)
#pragma unroll
        for (int b = 0; b < 8; b++)
#pragma unroll
            for (int c = 0; c < 4; c++) acc[a][b][c] = 0.f;

    gemm_stage(swb, 0, tid, sAh, sAl, sBh, sBl, 0);
    CP_COMMIT();

    for (int it = 0; it < 16; it++) {
        const int buf = it & 1;
        __syncthreads();   // all warps done reading buf^1 from iteration it-1
        if (it + 1 < 16) {
            gemm_stage(swb, buf ^ 1, tid, sAh, sAl, sBh, sBl, (it + 1) * 64);
            CP_COMMIT();
            CP_WAIT(1);
        } else {
            CP_WAIT(0);
        }
        __syncthreads();   // tile it visible to all

        uint32_t* Ash = sw + buf * 4 * GW;
        uint32_t* Asl = Ash + GW;
        uint32_t* Bsh = Ash + 2 * GW;
        uint32_t* Bsl = Ash + 3 * GW;

#pragma unroll
        for (int ks = 0; ks < 4; ks++) {
            uint32_t ah[2][4], al[2][4];
#pragma unroll
            for (int mt = 0; mt < 2; mt++) {
                int r = wm * 32 + mt * 16 + g;
                int base = r * 36 + ks * 8 + t;
                ah[mt][0] = Ash[base];     ah[mt][1] = Ash[base + 8*36];
                ah[mt][2] = Ash[base + 4]; ah[mt][3] = Ash[base + 8*36 + 4];
                al[mt][0] = Asl[base];     al[mt][1] = Asl[base + 8*36];
                al[mt][2] = Asl[base + 4]; al[mt][3] = Asl[base + 8*36 + 4];
            }
#pragma unroll
            for (int nt = 0; nt < 8; nt++) {
                int n = wn * 64 + nt * 8 + g;
                int base = n * 36 + ks * 8 + t;
                uint32_t bh0 = Bsh[base], bh1 = Bsh[base + 4];
                uint32_t bl0 = Bsl[base], bl1 = Bsl[base + 4];
#pragma unroll
                for (int mt = 0; mt < 2; mt++) {
                    MMA16816(acc[mt][nt], ah[mt], bh0, bh1);
                    MMA16816(acc[mt][nt], ah[mt], bl0, bl1);
                    MMA16816(acc[mt][nt], al[mt], bh0, bh1);
                }
            }
        }
    }

    // epilogue
#pragma unroll
    for (int mt = 0; mt < 2; mt++) {
#pragma unroll
        for (int nt = 0; nt < 8; nt++) {
            int r0 = m0 + wm * 32 + mt * 16 + g;
            int r1 = r0 + 8;
            int c0 = n0 + wn * 64 + nt * 8 + 2 * t;
            float2 bb = *reinterpret_cast<const float2*>(&bias[c0]);
            float v0 = (acc[mt][nt][0] + bb.x) * scale;
            float v1 = (acc[mt][nt][1] + bb.y) * scale;
            float v2 = (acc[mt][nt][2] + bb.x) * scale;
            float v3 = (acc[mt][nt][3] + bb.y) * scale;
            if (mode == 0) {
                *reinterpret_cast<float2*>(&outf[(size_t)r0 * EMBED + c0]) = make_float2(v0, v1);
                *reinterpret_cast<float2*>(&outf[(size_t)r1 * EMBED + c0]) = make_float2(v2, v3);
            } else {
                int hh = c0 >> 6, d = c0 & 63;
                int b0i = r0 >> 11, s0i = r0 & (SEQ - 1);
                int b1i = r1 >> 11, s1i = r1 & (SEQ - 1);
                __nv_bfloat16 h0 = __float2bfloat16(v0), h1 = __float2bfloat16(v1);
                __nv_bfloat16 h2 = __float2bfloat16(v2), h3 = __float2bfloat16(v3);
                uint32_t l01 = pk2(v0 - __bfloat162float(h0), v1 - __bfloat162float(h1));
                uint32_t l23 = pk2(v2 - __bfloat162float(h2), v3 - __bfloat162float(h3));
                if (mode <= 2) {
                    __nv_bfloat16* oh = (mode == 1) ? g_qh : g_kh;
                    __nv_bfloat16* ol = (mode == 1) ? g_ql : g_kl;
                    size_t o0 = ((size_t)(b0i*NHEAD+hh)*SEQ + s0i)*HDIM + d;
                    size_t o1 = ((size_t)(b1i*NHEAD+hh)*SEQ + s1i)*HDIM + d;
                    __nv_bfloat162 hp0(h0, h1), hp1(h2, h3);
                    *reinterpret_cast<__nv_bfloat162*>(oh + o0) = hp0;
                    *reinterpret_cast<uint32_t*>(ol + o0) = l01;
                    *reinterpret_cast<__nv_bfloat162*>(oh + o1) = hp1;
                    *reinterpret_cast<uint32_t*>(ol + o1) = l23;
                } else {
                    size_t base0 = (size_t)(b0i*NHEAD+hh)*HDIM*SEQ;
                    size_t base1 = (size_t)(b1i*NHEAD+hh)*HDIM*SEQ;
                    g_vth[base0 + (size_t)d * SEQ + s0i]     = h0;
                    g_vth[base0 + (size_t)(d+1) * SEQ + s0i] = h1;
                    g_vth[base1 + (size_t)d * SEQ + s1i]     = h2;
                    g_vth[base1 + (size_t)(d+1) * SEQ + s1i] = h3;
                    g_vtl[base0 + (size_t)d * SEQ + s0i]     = __float2bfloat16(v0 - __bfloat162float(h0));
                    g_vtl[base0 + (size_t)(d+1) * SEQ + s0i] = __float2bfloat16(v1 - __bfloat162float(h1));
                    g_vtl[base1 + (size_t)d * SEQ + s1i]     = __float2bfloat16(v2 - __bfloat162float(h2));
                    g_vtl[base1 + (size_t)(d+1) * SEQ + s1i] = __float2bfloat16(v3 - __bfloat162float(h3));
                }
            }
        }
    }
}

extern "C" __global__ void __launch_bounds__(256, 1)
qkv_mma_kernel(const float* __restrict__ bq, const float* __restrict__ bk,
               const float* __restrict__ bv)
{
    const int z = blockIdx.z;
    const __nv_bfloat16* Bh = g_wh + (size_t)z * EMBED * EMBED;
    const __nv_bfloat16* Bl = g_wl + (size_t)z * EMBED * EMBED;
    const float* bias = (z == 0) ? bq : (z == 1) ? bk : bv;
    int mode = (z == 0) ? 1 : (z == 1) ? 2 : 3;
    float scale = (z == 0) ? 0.125f : 1.0f;   // fold 1/sqrt(64) into Q
    gemm_mma_body(g_xh, g_xl, Bh, Bl, bias, mode, nullptr, scale);
}

extern "C" __global__ void __launch_bounds__(256, 1)
oproj_mma_kernel(const float* __restrict__ bo, float* __restrict__ out)
{
    gemm_mma_body(g_ch, g_cl, g_wh + (size_t)3 * EMBED * EMBED,
                  g_wl + (size_t)3 * EMBED * EMBED, bo, 0, out, 1.0f);
}

// ---------------------------------------------------------------------------
// Flash attention, fragment code identical to R3; staging via cp.async with
// double-buffered K/V tiles; whole mask row cached in smem.
// ---------------------------------------------------------------------------
#define KW (128*36)
#define VW (64*68)
#define ABUFW (2*KW + 2*VW)                     // 17920 words per buffer
#define ASMEM2 ((2*ABUFW + SEQ)*4)              // + mask floats

__device__ __forceinline__ void attn_stage_kv(
    uint32_t swb, int buf, int tid,
    const __nv_bfloat16* kh, const __nv_bfloat16* kl,
    const __nv_bfloat16* vth, const __nv_bfloat16* vtl, int s0)
{
    const uint32_t dbase = swb + (uint32_t)(buf * ABUFW) * 4;
#pragma unroll
    for (int j = 0; j < 4; j++) {
        int idx = tid + j * 256;
        {   // K: 1024 chunks per array
            int r = idx >> 3, c = idx & 7;
            uint32_t doff = (uint32_t)(r * 36 + c * 4) * 4;
            size_t soff = (size_t)(s0 + r) * HDIM + c * 8;
            CP_ASYNC16(dbase + doff,                kh + soff);
            CP_ASYNC16(dbase + (uint32_t)KW*4 + doff, kl + soff);
        }
        {   // Vt: 1024 chunks per array
            int d = idx >> 4, c = idx & 15;
            uint32_t doff = (uint32_t)(2*KW + d * 68 + c * 4) * 4;
            size_t soff = (size_t)d * SEQ + s0 + c * 8;
            CP_ASYNC16(dbase + doff,                vth + soff);
            CP_ASYNC16(dbase + (uint32_t)VW*4 + doff, vtl + soff);
        }
    }
}

extern "C" __global__ void __launch_bounds__(256, 1)
attn_mma_kernel(const int* __restrict__ mask)
{
    extern __shared__ uint32_t sw[];
    const uint32_t swb = smem_u32(sw);
    float* mskf = reinterpret_cast<float*>(sw + 2 * ABUFW);

    const int tid = threadIdx.x, lane = tid & 31, wid = tid >> 5;
    const int g = lane >> 2, t = lane & 3;
    const int b = blockIdx.z, h = blockIdx.y;
    const int q0 = blockIdx.x * 128;
    const int qw = wid * 16;
    const size_t bh = (size_t)(b * NHEAD + h);
    const __nv_bfloat16* qhp = g_qh + bh * SEQ * HDIM;
    const __nv_bfloat16* qlp = g_ql + bh * SEQ * HDIM;
    const __nv_bfloat16* khp = g_kh + bh * SEQ * HDIM;
    const __nv_bfloat16* klp = g_kl + bh * SEQ * HDIM;
    const __nv_bfloat16* vhp = g_vth + bh * HDIM * SEQ;
    const __nv_bfloat16* vlp = g_vtl + bh * HDIM * SEQ;
    const int* mb = mask + b * SEQ;

    // ---- mask row to smem (once)
#pragma unroll
    for (int i = 0; i < SEQ / 256; i++)
        mskf[tid + i * 256] = (float)mb[tid + i * 256];

    // ---- stage Q (hi/lo) into buffer0 K-area, extract fragments
#pragma unroll
    for (int j = 0; j < 4; j++) {
        int idx = tid + j * 256;
        int r = idx >> 3, c = idx & 7;
        uint32_t doff = (uint32_t)(r * 36 + c * 4) * 4;
        size_t soff = (size_t)(q0 + r) * HDIM + c * 8;
        CP_ASYNC16(swb + doff,                  qhp + soff);
        CP_ASYNC16(swb + (uint32_t)KW*4 + doff, qlp + soff);
    }
    CP_COMMIT();
    CP_WAIT(0);
    __syncthreads();

    uint32_t qh[4][4], ql[4][4];
    {
        uint32_t* Qh = sw;
        uint32_t* Ql = sw + KW;
#pragma unroll
        for (int ks = 0; ks < 4; ks++) {
#pragma unroll
            for (int p = 0; p < 4; p++) {
                int row = qw + g + ((p & 1) ? 8 : 0);
                int col = ks * 8 + t + ((p >= 2) ? 4 : 0);
                qh[ks][p] = Qh[row * 36 + col];
                ql[ks][p] = Ql[row * 36 + col];
            }
        }
    }
    __syncthreads();

    // prefetch tile 0
    attn_stage_kv(swb, 0, tid, khp, klp, vhp, vlp, 0);
    CP_COMMIT();

    float mrow[2] = {-1e30f, -1e30f};
    float lrow[2] = {0.f, 0.f};
    float o[8][4];
#pragma unroll
    for (int i = 0; i < 8; i++)
#pragma unroll
        for (int j = 0; j < 4; j++) o[i][j] = 0.f;

    for (int it = 0; it < 16; it++) {
        const int buf = it & 1;
        const int s0 = it * 128;
        __syncthreads();   // everyone done reading buf^1
        if (it + 1 < 16) {
            attn_stage_kv(swb, buf ^ 1, tid, khp, klp, vhp, vlp, (it + 1) * 128);
            CP_COMMIT();
            CP_WAIT(1);
        } else {
            CP_WAIT(0);
        }
        __syncthreads();   // tile it visible

        uint32_t* Ksh = sw + buf * ABUFW;
        uint32_t* Ksl = Ksh + KW;
        uint32_t* Vth = Ksh + 2 * KW;
        uint32_t* Vtl = Ksh + 2 * KW + VW;

        // ---- S = Q K^T
        float sc[16][4];
#pragma unroll
        for (int nt = 0; nt < 16; nt++)
#pragma unroll
            for (int j = 0; j < 4; j++) sc[nt][j] = 0.f;
#pragma unroll
        for (int ks = 0; ks < 4; ks++) {
#pragma unroll
            for (int nt = 0; nt < 16; nt++) {
                int base = (nt * 8 + g) * 36 + ks * 8 + t;
                uint32_t b0 = Ksh[base], b1 = Ksh[base + 4];
                uint32_t c0 = Ksl[base], c1 = Ksl[base + 4];
                MMA16816(sc[nt], qh[ks], b0, b1);
                MMA16816(sc[nt], qh[ks], c0, c1);
                MMA16816(sc[nt], ql[ks], b0, b1);
            }
        }

        // ---- mask
#pragma unroll
        for (int nt = 0; nt < 16; nt++) {
            float2 mv = *reinterpret_cast<float2*>(&mskf[s0 + nt * 8 + 2 * t]);
            if (mv.x == 0.f) { sc[nt][0] = -1e30f; sc[nt][2] = -1e30f; }
            if (mv.y == 0.f) { sc[nt][1] = -1e30f; sc[nt][3] = -1e30f; }
        }

        // ---- online softmax
        float alpha[2];
#pragma unroll
        for (int rh = 0; rh < 2; rh++) {
            float mt_ = -1e30f;
#pragma unroll
            for (int nt = 0; nt < 16; nt++)
                mt_ = fmaxf(mt_, fmaxf(sc[nt][rh * 2 + 0], sc[nt][rh * 2 + 1]));
            mt_ = fmaxf(mt_, __shfl_xor_sync(0xffffffffu, mt_, 1));
            mt_ = fmaxf(mt_, __shfl_xor_sync(0xffffffffu, mt_, 2));
            float mn = fmaxf(mrow[rh], mt_);
            alpha[rh] = __expf(mrow[rh] - mn);
            float ls = 0.f;
#pragma unroll
            for (int nt = 0; nt < 16; nt++) {
                float p0 = __expf(sc[nt][rh * 2 + 0] - mn);
                float p1 = __expf(sc[nt][rh * 2 + 1] - mn);
                sc[nt][rh * 2 + 0] = p0;
                sc[nt][rh * 2 + 1] = p1;
                ls += p0 + p1;
            }
            ls += __shfl_xor_sync(0xffffffffu, ls, 1);
            ls += __shfl_xor_sync(0xffffffffu, ls, 2);
            lrow[rh] = lrow[rh] * alpha[rh] + ls;
            mrow[rh] = mn;
        }
#pragma unroll
        for (int dt = 0; dt < 8; dt++) {
            o[dt][0] *= alpha[0]; o[dt][1] *= alpha[0];
            o[dt][2] *= alpha[1]; o[dt][3] *= alpha[1];
        }

        // ---- O += P V
#pragma unroll
        for (int j = 0; j < 8; j++) {
            uint32_t ph[4], pl[4];
#pragma unroll
            for (int p = 0; p < 4; p++) {
                int nt = 2 * j + (p >> 1);
                int ix = (p & 1) * 2;
                float e0 = sc[nt][ix], e1 = sc[nt][ix + 1];
                __nv_bfloat16 h0 = __float2bfloat16(e0);
                __nv_bfloat16 h1 = __float2bfloat16(e1);
                __nv_bfloat162 hh(h0, h1);
                ph[p] = *reinterpret_cast<uint32_t*>(&hh);
                pl[p] = pk2(e0 - __bfloat162float(h0), e1 - __bfloat162float(h1));
            }
#pragma unroll
            for (int dt = 0; dt < 8; dt++) {
                int base = (dt * 8 + g) * 68 + j * 8 + t;
                uint32_t v0 = Vth[base], v1 = Vth[base + 4];
                uint32_t w0 = Vtl[base], w1 = Vtl[base + 4];
                MMA16816(o[dt], ph, v0, v1);
                MMA16816(o[dt], pl, v0, v1);
                MMA16816(o[dt], ph, w0, w1);
            }
        }
    }

    // ---- write ctx (hi/lo) [m][e]
    float inv0 = (lrow[0] > 0.f) ? (1.f / lrow[0]) : 0.f;
    float inv1 = (lrow[1] > 0.f) ? (1.f / lrow[1]) : 0.f;
    int r0 = q0 + qw + g, r1 = r0 + 8;
#pragma unroll
    for (int dt = 0; dt < 8; dt++) {
        int e = h * HDIM + dt * 8 + 2 * t;
        float v0 = o[dt][0] * inv0, v1 = o[dt][1] * inv0;
        float v2 = o[dt][2] * inv1, v3 = o[dt][3] * inv1;
        __nv_bfloat16 h0 = __float2bfloat16(v0), h1 = __float2bfloat16(v1);
        __nv_bfloat16 h2 = __float2bfloat16(v2), h3 = __float2bfloat16(v3);
        __nv_bfloat162 hp0(h0, h1), hp1(h2, h3);
        *reinterpret_cast<__nv_bfloat162*>(&g_ch[(size_t)(b * SEQ + r0) * EMBED + e]) = hp0;
        *reinterpret_cast<uint32_t*>(&g_cl[(size_t)(b * SEQ + r0) * EMBED + e]) =
            pk2(v0 - __bfloat162float(h0), v1 - __bfloat162float(h1));
        *reinterpret_cast<__nv_bfloat162*>(&g_ch[(size_t)(b * SEQ + r1) * EMBED + e]) = hp1;
        *reinterpret_cast<uint32_t*>(&g_cl[(size_t)(b * SEQ + r1) * EMBED + e]) =
            pk2(v2 - __bfloat162float(h2), v3 - __bfloat162float(h3));
    }
}

// ---------------------------------------------------------------------------
extern "C" void kernel_launch(void* const* d_in, const int* in_sizes, int n_in,
                              void* d_out, int out_size)
{
    const float* x    = (const float*)d_in[0];
    const int*   mask = (const int*)d_in[1];
    const float* Wq   = (const float*)d_in[2];
    const float* bq   = (const float*)d_in[3];
    const float* Wk   = (const float*)d_in[4];
    const float* bk   = (const float*)d_in[5];
    const float* Wv   = (const float*)d_in[6];
    const float* bv   = (const float*)d_in[7];
    const float* Wo   = (const float*)d_in[8];
    const float* bo   = (const float*)d_in[9];
    float* out = (float*)d_out;
    (void)in_sizes; (void)n_in; (void)out_size;

    cudaFuncSetAttribute(qkv_mma_kernel,
                         cudaFuncAttributeMaxDynamicSharedMemorySize, GSMEM2);
    cudaFuncSetAttribute(oproj_mma_kernel,
                         cudaFuncAttributeMaxDynamicSharedMemorySize, GSMEM2);
    cudaFuncSetAttribute(attn_mma_kernel,
                         cudaFuncAttributeMaxDynamicSharedMemorySize, ASMEM2);

    cvt_x_kernel<<<(MROWS * EMBED) / 1024, 256>>>(x);
    cvt_w_kernel<<<dim3(32, 32, 4), dim3(32, 8)>>>(Wq, Wk, Wv, Wo);

    dim3 gq(EMBED / 128, MROWS / 128, 3);
    qkv_mma_kernel<<<gq, 256, GSMEM2>>>(bq, bk, bv);

    dim3 ga(SEQ / 128, NHEAD, BATCH);
    attn_mma_kernel<<<ga, 256, ASMEM2>>>(mask);

    dim3 go(EMBED / 128, MROWS / 128, 1);
    oproj_mma_kernel<<<go, 256, GSMEM2>>>(bo, out);
}

// round 6
// speedup vs baseline: 1.1618x; 1.0169x over previous
#include <cuda_runtime.h>
#include <cuda_bf16.h>
#include <cstdint>

#define EMBED 1024
#define NHEAD 16
#define HDIM  64
#define BATCH 2
#define SEQ   2048
#define MROWS (BATCH*SEQ)   // 4096

// ---------------------------------------------------------------------------
// Device-global scratch: hi/lo split stored as SEPARATE bf16 arrays so tiles
// can be staged with raw cp.async. value ~= hi + lo.
// ---------------------------------------------------------------------------
__device__ __nv_bfloat16 g_xh [MROWS*EMBED],          g_xl [MROWS*EMBED];
__device__ __nv_bfloat16 g_wh [4*EMBED*EMBED],        g_wl [4*EMBED*EMBED];
__device__ __nv_bfloat16 g_qh [BATCH*NHEAD*SEQ*HDIM], g_ql [BATCH*NHEAD*SEQ*HDIM];
__device__ __nv_bfloat16 g_kh [BATCH*NHEAD*SEQ*HDIM], g_kl [BATCH*NHEAD*SEQ*HDIM];
__device__ __nv_bfloat16 g_vth[BATCH*NHEAD*HDIM*SEQ], g_vtl[BATCH*NHEAD*HDIM*SEQ];
__device__ __nv_bfloat16 g_ch [MROWS*EMBED],          g_cl [MROWS*EMBED];

// ---------------------------------------------------------------------------
// Helpers
// ---------------------------------------------------------------------------
__device__ __forceinline__ uint32_t smem_u32(const void* p) {
    uint32_t a;
    asm("{ .reg .u64 t; cvta.to.shared.u64 t, %1; cvt.u32.u64 %0, t; }"
        : "=r"(a) : "l"(p));
    return a;
}
__device__ __forceinline__ uint32_t pk2(float e0, float e1) {
    uint32_t d;
    asm("cvt.rn.bf16x2.f32 %0, %1, %2;" : "=r"(d) : "f"(e1), "f"(e0));
    return d;
}
__device__ __forceinline__ float ex2(float x) {   // exp2, same unit __expf uses
    float r;
    asm("ex2.approx.f32 %0, %1;" : "=f"(r) : "f"(x));
    return r;
}

// NOTE: NOT volatile — register-only in/out, lets ptxas schedule/interleave.
#define MMA16816(c, a, b0, b1)                                              \
    asm("mma.sync.aligned.m16n8k16.row.col.f32.bf16.bf16.f32 "              \
        "{%0,%1,%2,%3}, {%4,%5,%6,%7}, {%8,%9}, {%0,%1,%2,%3};"             \
        : "+f"((c)[0]), "+f"((c)[1]), "+f"((c)[2]), "+f"((c)[3])            \
        : "r"((a)[0]), "r"((a)[1]), "r"((a)[2]), "r"((a)[3]),               \
          "r"(b0), "r"(b1))

#define CP_ASYNC16(dst, src)                                                \
    asm volatile("cp.async.cg.shared.global [%0], [%1], 16;"                \
        :: "r"(dst), "l"(src) : "memory")
#define CP_COMMIT() asm volatile("cp.async.commit_group;" ::: "memory")
#define CP_WAIT(n)  asm volatile("cp.async.wait_group %0;" :: "n"(n) : "memory")

#define QSCALE 0.180336880111120419f   // 0.125 * log2(e): base-2 softmax domain

// ---------------------------------------------------------------------------
// Conversion kernels
// ---------------------------------------------------------------------------
extern "C" __global__ void __launch_bounds__(256)
cvt_x_kernel(const float* __restrict__ src)
{
    int i = (blockIdx.x * 256 + threadIdx.x) * 4;
    float4 v = *reinterpret_cast<const float4*>(src + i);
    float vv[4] = {v.x, v.y, v.z, v.w};
    uint32_t hw[2], lw[2];
#pragma unroll
    for (int p = 0; p < 2; p++) {
        float a = vv[2*p], b = vv[2*p+1];
        __nv_bfloat16 ha = __float2bfloat16(a), hb = __float2bfloat16(b);
        __nv_bfloat162 hh(ha, hb);
        hw[p] = *reinterpret_cast<uint32_t*>(&hh);
        lw[p] = pk2(a - __bfloat162float(ha), b - __bfloat162float(hb));
    }
    *reinterpret_cast<uint2*>(g_xh + i) = make_uint2(hw[0], hw[1]);
    *reinterpret_cast<uint2*>(g_xl + i) = make_uint2(lw[0], lw[1]);
}

extern "C" __global__ void __launch_bounds__(256)
cvt_w_kernel(const float* __restrict__ Wq, const float* __restrict__ Wk,
             const float* __restrict__ Wv, const float* __restrict__ Wo)
{
    __shared__ float t[32][33];
    const float* W = (blockIdx.z == 0) ? Wq : (blockIdx.z == 1) ? Wk :
                     (blockIdx.z == 2) ? Wv : Wo;
    __nv_bfloat16* oh = g_wh + (size_t)blockIdx.z * EMBED * EMBED;
    __nv_bfloat16* ol = g_wl + (size_t)blockIdx.z * EMBED * EMBED;
    int bx = blockIdx.x * 32;  // n base
    int by = blockIdx.y * 32;  // k base
    int tx = threadIdx.x, ty = threadIdx.y;
#pragma unroll
    for (int i = 0; i < 4; i++) {
        int r = ty + i * 8;
        t[r][tx] = W[(size_t)(by + r) * EMBED + bx + tx];
    }
    __syncthreads();
#pragma unroll
    for (int i = 0; i < 4; i++) {
        int r = ty + i * 8;
        float v = t[tx][r];
        __nv_bfloat16 h = __float2bfloat16(v);
        size_t o = (size_t)(bx + r) * EMBED + by + tx;
        oh[o] = h;
        ol[o] = __float2bfloat16(v - __bfloat162float(h));
    }
}

// ---------------------------------------------------------------------------
// mma.sync split-bf16 GEMM: C[4096,1024] = A @ B^T(+bias)
// 128x128 tile, BK=64, 8 warps (4m x 2n), warp 32x64.
// cp.async double-buffered staging; MMAs interleaved across accumulators.
// ---------------------------------------------------------------------------
#define GW (128*36)                  // words per array per buffer
#define GSMEM2 (2*4*GW*4)            // 147456 B

__device__ __forceinline__ void gemm_stage(
    uint32_t swb, int buf, int tid,
    const __nv_bfloat16* sAh, const __nv_bfloat16* sAl,
    const __nv_bfloat16* sBh, const __nv_bfloat16* sBl, int k0)
{
    const uint32_t dbase = swb + (uint32_t)(buf * 4 * GW) * 4;
#pragma unroll
    for (int j = 0; j < 4; j++) {
        int idx = tid + j * 256;
        int r = idx >> 3, c = idx & 7;
        uint32_t doff = (uint32_t)(r * 36 + c * 4) * 4;
        size_t soff = (size_t)r * EMBED + k0 + c * 8;
        CP_ASYNC16(dbase + doff,               sAh + soff);
        CP_ASYNC16(dbase + (uint32_t)GW*4   + doff, sAl + soff);
        CP_ASYNC16(dbase + (uint32_t)2*GW*4 + doff, sBh + soff);
        CP_ASYNC16(dbase + (uint32_t)3*GW*4 + doff, sBl + soff);
    }
}

__device__ __forceinline__ void gemm_mma_body(
    const __nv_bfloat16* __restrict__ Ah, const __nv_bfloat16* __restrict__ Al,
    const __nv_bfloat16* __restrict__ Bh, const __nv_bfloat16* __restrict__ Bl,
    const float* __restrict__ bias, int mode, float* __restrict__ outf, float scale)
{
    extern __shared__ uint32_t sw[];
    const uint32_t swb = smem_u32(sw);
    const int tid = threadIdx.x;
    const int lane = tid & 31, wid = tid >> 5;
    const int g = lane >> 2, t = lane & 3;
    const int wm = wid & 3, wn = wid >> 2;
    const int m0 = blockIdx.y * 128, n0 = blockIdx.x * 128;

    const __nv_bfloat16* sAh = Ah + (size_t)m0 * EMBED;
    const __nv_bfloat16* sAl = Al + (size_t)m0 * EMBED;
    const __nv_bfloat16* sBh = Bh + (size_t)n0 * EMBED;
    const __nv_bfloat16* sBl = Bl + (size_t)n0 * EMBED;

    float acc[2][8][4];
#pragma unroll
    for (int a = 0; a < 2; a++)
#pragma unroll
        for (int b = 0; b < 8; b++)
#pragma unroll
            for (int c = 0; c < 4; c++) acc[a][b][c] = 0.f;

    gemm_stage(swb, 0, tid, sAh, sAl, sBh, sBl, 0);
    CP_COMMIT();

    for (int it = 0; it < 16; it++) {
        const int buf = it & 1;
        __syncthreads();
        if (it + 1 < 16) {
            gemm_stage(swb, buf ^ 1, tid, sAh, sAl, sBh, sBl, (it + 1) * 64);
            CP_COMMIT();
            CP_WAIT(1);
        } else {
            CP_WAIT(0);
        }
        __syncthreads();

        uint32_t* Ash = sw + buf * 4 * GW;
        uint32_t* Asl = Ash + GW;
        uint32_t* Bsh = Ash + 2 * GW;
        uint32_t* Bsl = Ash + 3 * GW;

#pragma unroll
        for (int ks = 0; ks < 4; ks++) {
            uint32_t ah[2][4], al[2][4];
#pragma unroll
            for (int mt = 0; mt < 2; mt++) {
                int r = wm * 32 + mt * 16 + g;
                int base = r * 36 + ks * 8 + t;
                ah[mt][0] = Ash[base];     ah[mt][1] = Ash[base + 8*36];
                ah[mt][2] = Ash[base + 4]; ah[mt][3] = Ash[base + 8*36 + 4];
                al[mt][0] = Asl[base];     al[mt][1] = Asl[base + 8*36];
                al[mt][2] = Asl[base + 4]; al[mt][3] = Asl[base + 8*36 + 4];
            }
            // nt in pairs: 4 independent accs (2nt x 2mt) per product pass
#pragma unroll
            for (int ntp = 0; ntp < 4; ntp++) {
                uint32_t b0[2], b1[2], c0[2], c1[2];
#pragma unroll
                for (int q = 0; q < 2; q++) {
                    int n = wn * 64 + (2 * ntp + q) * 8 + g;
                    int base = n * 36 + ks * 8 + t;
                    b0[q] = Bsh[base]; b1[q] = Bsh[base + 4];
                    c0[q] = Bsl[base]; c1[q] = Bsl[base + 4];
                }
#pragma unroll
                for (int q = 0; q < 2; q++)
#pragma unroll
                    for (int mt = 0; mt < 2; mt++)
                        MMA16816(acc[mt][2*ntp+q], ah[mt], b0[q], b1[q]);
#pragma unroll
                for (int q = 0; q < 2; q++)
#pragma unroll
                    for (int mt = 0; mt < 2; mt++)
                        MMA16816(acc[mt][2*ntp+q], ah[mt], c0[q], c1[q]);
#pragma unroll
                for (int q = 0; q < 2; q++)
#pragma unroll
                    for (int mt = 0; mt < 2; mt++)
                        MMA16816(acc[mt][2*ntp+q], al[mt], b0[q], b1[q]);
            }
        }
    }

    // epilogue
#pragma unroll
    for (int mt = 0; mt < 2; mt++) {
#pragma unroll
        for (int nt = 0; nt < 8; nt++) {
            int r0 = m0 + wm * 32 + mt * 16 + g;
            int r1 = r0 + 8;
            int c0 = n0 + wn * 64 + nt * 8 + 2 * t;
            float2 bb = *reinterpret_cast<const float2*>(&bias[c0]);
            float v0 = (acc[mt][nt][0] + bb.x) * scale;
            float v1 = (acc[mt][nt][1] + bb.y) * scale;
            float v2 = (acc[mt][nt][2] + bb.x) * scale;
            float v3 = (acc[mt][nt][3] + bb.y) * scale;
            if (mode == 0) {
                *reinterpret_cast<float2*>(&outf[(size_t)r0 * EMBED + c0]) = make_float2(v0, v1);
                *reinterpret_cast<float2*>(&outf[(size_t)r1 * EMBED + c0]) = make_float2(v2, v3);
            } else {
                int hh = c0 >> 6, d = c0 & 63;
                int b0i = r0 >> 11, s0i = r0 & (SEQ - 1);
                int b1i = r1 >> 11, s1i = r1 & (SEQ - 1);
                __nv_bfloat16 h0 = __float2bfloat16(v0), h1 = __float2bfloat16(v1);
                __nv_bfloat16 h2 = __float2bfloat16(v2), h3 = __float2bfloat16(v3);
                uint32_t l01 = pk2(v0 - __bfloat162float(h0), v1 - __bfloat162float(h1));
                uint32_t l23 = pk2(v2 - __bfloat162float(h2), v3 - __bfloat162float(h3));
                if (mode <= 2) {
                    __nv_bfloat16* oh = (mode == 1) ? g_qh : g_kh;
                    __nv_bfloat16* ol = (mode == 1) ? g_ql : g_kl;
                    size_t o0 = ((size_t)(b0i*NHEAD+hh)*SEQ + s0i)*HDIM + d;
                    size_t o1 = ((size_t)(b1i*NHEAD+hh)*SEQ + s1i)*HDIM + d;
                    __nv_bfloat162 hp0(h0, h1), hp1(h2, h3);
                    *reinterpret_cast<__nv_bfloat162*>(oh + o0) = hp0;
                    *reinterpret_cast<uint32_t*>(ol + o0) = l01;
                    *reinterpret_cast<__nv_bfloat162*>(oh + o1) = hp1;
                    *reinterpret_cast<uint32_t*>(ol + o1) = l23;
                } else {
                    size_t base0 = (size_t)(b0i*NHEAD+hh)*HDIM*SEQ;
                    size_t base1 = (size_t)(b1i*NHEAD+hh)*HDIM*SEQ;
                    g_vth[base0 + (size_t)d * SEQ + s0i]     = h0;
                    g_vth[base0 + (size_t)(d+1) * SEQ + s0i] = h1;
                    g_vth[base1 + (size_t)d * SEQ + s1i]     = h2;
                    g_vth[base1 + (size_t)(d+1) * SEQ + s1i] = h3;
                    g_vtl[base0 + (size_t)d * SEQ + s0i]     = __float2bfloat16(v0 - __bfloat162float(h0));
                    g_vtl[base0 + (size_t)(d+1) * SEQ + s0i] = __float2bfloat16(v1 - __bfloat162float(h1));
                    g_vtl[base1 + (size_t)d * SEQ + s1i]     = __float2bfloat16(v2 - __bfloat162float(h2));
                    g_vtl[base1 + (size_t)(d+1) * SEQ + s1i] = __float2bfloat16(v3 - __bfloat162float(h3));
                }
            }
        }
    }
}

extern "C" __global__ void __launch_bounds__(256, 1)
qkv_mma_kernel(const float* __restrict__ bq, const float* __restrict__ bk,
               const float* __restrict__ bv)
{
    const int z = blockIdx.z;
    const __nv_bfloat16* Bh = g_wh + (size_t)z * EMBED * EMBED;
    const __nv_bfloat16* Bl = g_wl + (size_t)z * EMBED * EMBED;
    const float* bias = (z == 0) ? bq : (z == 1) ? bk : bv;
    int mode = (z == 0) ? 1 : (z == 1) ? 2 : 3;
    float scale = (z == 0) ? QSCALE : 1.0f;   // Q in base-2 softmax domain
    gemm_mma_body(g_xh, g_xl, Bh, Bl, bias, mode, nullptr, scale);
}

extern "C" __global__ void __launch_bounds__(256, 1)
oproj_mma_kernel(const float* __restrict__ bo, float* __restrict__ out)
{
    gemm_mma_body(g_ch, g_cl, g_wh + (size_t)3 * EMBED * EMBED,
                  g_wl + (size_t)3 * EMBED * EMBED, bo, 0, out, 1.0f);
}

// ---------------------------------------------------------------------------
// Flash attention: cp.async double-buffered K/V, base-2 online softmax,
// MMAs interleaved across independent accumulators.
// ---------------------------------------------------------------------------
#define KW (128*36)
#define VW (64*68)
#define ABUFW (2*KW + 2*VW)
#define ASMEM2 ((2*ABUFW + SEQ)*4)

__device__ __forceinline__ void attn_stage_kv(
    uint32_t swb, int buf, int tid,
    const __nv_bfloat16* kh, const __nv_bfloat16* kl,
    const __nv_bfloat16* vth, const __nv_bfloat16* vtl, int s0)
{
    const uint32_t dbase = swb + (uint32_t)(buf * ABUFW) * 4;
#pragma unroll
    for (int j = 0; j < 4; j++) {
        int idx = tid + j * 256;
        {
            int r = idx >> 3, c = idx & 7;
            uint32_t doff = (uint32_t)(r * 36 + c * 4) * 4;
            size_t soff = (size_t)(s0 + r) * HDIM + c * 8;
            CP_ASYNC16(dbase + doff,                kh + soff);
            CP_ASYNC16(dbase + (uint32_t)KW*4 + doff, kl + soff);
        }
        {
            int d = idx >> 4, c = idx & 15;
            uint32_t doff = (uint32_t)(2*KW + d * 68 + c * 4) * 4;
            size_t soff = (size_t)d * SEQ + s0 + c * 8;
            CP_ASYNC16(dbase + doff,                vth + soff);
            CP_ASYNC16(dbase + (uint32_t)VW*4 + doff, vtl + soff);
        }
    }
}

extern "C" __global__ void __launch_bounds__(256, 1)
attn_mma_kernel(const int* __restrict__ mask)
{
    extern __shared__ uint32_t sw[];
    const uint32_t swb = smem_u32(sw);
    float* mskf = reinterpret_cast<float*>(sw + 2 * ABUFW);

    const int tid = threadIdx.x, lane = tid & 31, wid = tid >> 5;
    const int g = lane >> 2, t = lane & 3;
    const int b = blockIdx.z, h = blockIdx.y;
    const int q0 = blockIdx.x * 128;
    const int qw = wid * 16;
    const size_t bh = (size_t)(b * NHEAD + h);
    const __nv_bfloat16* qhp = g_qh + bh * SEQ * HDIM;
    const __nv_bfloat16* qlp = g_ql + bh * SEQ * HDIM;
    const __nv_bfloat16* khp = g_kh + bh * SEQ * HDIM;
    const __nv_bfloat16* klp = g_kl + bh * SEQ * HDIM;
    const __nv_bfloat16* vhp = g_vth + bh * HDIM * SEQ;
    const __nv_bfloat16* vlp = g_vtl + bh * HDIM * SEQ;
    const int* mb = mask + b * SEQ;

#pragma unroll
    for (int i = 0; i < SEQ / 256; i++)
        mskf[tid + i * 256] = (float)mb[tid + i * 256];

    // stage Q into buffer0 K-area, extract fragments
#pragma unroll
    for (int j = 0; j < 4; j++) {
        int idx = tid + j * 256;
        int r = idx >> 3, c = idx & 7;
        uint32_t doff = (uint32_t)(r * 36 + c * 4) * 4;
        size_t soff = (size_t)(q0 + r) * HDIM + c * 8;
        CP_ASYNC16(swb + doff,                  qhp + soff);
        CP_ASYNC16(swb + (uint32_t)KW*4 + doff, qlp + soff);
    }
    CP_COMMIT();
    CP_WAIT(0);
    __syncthreads();

    uint32_t qh[4][4], ql[4][4];
    {
        uint32_t* Qh = sw;
        uint32_t* Ql = sw + KW;
#pragma unroll
        for (int ks = 0; ks < 4; ks++) {
#pragma unroll
            for (int p = 0; p < 4; p++) {
                int row = qw + g + ((p & 1) ? 8 : 0);
                int col = ks * 8 + t + ((p >= 2) ? 4 : 0);
                qh[ks][p] = Qh[row * 36 + col];
                ql[ks][p] = Ql[row * 36 + col];
            }
        }
    }
    __syncthreads();

    attn_stage_kv(swb, 0, tid, khp, klp, vhp, vlp, 0);
    CP_COMMIT();

    float mrow[2] = {-1e30f, -1e30f};
    float lrow[2] = {0.f, 0.f};
    float o[8][4];
#pragma unroll
    for (int i = 0; i < 8; i++)
#pragma unroll
        for (int j = 0; j < 4; j++) o[i][j] = 0.f;

    for (int it = 0; it < 16; it++) {
        const int buf = it & 1;
        const int s0 = it * 128;
        __syncthreads();
        if (it + 1 < 16) {
            attn_stage_kv(swb, buf ^ 1, tid, khp, klp, vhp, vlp, (it + 1) * 128);
            CP_COMMIT();
            CP_WAIT(1);
        } else {
            CP_WAIT(0);
        }
        __syncthreads();

        uint32_t* Ksh = sw + buf * ABUFW;
        uint32_t* Ksl = Ksh + KW;
        uint32_t* Vth = Ksh + 2 * KW;
        uint32_t* Vtl = Ksh + 2 * KW + VW;

        // ---- S = Q K^T (base-2 domain; scale folded into Q)
        float sc[16][4];
#pragma unroll
        for (int nt = 0; nt < 16; nt++)
#pragma unroll
            for (int j = 0; j < 4; j++) sc[nt][j] = 0.f;
#pragma unroll
        for (int ks = 0; ks < 4; ks++) {
#pragma unroll
            for (int ng = 0; ng < 4; ng++) {     // groups of 4 accumulators
                uint32_t b0[4], b1[4], c0[4], c1[4];
#pragma unroll
                for (int q = 0; q < 4; q++) {
                    int base = ((ng * 4 + q) * 8 + g) * 36 + ks * 8 + t;
                    b0[q] = Ksh[base]; b1[q] = Ksh[base + 4];
                    c0[q] = Ksl[base]; c1[q] = Ksl[base + 4];
                }
#pragma unroll
                for (int q = 0; q < 4; q++)
                    MMA16816(sc[ng*4+q], qh[ks], b0[q], b1[q]);
#pragma unroll
                for (int q = 0; q < 4; q++)
                    MMA16816(sc[ng*4+q], qh[ks], c0[q], c1[q]);
#pragma unroll
                for (int q = 0; q < 4; q++)
                    MMA16816(sc[ng*4+q], ql[ks], b0[q], b1[q]);
            }
        }

        // ---- mask
#pragma unroll
        for (int nt = 0; nt < 16; nt++) {
            float2 mv = *reinterpret_cast<float2*>(&mskf[s0 + nt * 8 + 2 * t]);
            if (mv.x == 0.f) { sc[nt][0] = -1e30f; sc[nt][2] = -1e30f; }
            if (mv.y == 0.f) { sc[nt][1] = -1e30f; sc[nt][3] = -1e30f; }
        }

        // ---- online softmax (base 2)
        float alpha[2];
#pragma unroll
        for (int rh = 0; rh < 2; rh++) {
            float mt_ = -1e30f;
#pragma unroll
            for (int nt = 0; nt < 16; nt++)
                mt_ = fmaxf(mt_, fmaxf(sc[nt][rh * 2 + 0], sc[nt][rh * 2 + 1]));
            mt_ = fmaxf(mt_, __shfl_xor_sync(0xffffffffu, mt_, 1));
            mt_ = fmaxf(mt_, __shfl_xor_sync(0xffffffffu, mt_, 2));
            float mn = fmaxf(mrow[rh], mt_);
            alpha[rh] = ex2(mrow[rh] - mn);
            float ls = 0.f;
#pragma unroll
            for (int nt = 0; nt < 16; nt++) {
                float p0 = ex2(sc[nt][rh * 2 + 0] - mn);
                float p1 = ex2(sc[nt][rh * 2 + 1] - mn);
                sc[nt][rh * 2 + 0] = p0;
                sc[nt][rh * 2 + 1] = p1;
                ls += p0 + p1;
            }
            ls += __shfl_xor_sync(0xffffffffu, ls, 1);
            ls += __shfl_xor_sync(0xffffffffu, ls, 2);
            lrow[rh] = lrow[rh] * alpha[rh] + ls;
            mrow[rh] = mn;
        }
#pragma unroll
        for (int dt = 0; dt < 8; dt++) {
            o[dt][0] *= alpha[0]; o[dt][1] *= alpha[0];
            o[dt][2] *= alpha[1]; o[dt][3] *= alpha[1];
        }

        // ---- O += P V (dt in groups of 4 independent accumulators)
#pragma unroll
        for (int j = 0; j < 8; j++) {
            uint32_t ph[4], pl[4];
#pragma unroll
            for (int p = 0; p < 4; p++) {
                int nt = 2 * j + (p >> 1);
                int ix = (p & 1) * 2;
                float e0 = sc[nt][ix], e1 = sc[nt][ix + 1];
                __nv_bfloat16 h0 = __float2bfloat16(e0);
                __nv_bfloat16 h1 = __float2bfloat16(e1);
                __nv_bfloat162 hh(h0, h1);
                ph[p] = *reinterpret_cast<uint32_t*>(&hh);
                pl[p] = pk2(e0 - __bfloat162float(h0), e1 - __bfloat162float(h1));
            }
#pragma unroll
            for (int dg = 0; dg < 2; dg++) {
                uint32_t v0[4], v1[4], w0[4], w1[4];
#pragma unroll
                for (int q = 0; q < 4; q++) {
                    int base = ((dg * 4 + q) * 8 + g) * 68 + j * 8 + t;
                    v0[q] = Vth[base]; v1[q] = Vth[base + 4];
                    w0[q] = Vtl[base]; w1[q] = Vtl[base + 4];
                }
#pragma unroll
                for (int q = 0; q < 4; q++)
                    MMA16816(o[dg*4+q], ph, v0[q], v1[q]);
#pragma unroll
                for (int q = 0; q < 4; q++)
                    MMA16816(o[dg*4+q], pl, v0[q], v1[q]);
#pragma unroll
                for (int q = 0; q < 4; q++)
                    MMA16816(o[dg*4+q], ph, w0[q], w1[q]);
            }
        }
    }

    // ---- write ctx (hi/lo) [m][e]
    float inv0 = (lrow[0] > 0.f) ? (1.f / lrow[0]) : 0.f;
    float inv1 = (lrow[1] > 0.f) ? (1.f / lrow[1]) : 0.f;
    int r0 = q0 + qw + g, r1 = r0 + 8;
#pragma unroll
    for (int dt = 0; dt < 8; dt++) {
        int e = h * HDIM + dt * 8 + 2 * t;
        float v0 = o[dt][0] * inv0, v1 = o[dt][1] * inv0;
        float v2 = o[dt][2] * inv1, v3 = o[dt][3] * inv1;
        __nv_bfloat16 h0 = __float2bfloat16(v0), h1 = __float2bfloat16(v1);
        __nv_bfloat16 h2 = __float2bfloat16(v2), h3 = __float2bfloat16(v3);
        __nv_bfloat162 hp0(h0, h1), hp1(h2, h3);
        *reinterpret_cast<__nv_bfloat162*>(&g_ch[(size_t)(b * SEQ + r0) * EMBED + e]) = hp0;
        *reinterpret_cast<uint32_t*>(&g_cl[(size_t)(b * SEQ + r0) * EMBED + e]) =
            pk2(v0 - __bfloat162float(h0), v1 - __bfloat162float(h1));
        *reinterpret_cast<__nv_bfloat162*>(&g_ch[(size_t)(b * SEQ + r1) * EMBED + e]) = hp1;
        *reinterpret_cast<uint32_t*>(&g_cl[(size_t)(b * SEQ + r1) * EMBED + e]) =
            pk2(v2 - __bfloat162float(h2), v3 - __bfloat162float(h3));
    }
}

// ---------------------------------------------------------------------------
extern "C" void kernel_launch(void* const* d_in, const int* in_sizes, int n_in,
                              void* d_out, int out_size)
{
    const float* x    = (const float*)d_in[0];
    const int*   mask = (const int*)d_in[1];
    const float* Wq   = (const float*)d_in[2];
    const float* bq   = (const float*)d_in[3];
    const float* Wk   = (const float*)d_in[4];
    const float* bk   = (const float*)d_in[5];
    const float* Wv   = (const float*)d_in[6];
    const float* bv   = (const float*)d_in[7];
    const float* Wo   = (const float*)d_in[8];
    const float* bo   = (const float*)d_in[9];
    float* out = (float*)d_out;
    (void)in_sizes; (void)n_in; (void)out_size;

    cudaFuncSetAttribute(qkv_mma_kernel,
                         cudaFuncAttributeMaxDynamicSharedMemorySize, GSMEM2);
    cudaFuncSetAttribute(oproj_mma_kernel,
                         cudaFuncAttributeMaxDynamicSharedMemorySize, GSMEM2);
    cudaFuncSetAttribute(attn_mma_kernel,
                         cudaFuncAttributeMaxDynamicSharedMemorySize, ASMEM2);

    cvt_x_kernel<<<(MROWS * EMBED) / 1024, 256>>>(x);
    cvt_w_kernel<<<dim3(32, 32, 4), dim3(32, 8)>>>(Wq, Wk, Wv, Wo);

    dim3 gq(EMBED / 128, MROWS / 128, 3);
    qkv_mma_kernel<<<gq, 256, GSMEM2>>>(bq, bk, bv);

    dim3 ga(SEQ / 128, NHEAD, BATCH);
    attn_mma_kernel<<<ga, 256, ASMEM2>>>(mask);

    dim3 go(EMBED / 128, MROWS / 128, 1);
    oproj_mma_kernel<<<go, 256, GSMEM2>>>(bo, out);
}

// round 7
// speedup vs baseline: 1.3609x; 1.1714x over previous
#include <cuda_runtime.h>
#include <cuda_bf16.h>
#include <cuda_fp16.h>
#include <cstdint>

#define EMBED 1024
#define NHEAD 16
#define HDIM  64
#define BATCH 2
#define SEQ   2048
#define MROWS (BATCH*SEQ)   // 4096

// ---------------------------------------------------------------------------
// Device-global scratch.
// Projection inputs: bf16 hi/lo split (3-product, near-exact).
// Attention operands: Q fp16 hi/lo split; K, Vt single fp16 (2-product MMA).
// ctx: bf16 hi/lo split for the bf16 3-product output projection.
// ---------------------------------------------------------------------------
__device__ __nv_bfloat16 g_xh [MROWS*EMBED],          g_xl [MROWS*EMBED];
__device__ __nv_bfloat16 g_wh [4*EMBED*EMBED],        g_wl [4*EMBED*EMBED];
__device__ __half        g_qfh[BATCH*NHEAD*SEQ*HDIM], g_qfl[BATCH*NHEAD*SEQ*HDIM];
__device__ __half        g_kf [BATCH*NHEAD*SEQ*HDIM];                 // [b,h,s,d]
__device__ __half        g_vf [BATCH*NHEAD*HDIM*SEQ];                 // [b,h,d,s]
__device__ __nv_bfloat16 g_ch [MROWS*EMBED],          g_cl [MROWS*EMBED];

// ---------------------------------------------------------------------------
// Helpers
// ---------------------------------------------------------------------------
__device__ __forceinline__ uint32_t smem_u32(const void* p) {
    uint32_t a;
    asm("{ .reg .u64 t; cvta.to.shared.u64 t, %1; cvt.u32.u64 %0, t; }"
        : "=r"(a) : "l"(p));
    return a;
}
__device__ __forceinline__ uint32_t pk2(float e0, float e1) {   // bf16x2
    uint32_t d;
    asm("cvt.rn.bf16x2.f32 %0, %1, %2;" : "=r"(d) : "f"(e1), "f"(e0));
    return d;
}
__device__ __forceinline__ uint32_t pk2h(float e0, float e1) {  // f16x2, e0 low
    uint32_t d;
    asm("cvt.rn.f16x2.f32 %0, %1, %2;" : "=r"(d) : "f"(e1), "f"(e0));
    return d;
}
__device__ __forceinline__ float ex2(float x) {
    float r;
    asm("ex2.approx.f32 %0, %1;" : "=f"(r) : "f"(x));
    return r;
}

#define MMA16816(c, a, b0, b1)                                              \
    asm("mma.sync.aligned.m16n8k16.row.col.f32.bf16.bf16.f32 "              \
        "{%0,%1,%2,%3}, {%4,%5,%6,%7}, {%8,%9}, {%0,%1,%2,%3};"             \
        : "+f"((c)[0]), "+f"((c)[1]), "+f"((c)[2]), "+f"((c)[3])            \
        : "r"((a)[0]), "r"((a)[1]), "r"((a)[2]), "r"((a)[3]),               \
          "r"(b0), "r"(b1))

#define MMAF16(c, a, b0, b1)                                                \
    asm("mma.sync.aligned.m16n8k16.row.col.f32.f16.f16.f32 "                \
        "{%0,%1,%2,%3}, {%4,%5,%6,%7}, {%8,%9}, {%0,%1,%2,%3};"             \
        : "+f"((c)[0]), "+f"((c)[1]), "+f"((c)[2]), "+f"((c)[3])            \
        : "r"((a)[0]), "r"((a)[1]), "r"((a)[2]), "r"((a)[3]),               \
          "r"(b0), "r"(b1))

#define CP_ASYNC16(dst, src)                                                \
    asm volatile("cp.async.cg.shared.global [%0], [%1], 16;"                \
        :: "r"(dst), "l"(src) : "memory")
#define CP_COMMIT() asm volatile("cp.async.commit_group;" ::: "memory")
#define CP_WAIT(n)  asm volatile("cp.async.wait_group %0;" :: "n"(n) : "memory")

#define QSCALE 0.180336880111120419f   // 0.125 * log2(e): base-2 softmax

// ---------------------------------------------------------------------------
// Conversion kernels (projection inputs, bf16 split)
// ---------------------------------------------------------------------------
extern "C" __global__ void __launch_bounds__(256)
cvt_x_kernel(const float* __restrict__ src)
{
    int i = (blockIdx.x * 256 + threadIdx.x) * 4;
    float4 v = *reinterpret_cast<const float4*>(src + i);
    float vv[4] = {v.x, v.y, v.z, v.w};
    uint32_t hw[2], lw[2];
#pragma unroll
    for (int p = 0; p < 2; p++) {
        float a = vv[2*p], b = vv[2*p+1];
        __nv_bfloat16 ha = __float2bfloat16(a), hb = __float2bfloat16(b);
        __nv_bfloat162 hh(ha, hb);
        hw[p] = *reinterpret_cast<uint32_t*>(&hh);
        lw[p] = pk2(a - __bfloat162float(ha), b - __bfloat162float(hb));
    }
    *reinterpret_cast<uint2*>(g_xh + i) = make_uint2(hw[0], hw[1]);
    *reinterpret_cast<uint2*>(g_xl + i) = make_uint2(lw[0], lw[1]);
}

extern "C" __global__ void __launch_bounds__(256)
cvt_w_kernel(const float* __restrict__ Wq, const float* __restrict__ Wk,
             const float* __restrict__ Wv, const float* __restrict__ Wo)
{
    __shared__ float t[32][33];
    const float* W = (blockIdx.z == 0) ? Wq : (blockIdx.z == 1) ? Wk :
                     (blockIdx.z == 2) ? Wv : Wo;
    __nv_bfloat16* oh = g_wh + (size_t)blockIdx.z * EMBED * EMBED;
    __nv_bfloat16* ol = g_wl + (size_t)blockIdx.z * EMBED * EMBED;
    int bx = blockIdx.x * 32;  // n base
    int by = blockIdx.y * 32;  // k base
    int tx = threadIdx.x, ty = threadIdx.y;
#pragma unroll
    for (int i = 0; i < 4; i++) {
        int r = ty + i * 8;
        t[r][tx] = W[(size_t)(by + r) * EMBED + bx + tx];
    }
    __syncthreads();
#pragma unroll
    for (int i = 0; i < 4; i++) {
        int r = ty + i * 8;
        float v = t[tx][r];
        __nv_bfloat16 h = __float2bfloat16(v);
        size_t o = (size_t)(bx + r) * EMBED + by + tx;
        oh[o] = h;
        ol[o] = __float2bfloat16(v - __bfloat162float(h));
    }
}

// ---------------------------------------------------------------------------
// bf16 3-product GEMM (projections): C[4096,1024] = A @ B^T(+bias)
// 128x128 tile, BK=64, 8 warps (4m x 2n). cp.async double-buffered.
// mode 0: fp32 out; 1: Q (fp16 split, QSCALE); 2: K (fp16); 3: Vt (fp16)
// ---------------------------------------------------------------------------
#define GW (128*36)
#define GSMEM2 (2*4*GW*4)            // 147456 B

__device__ __forceinline__ void gemm_stage(
    uint32_t swb, int buf, int tid,
    const __nv_bfloat16* sAh, const __nv_bfloat16* sAl,
    const __nv_bfloat16* sBh, const __nv_bfloat16* sBl, int k0)
{
    const uint32_t dbase = swb + (uint32_t)(buf * 4 * GW) * 4;
#pragma unroll
    for (int j = 0; j < 4; j++) {
        int idx = tid + j * 256;
        int r = idx >> 3, c = idx & 7;
        uint32_t doff = (uint32_t)(r * 36 + c * 4) * 4;
        size_t soff = (size_t)r * EMBED + k0 + c * 8;
        CP_ASYNC16(dbase + doff,               sAh + soff);
        CP_ASYNC16(dbase + (uint32_t)GW*4   + doff, sAl + soff);
        CP_ASYNC16(dbase + (uint32_t)2*GW*4 + doff, sBh + soff);
        CP_ASYNC16(dbase + (uint32_t)3*GW*4 + doff, sBl + soff);
    }
}

__device__ __forceinline__ void gemm_mma_body(
    const __nv_bfloat16* __restrict__ Ah, const __nv_bfloat16* __restrict__ Al,
    const __nv_bfloat16* __restrict__ Bh, const __nv_bfloat16* __restrict__ Bl,
    const float* __restrict__ bias, int mode, float* __restrict__ outf, float scale)
{
    extern __shared__ uint32_t sw[];
    const uint32_t swb = smem_u32(sw);
    const int tid = threadIdx.x;
    const int lane = tid & 31, wid = tid >> 5;
    const int g = lane >> 2, t = lane & 3;
    const int wm = wid & 3, wn = wid >> 2;
    const int m0 = blockIdx.y * 128, n0 = blockIdx.x * 128;

    const __nv_bfloat16* sAh = Ah + (size_t)m0 * EMBED;
    const __nv_bfloat16* sAl = Al + (size_t)m0 * EMBED;
    const __nv_bfloat16* sBh = Bh + (size_t)n0 * EMBED;
    const __nv_bfloat16* sBl = Bl + (size_t)n0 * EMBED;

    float acc[2][8][4];
#pragma unroll
    for (int a = 0; a < 2; a++)
#pragma unroll
        for (int b = 0; b < 8; b++)
#pragma unroll
            for (int c = 0; c < 4; c++) acc[a][b][c] = 0.f;

    gemm_stage(swb, 0, tid, sAh, sAl, sBh, sBl, 0);
    CP_COMMIT();

    for (int it = 0; it < 16; it++) {
        const int buf = it & 1;
        __syncthreads();
        if (it + 1 < 16) {
            gemm_stage(swb, buf ^ 1, tid, sAh, sAl, sBh, sBl, (it + 1) * 64);
            CP_COMMIT();
            CP_WAIT(1);
        } else {
            CP_WAIT(0);
        }
        __syncthreads();

        uint32_t* Ash = sw + buf * 4 * GW;
        uint32_t* Asl = Ash + GW;
        uint32_t* Bsh = Ash + 2 * GW;
        uint32_t* Bsl = Ash + 3 * GW;

#pragma unroll
        for (int ks = 0; ks < 4; ks++) {
            uint32_t ah[2][4], al[2][4];
#pragma unroll
            for (int mt = 0; mt < 2; mt++) {
                int r = wm * 32 + mt * 16 + g;
                int base = r * 36 + ks * 8 + t;
                ah[mt][0] = Ash[base];     ah[mt][1] = Ash[base + 8*36];
                ah[mt][2] = Ash[base + 4]; ah[mt][3] = Ash[base + 8*36 + 4];
                al[mt][0] = Asl[base];     al[mt][1] = Asl[base + 8*36];
                al[mt][2] = Asl[base + 4]; al[mt][3] = Asl[base + 8*36 + 4];
            }
#pragma unroll
            for (int ntp = 0; ntp < 4; ntp++) {
                uint32_t b0[2], b1[2], c0[2], c1[2];
#pragma unroll
                for (int q = 0; q < 2; q++) {
                    int n = wn * 64 + (2 * ntp + q) * 8 + g;
                    int base = n * 36 + ks * 8 + t;
                    b0[q] = Bsh[base]; b1[q] = Bsh[base + 4];
                    c0[q] = Bsl[base]; c1[q] = Bsl[base + 4];
                }
#pragma unroll
                for (int q = 0; q < 2; q++)
#pragma unroll
                    for (int mt = 0; mt < 2; mt++)
                        MMA16816(acc[mt][2*ntp+q], ah[mt], b0[q], b1[q]);
#pragma unroll
                for (int q = 0; q < 2; q++)
#pragma unroll
                    for (int mt = 0; mt < 2; mt++)
                        MMA16816(acc[mt][2*ntp+q], ah[mt], c0[q], c1[q]);
#pragma unroll
                for (int q = 0; q < 2; q++)
#pragma unroll
                    for (int mt = 0; mt < 2; mt++)
                        MMA16816(acc[mt][2*ntp+q], al[mt], b0[q], b1[q]);
            }
        }
    }

    // epilogue
#pragma unroll
    for (int mt = 0; mt < 2; mt++) {
#pragma unroll
        for (int nt = 0; nt < 8; nt++) {
            int r0 = m0 + wm * 32 + mt * 16 + g;
            int r1 = r0 + 8;
            int c0 = n0 + wn * 64 + nt * 8 + 2 * t;
            float2 bb = *reinterpret_cast<const float2*>(&bias[c0]);
            float v0 = (acc[mt][nt][0] + bb.x) * scale;
            float v1 = (acc[mt][nt][1] + bb.y) * scale;
            float v2 = (acc[mt][nt][2] + bb.x) * scale;
            float v3 = (acc[mt][nt][3] + bb.y) * scale;
            if (mode == 0) {
                *reinterpret_cast<float2*>(&outf[(size_t)r0 * EMBED + c0]) = make_float2(v0, v1);
                *reinterpret_cast<float2*>(&outf[(size_t)r1 * EMBED + c0]) = make_float2(v2, v3);
            } else {
                int hh = c0 >> 6, d = c0 & 63;
                int b0i = r0 >> 11, s0i = r0 & (SEQ - 1);
                int b1i = r1 >> 11, s1i = r1 & (SEQ - 1);
                if (mode == 1) {          // Q: fp16 hi/lo split
                    size_t o0 = ((size_t)(b0i*NHEAD+hh)*SEQ + s0i)*HDIM + d;
                    size_t o1 = ((size_t)(b1i*NHEAD+hh)*SEQ + s1i)*HDIM + d;
                    __half h0 = __float2half_rn(v0), h1 = __float2half_rn(v1);
                    __half h2 = __float2half_rn(v2), h3 = __float2half_rn(v3);
                    __half2 hp0(h0, h1), hp1(h2, h3);
                    *reinterpret_cast<__half2*>(g_qfh + o0) = hp0;
                    *reinterpret_cast<uint32_t*>(g_qfl + o0) =
                        pk2h(v0 - __half2float(h0), v1 - __half2float(h1));
                    *reinterpret_cast<__half2*>(g_qfh + o1) = hp1;
                    *reinterpret_cast<uint32_t*>(g_qfl + o1) =
                        pk2h(v2 - __half2float(h2), v3 - __half2float(h3));
                } else if (mode == 2) {   // K: single fp16
                    size_t o0 = ((size_t)(b0i*NHEAD+hh)*SEQ + s0i)*HDIM + d;
                    size_t o1 = ((size_t)(b1i*NHEAD+hh)*SEQ + s1i)*HDIM + d;
                    *reinterpret_cast<uint32_t*>(g_kf + o0) = pk2h(v0, v1);
                    *reinterpret_cast<uint32_t*>(g_kf + o1) = pk2h(v2, v3);
                } else {                  // Vt: single fp16, [b,h,d,s]
                    size_t base0 = (size_t)(b0i*NHEAD+hh)*HDIM*SEQ;
                    size_t base1 = (size_t)(b1i*NHEAD+hh)*HDIM*SEQ;
                    g_vf[base0 + (size_t)d * SEQ + s0i]     = __float2half_rn(v0);
                    g_vf[base0 + (size_t)(d+1) * SEQ + s0i] = __float2half_rn(v1);
                    g_vf[base1 + (size_t)d * SEQ + s1i]     = __float2half_rn(v2);
                    g_vf[base1 + (size_t)(d+1) * SEQ + s1i] = __float2half_rn(v3);
                }
            }
        }
    }
}

extern "C" __global__ void __launch_bounds__(256, 1)
qkv_mma_kernel(const float* __restrict__ bq, const float* __restrict__ bk,
               const float* __restrict__ bv)
{
    const int z = blockIdx.z;
    const __nv_bfloat16* Bh = g_wh + (size_t)z * EMBED * EMBED;
    const __nv_bfloat16* Bl = g_wl + (size_t)z * EMBED * EMBED;
    const float* bias = (z == 0) ? bq : (z == 1) ? bk : bv;
    int mode = (z == 0) ? 1 : (z == 1) ? 2 : 3;
    float scale = (z == 0) ? QSCALE : 1.0f;
    gemm_mma_body(g_xh, g_xl, Bh, Bl, bias, mode, nullptr, scale);
}

extern "C" __global__ void __launch_bounds__(256, 1)
oproj_mma_kernel(const float* __restrict__ bo, float* __restrict__ out)
{
    gemm_mma_body(g_ch, g_cl, g_wh + (size_t)3 * EMBED * EMBED,
                  g_wl + (size_t)3 * EMBED * EMBED, bo, 0, out, 1.0f);
}

// ---------------------------------------------------------------------------
// Flash attention, fp16 2-product MMAs:
//   S = (Qh + Ql)·K   (K single fp16)
//   O += (Ph + Pl)·V  (V single fp16)
// cp.async double-buffered K/V (single arrays), base-2 online softmax.
// ---------------------------------------------------------------------------
#define KW (128*36)
#define VW (64*68)
#define ABUFW (KW + VW)                 // 8960 words per buffer
#define ASMEM2 ((2*ABUFW + SEQ)*4)      // 79872 B

__device__ __forceinline__ void attn_stage_kv(
    uint32_t swb, int buf, int tid,
    const __half* kf, const __half* vf, int s0)
{
    const uint32_t dbase = swb + (uint32_t)(buf * ABUFW) * 4;
#pragma unroll
    for (int j = 0; j < 4; j++) {
        int idx = tid + j * 256;
        {   // K tile: 128 rows x 8 chunks
            int r = idx >> 3, c = idx & 7;
            uint32_t doff = (uint32_t)(r * 36 + c * 4) * 4;
            CP_ASYNC16(dbase + doff, kf + (size_t)(s0 + r) * HDIM + c * 8);
        }
        {   // Vt tile: 64 rows x 16 chunks
            int d = idx >> 4, c = idx & 15;
            uint32_t doff = (uint32_t)(KW + d * 68 + c * 4) * 4;
            CP_ASYNC16(dbase + doff, vf + (size_t)d * SEQ + s0 + c * 8);
        }
    }
}

extern "C" __global__ void __launch_bounds__(256, 1)
attn_mma_kernel(const int* __restrict__ mask)
{
    extern __shared__ uint32_t sw[];
    const uint32_t swb = smem_u32(sw);
    float* mskf = reinterpret_cast<float*>(sw + 2 * ABUFW);

    const int tid = threadIdx.x, lane = tid & 31, wid = tid >> 5;
    const int g = lane >> 2, t = lane & 3;
    const int b = blockIdx.z, h = blockIdx.y;
    const int q0 = blockIdx.x * 128;
    const int qw = wid * 16;
    const size_t bh = (size_t)(b * NHEAD + h);
    const __half* qhp = g_qfh + bh * SEQ * HDIM;
    const __half* qlp = g_qfl + bh * SEQ * HDIM;
    const __half* kfp = g_kf  + bh * SEQ * HDIM;
    const __half* vfp = g_vf  + bh * HDIM * SEQ;
    const int* mb = mask + b * SEQ;

#pragma unroll
    for (int i = 0; i < SEQ / 256; i++)
        mskf[tid + i * 256] = (float)mb[tid + i * 256];

    // ---- stage Q (hi at sw, lo at sw+KW), extract fragments
#pragma unroll
    for (int j = 0; j < 4; j++) {
        int idx = tid + j * 256;
        int r = idx >> 3, c = idx & 7;
        uint32_t doff = (uint32_t)(r * 36 + c * 4) * 4;
        size_t soff = (size_t)(q0 + r) * HDIM + c * 8;
        CP_ASYNC16(swb + doff,                  qhp + soff);
        CP_ASYNC16(swb + (uint32_t)KW*4 + doff, qlp + soff);
    }
    CP_COMMIT();
    CP_WAIT(0);
    __syncthreads();

    uint32_t qh[4][4], ql[4][4];
    {
        uint32_t* Qh = sw;
        uint32_t* Ql = sw + KW;
#pragma unroll
        for (int ks = 0; ks < 4; ks++) {
#pragma unroll
            for (int p = 0; p < 4; p++) {
                int row = qw + g + ((p & 1) ? 8 : 0);
                int col = ks * 8 + t + ((p >= 2) ? 4 : 0);
                qh[ks][p] = Qh[row * 36 + col];
                ql[ks][p] = Ql[row * 36 + col];
            }
        }
    }
    __syncthreads();

    attn_stage_kv(swb, 0, tid, kfp, vfp, 0);
    CP_COMMIT();

    float mrow[2] = {-1e30f, -1e30f};
    float lrow[2] = {0.f, 0.f};
    float o[8][4];
#pragma unroll
    for (int i = 0; i < 8; i++)
#pragma unroll
        for (int j = 0; j < 4; j++) o[i][j] = 0.f;

    for (int it = 0; it < 16; it++) {
        const int buf = it & 1;
        const int s0 = it * 128;
        __syncthreads();
        if (it + 1 < 16) {
            attn_stage_kv(swb, buf ^ 1, tid, kfp, vfp, (it + 1) * 128);
            CP_COMMIT();
            CP_WAIT(1);
        } else {
            CP_WAIT(0);
        }
        __syncthreads();

        uint32_t* Ksh = sw + buf * ABUFW;
        uint32_t* Vth = Ksh + KW;

        // ---- S = Q K^T (2 products: qh, ql vs single K)
        float sc[16][4];
#pragma unroll
        for (int nt = 0; nt < 16; nt++)
#pragma unroll
            for (int j = 0; j < 4; j++) sc[nt][j] = 0.f;
#pragma unroll
        for (int ks = 0; ks < 4; ks++) {
#pragma unroll
            for (int ng = 0; ng < 4; ng++) {
                uint32_t b0[4], b1[4];
#pragma unroll
                for (int q = 0; q < 4; q++) {
                    int base = ((ng * 4 + q) * 8 + g) * 36 + ks * 8 + t;
                    b0[q] = Ksh[base]; b1[q] = Ksh[base + 4];
                }
#pragma unroll
                for (int q = 0; q < 4; q++)
                    MMAF16(sc[ng*4+q], qh[ks], b0[q], b1[q]);
#pragma unroll
                for (int q = 0; q < 4; q++)
                    MMAF16(sc[ng*4+q], ql[ks], b0[q], b1[q]);
            }
        }

        // ---- mask
#pragma unroll
        for (int nt = 0; nt < 16; nt++) {
            float2 mv = *reinterpret_cast<float2*>(&mskf[s0 + nt * 8 + 2 * t]);
            if (mv.x == 0.f) { sc[nt][0] = -1e30f; sc[nt][2] = -1e30f; }
            if (mv.y == 0.f) { sc[nt][1] = -1e30f; sc[nt][3] = -1e30f; }
        }

        // ---- online softmax (base 2)
        float alpha[2];
#pragma unroll
        for (int rh = 0; rh < 2; rh++) {
            float mt_ = -1e30f;
#pragma unroll
            for (int nt = 0; nt < 16; nt++)
                mt_ = fmaxf(mt_, fmaxf(sc[nt][rh * 2 + 0], sc[nt][rh * 2 + 1]));
            mt_ = fmaxf(mt_, __shfl_xor_sync(0xffffffffu, mt_, 1));
            mt_ = fmaxf(mt_, __shfl_xor_sync(0xffffffffu, mt_, 2));
            float mn = fmaxf(mrow[rh], mt_);
            alpha[rh] = ex2(mrow[rh] - mn);
            float ls = 0.f;
#pragma unroll
            for (int nt = 0; nt < 16; nt++) {
                float p0 = ex2(sc[nt][rh * 2 + 0] - mn);
                float p1 = ex2(sc[nt][rh * 2 + 1] - mn);
                sc[nt][rh * 2 + 0] = p0;
                sc[nt][rh * 2 + 1] = p1;
                ls += p0 + p1;
            }
            ls += __shfl_xor_sync(0xffffffffu, ls, 1);
            ls += __shfl_xor_sync(0xffffffffu, ls, 2);
            lrow[rh] = lrow[rh] * alpha[rh] + ls;
            mrow[rh] = mn;
        }
#pragma unroll
        for (int dt = 0; dt < 8; dt++) {
            o[dt][0] *= alpha[0]; o[dt][1] *= alpha[0];
            o[dt][2] *= alpha[1]; o[dt][3] *= alpha[1];
        }

        // ---- O += P V (2 products: ph, pl vs single V)
#pragma unroll
        for (int j = 0; j < 8; j++) {
            uint32_t ph[4], pl[4];
#pragma unroll
            for (int p = 0; p < 4; p++) {
                int nt = 2 * j + (p >> 1);
                int ix = (p & 1) * 2;
                float e0 = sc[nt][ix], e1 = sc[nt][ix + 1];
                __half h0 = __float2half_rn(e0);
                __half h1 = __float2half_rn(e1);
                __half2 hh(h0, h1);
                ph[p] = *reinterpret_cast<uint32_t*>(&hh);
                pl[p] = pk2h(e0 - __half2float(h0), e1 - __half2float(h1));
            }
#pragma unroll
            for (int dg = 0; dg < 2; dg++) {
                uint32_t v0[4], v1[4];
#pragma unroll
                for (int q = 0; q < 4; q++) {
                    int base = ((dg * 4 + q) * 8 + g) * 68 + j * 8 + t;
                    v0[q] = Vth[base]; v1[q] = Vth[base + 4];
                }
#pragma unroll
                for (int q = 0; q < 4; q++)
                    MMAF16(o[dg*4+q], ph, v0[q], v1[q]);
#pragma unroll
                for (int q = 0; q < 4; q++)
                    MMAF16(o[dg*4+q], pl, v0[q], v1[q]);
            }
        }
    }

    // ---- write ctx (bf16 hi/lo) [m][e]
    float inv0 = (lrow[0] > 0.f) ? (1.f / lrow[0]) : 0.f;
    float inv1 = (lrow[1] > 0.f) ? (1.f / lrow[1]) : 0.f;
    int r0 = q0 + qw + g, r1 = r0 + 8;
#pragma unroll
    for (int dt = 0; dt < 8; dt++) {
        int e = h * HDIM + dt * 8 + 2 * t;
        float v0 = o[dt][0] * inv0, v1 = o[dt][1] * inv0;
        float v2 = o[dt][2] * inv1, v3 = o[dt][3] * inv1;
        __nv_bfloat16 h0 = __float2bfloat16(v0), h1 = __float2bfloat16(v1);
        __nv_bfloat16 h2 = __float2bfloat16(v2), h3 = __float2bfloat16(v3);
        __nv_bfloat162 hp0(h0, h1), hp1(h2, h3);
        *reinterpret_cast<__nv_bfloat162*>(&g_ch[(size_t)(b * SEQ + r0) * EMBED + e]) = hp0;
        *reinterpret_cast<uint32_t*>(&g_cl[(size_t)(b * SEQ + r0) * EMBED + e]) =
            pk2(v0 - __bfloat162float(h0), v1 - __bfloat162float(h1));
        *reinterpret_cast<__nv_bfloat162*>(&g_ch[(size_t)(b * SEQ + r1) * EMBED + e]) = hp1;
        *reinterpret_cast<uint32_t*>(&g_cl[(size_t)(b * SEQ + r1) * EMBED + e]) =
            pk2(v2 - __bfloat162float(h2), v3 - __bfloat162float(h3));
    }
}

// ---------------------------------------------------------------------------
extern "C" void kernel_launch(void* const* d_in, const int* in_sizes, int n_in,
                              void* d_out, int out_size)
{
    const float* x    = (const float*)d_in[0];
    const int*   mask = (const int*)d_in[1];
    const float* Wq   = (const float*)d_in[2];
    const float* bq   = (const float*)d_in[3];
    const float* Wk   = (const float*)d_in[4];
    const float* bk   = (const float*)d_in[5];
    const float* Wv   = (const float*)d_in[6];
    const float* bv   = (const float*)d_in[7];
    const float* Wo   = (const float*)d_in[8];
    const float* bo   = (const float*)d_in[9];
    float* out = (float*)d_out;
    (void)in_sizes; (void)n_in; (void)out_size;

    cudaFuncSetAttribute(qkv_mma_kernel,
                         cudaFuncAttributeMaxDynamicSharedMemorySize, GSMEM2);
    cudaFuncSetAttribute(oproj_mma_kernel,
                         cudaFuncAttributeMaxDynamicSharedMemorySize, GSMEM2);
    cudaFuncSetAttribute(attn_mma_kernel,
                         cudaFuncAttributeMaxDynamicSharedMemorySize, ASMEM2);

    cvt_x_kernel<<<(MROWS * EMBED) / 1024, 256>>>(x);
    cvt_w_kernel<<<dim3(32, 32, 4), dim3(32, 8)>>>(Wq, Wk, Wv, Wo);

    dim3 gq(EMBED / 128, MROWS / 128, 3);
    qkv_mma_kernel<<<gq, 256, GSMEM2>>>(bq, bk, bv);

    dim3 ga(SEQ / 128, NHEAD, BATCH);
    attn_mma_kernel<<<ga, 256, ASMEM2>>>(mask);

    dim3 go(EMBED / 128, MROWS / 128, 1);
    oproj_mma_kernel<<<go, 256, GSMEM2>>>(bo, out);
}

// round 8
// speedup vs baseline: 1.6237x; 1.1931x over previous
#include <cuda_runtime.h>
#include <cuda_bf16.h>
#include <cuda_fp16.h>
#include <cstdint>

#define EMBED 1024
#define NHEAD 16
#define HDIM  64
#define BATCH 2
#define SEQ   2048
#define MROWS (BATCH*SEQ)   // 4096

// ---------------------------------------------------------------------------
// Device-global scratch. Everything fp16 now:
//  - activations (x, ctx): hi/lo split (2-product, A-side exact to ~22 bits)
//  - weights, K, Vt: single fp16
//  - Q: hi/lo split (scores feed exp -> keep A-side exact)
// ---------------------------------------------------------------------------
__device__ __half g_xfh[MROWS*EMBED],          g_xfl[MROWS*EMBED];
__device__ __half g_wf [4*EMBED*EMBED];                         // W^T [4][n][k]
__device__ __half g_qfh[BATCH*NHEAD*SEQ*HDIM], g_qfl[BATCH*NHEAD*SEQ*HDIM];
__device__ __half g_kf [BATCH*NHEAD*SEQ*HDIM];                  // [b,h,s,d]
__device__ __half g_vf [BATCH*NHEAD*HDIM*SEQ];                  // [b,h,d,s]
__device__ __half g_cfh[MROWS*EMBED],          g_cfl[MROWS*EMBED];

// ---------------------------------------------------------------------------
// Helpers
// ---------------------------------------------------------------------------
__device__ __forceinline__ uint32_t smem_u32(const void* p) {
    uint32_t a;
    asm("{ .reg .u64 t; cvta.to.shared.u64 t, %1; cvt.u32.u64 %0, t; }"
        : "=r"(a) : "l"(p));
    return a;
}
__device__ __forceinline__ uint32_t pk2h(float e0, float e1) {  // f16x2, e0 low
    uint32_t d;
    asm("cvt.rn.f16x2.f32 %0, %1, %2;" : "=r"(d) : "f"(e1), "f"(e0));
    return d;
}
__device__ __forceinline__ float ex2(float x) {
    float r;
    asm("ex2.approx.f32 %0, %1;" : "=f"(r) : "f"(x));
    return r;
}

#define MMAF16(c, a, b0, b1)                                                \
    asm("mma.sync.aligned.m16n8k16.row.col.f32.f16.f16.f32 "                \
        "{%0,%1,%2,%3}, {%4,%5,%6,%7}, {%8,%9}, {%0,%1,%2,%3};"             \
        : "+f"((c)[0]), "+f"((c)[1]), "+f"((c)[2]), "+f"((c)[3])            \
        : "r"((a)[0]), "r"((a)[1]), "r"((a)[2]), "r"((a)[3]),               \
          "r"(b0), "r"(b1))

#define CP_ASYNC16(dst, src)                                                \
    asm volatile("cp.async.cg.shared.global [%0], [%1], 16;"                \
        :: "r"(dst), "l"(src) : "memory")
#define CP_COMMIT() asm volatile("cp.async.commit_group;" ::: "memory")
#define CP_WAIT(n)  asm volatile("cp.async.wait_group %0;" :: "n"(n) : "memory")

#define QSCALE 0.180336880111120419f   // 0.125 * log2(e): base-2 softmax

// ---------------------------------------------------------------------------
// Conversion kernels
// ---------------------------------------------------------------------------
extern "C" __global__ void __launch_bounds__(256)
cvt_x_kernel(const float* __restrict__ src)
{
    int i = (blockIdx.x * 256 + threadIdx.x) * 4;
    float4 v = *reinterpret_cast<const float4*>(src + i);
    float vv[4] = {v.x, v.y, v.z, v.w};
    uint32_t hw[2], lw[2];
#pragma unroll
    for (int p = 0; p < 2; p++) {
        float a = vv[2*p], b = vv[2*p+1];
        __half ha = __float2half_rn(a), hb = __float2half_rn(b);
        __half2 hh(ha, hb);
        hw[p] = *reinterpret_cast<uint32_t*>(&hh);
        lw[p] = pk2h(a - __half2float(ha), b - __half2float(hb));
    }
    *reinterpret_cast<uint2*>(g_xfh + i) = make_uint2(hw[0], hw[1]);
    *reinterpret_cast<uint2*>(g_xfl + i) = make_uint2(lw[0], lw[1]);
}

extern "C" __global__ void __launch_bounds__(256)
cvt_w_kernel(const float* __restrict__ Wq, const float* __restrict__ Wk,
             const float* __restrict__ Wv, const float* __restrict__ Wo)
{
    __shared__ float t[32][33];
    const float* W = (blockIdx.z == 0) ? Wq : (blockIdx.z == 1) ? Wk :
                     (blockIdx.z == 2) ? Wv : Wo;
    __half* of = g_wf + (size_t)blockIdx.z * EMBED * EMBED;
    int bx = blockIdx.x * 32;  // n base
    int by = blockIdx.y * 32;  // k base
    int tx = threadIdx.x, ty = threadIdx.y;
#pragma unroll
    for (int i = 0; i < 4; i++) {
        int r = ty + i * 8;
        t[r][tx] = W[(size_t)(by + r) * EMBED + bx + tx];
    }
    __syncthreads();
#pragma unroll
    for (int i = 0; i < 4; i++) {
        int r = ty + i * 8;
        of[(size_t)(bx + r) * EMBED + by + tx] = __float2half_rn(t[tx][r]);
    }
}

// ---------------------------------------------------------------------------
// fp16 2-product GEMM (projections): C = (Ah+Al) @ B^T(+bias)
// 128x128 tile, BK=64, 8 warps (4m x 2n). cp.async double-buffered, 3 arrays.
// mode 0: fp32 out; 1: Q (fp16 split, QSCALE); 2: K (fp16); 3: Vt (fp16)
// ---------------------------------------------------------------------------
#define GW (128*36)
#define GSMEM2 (2*3*GW*4)            // 110592 B

__device__ __forceinline__ void gemm_stage(
    uint32_t swb, int buf, int tid,
    const __half* sAh, const __half* sAl, const __half* sB, int k0)
{
    const uint32_t dbase = swb + (uint32_t)(buf * 3 * GW) * 4;
#pragma unroll
    for (int j = 0; j < 4; j++) {
        int idx = tid + j * 256;
        int r = idx >> 3, c = idx & 7;
        uint32_t doff = (uint32_t)(r * 36 + c * 4) * 4;
        size_t soff = (size_t)r * EMBED + k0 + c * 8;
        CP_ASYNC16(dbase + doff,                  sAh + soff);
        CP_ASYNC16(dbase + (uint32_t)GW*4 + doff, sAl + soff);
        CP_ASYNC16(dbase + (uint32_t)2*GW*4 + doff, sB + soff);
    }
}

__device__ __forceinline__ void gemm_mma_body(
    const __half* __restrict__ Ah, const __half* __restrict__ Al,
    const __half* __restrict__ B,
    const float* __restrict__ bias, int mode, float* __restrict__ outf, float scale)
{
    extern __shared__ uint32_t sw[];
    const uint32_t swb = smem_u32(sw);
    const int tid = threadIdx.x;
    const int lane = tid & 31, wid = tid >> 5;
    const int g = lane >> 2, t = lane & 3;
    const int wm = wid & 3, wn = wid >> 2;
    const int m0 = blockIdx.y * 128, n0 = blockIdx.x * 128;

    const __half* sAh = Ah + (size_t)m0 * EMBED;
    const __half* sAl = Al + (size_t)m0 * EMBED;
    const __half* sB  = B  + (size_t)n0 * EMBED;

    float acc[2][8][4];
#pragma unroll
    for (int a = 0; a < 2; a++)
#pragma unroll
        for (int b = 0; b < 8; b++)
#pragma unroll
            for (int c = 0; c < 4; c++) acc[a][b][c] = 0.f;

    gemm_stage(swb, 0, tid, sAh, sAl, sB, 0);
    CP_COMMIT();

    for (int it = 0; it < 16; it++) {
        const int buf = it & 1;
        __syncthreads();
        if (it + 1 < 16) {
            gemm_stage(swb, buf ^ 1, tid, sAh, sAl, sB, (it + 1) * 64);
            CP_COMMIT();
            CP_WAIT(1);
        } else {
            CP_WAIT(0);
        }
        __syncthreads();

        uint32_t* Ash = sw + buf * 3 * GW;
        uint32_t* Asl = Ash + GW;
        uint32_t* Bs  = Ash + 2 * GW;

#pragma unroll
        for (int ks = 0; ks < 4; ks++) {
            uint32_t ah[2][4], al[2][4];
#pragma unroll
            for (int mt = 0; mt < 2; mt++) {
                int r = wm * 32 + mt * 16 + g;
                int base = r * 36 + ks * 8 + t;
                ah[mt][0] = Ash[base];     ah[mt][1] = Ash[base + 8*36];
                ah[mt][2] = Ash[base + 4]; ah[mt][3] = Ash[base + 8*36 + 4];
                al[mt][0] = Asl[base];     al[mt][1] = Asl[base + 8*36];
                al[mt][2] = Asl[base + 4]; al[mt][3] = Asl[base + 8*36 + 4];
            }
#pragma unroll
            for (int ntp = 0; ntp < 4; ntp++) {
                uint32_t b0[2], b1[2];
#pragma unroll
                for (int q = 0; q < 2; q++) {
                    int n = wn * 64 + (2 * ntp + q) * 8 + g;
                    int base = n * 36 + ks * 8 + t;
                    b0[q] = Bs[base]; b1[q] = Bs[base + 4];
                }
#pragma unroll
                for (int q = 0; q < 2; q++)
#pragma unroll
                    for (int mt = 0; mt < 2; mt++)
                        MMAF16(acc[mt][2*ntp+q], ah[mt], b0[q], b1[q]);
#pragma unroll
                for (int q = 0; q < 2; q++)
#pragma unroll
                    for (int mt = 0; mt < 2; mt++)
                        MMAF16(acc[mt][2*ntp+q], al[mt], b0[q], b1[q]);
            }
        }
    }

    // epilogue
#pragma unroll
    for (int mt = 0; mt < 2; mt++) {
#pragma unroll
        for (int nt = 0; nt < 8; nt++) {
            int r0 = m0 + wm * 32 + mt * 16 + g;
            int r1 = r0 + 8;
            int c0 = n0 + wn * 64 + nt * 8 + 2 * t;
            float2 bb = *reinterpret_cast<const float2*>(&bias[c0]);
            float v0 = (acc[mt][nt][0] + bb.x) * scale;
            float v1 = (acc[mt][nt][1] + bb.y) * scale;
            float v2 = (acc[mt][nt][2] + bb.x) * scale;
            float v3 = (acc[mt][nt][3] + bb.y) * scale;
            if (mode == 0) {
                *reinterpret_cast<float2*>(&outf[(size_t)r0 * EMBED + c0]) = make_float2(v0, v1);
                *reinterpret_cast<float2*>(&outf[(size_t)r1 * EMBED + c0]) = make_float2(v2, v3);
            } else {
                int hh = c0 >> 6, d = c0 & 63;
                int b0i = r0 >> 11, s0i = r0 & (SEQ - 1);
                int b1i = r1 >> 11, s1i = r1 & (SEQ - 1);
                if (mode == 1) {          // Q: fp16 hi/lo split (pre-scaled)
                    size_t o0 = ((size_t)(b0i*NHEAD+hh)*SEQ + s0i)*HDIM + d;
                    size_t o1 = ((size_t)(b1i*NHEAD+hh)*SEQ + s1i)*HDIM + d;
                    __half h0 = __float2half_rn(v0), h1 = __float2half_rn(v1);
                    __half h2 = __float2half_rn(v2), h3 = __float2half_rn(v3);
                    __half2 hp0(h0, h1), hp1(h2, h3);
                    *reinterpret_cast<__half2*>(g_qfh + o0) = hp0;
                    *reinterpret_cast<uint32_t*>(g_qfl + o0) =
                        pk2h(v0 - __half2float(h0), v1 - __half2float(h1));
                    *reinterpret_cast<__half2*>(g_qfh + o1) = hp1;
                    *reinterpret_cast<uint32_t*>(g_qfl + o1) =
                        pk2h(v2 - __half2float(h2), v3 - __half2float(h3));
                } else if (mode == 2) {   // K: single fp16
                    size_t o0 = ((size_t)(b0i*NHEAD+hh)*SEQ + s0i)*HDIM + d;
                    size_t o1 = ((size_t)(b1i*NHEAD+hh)*SEQ + s1i)*HDIM + d;
                    *reinterpret_cast<uint32_t*>(g_kf + o0) = pk2h(v0, v1);
                    *reinterpret_cast<uint32_t*>(g_kf + o1) = pk2h(v2, v3);
                } else {                  // Vt: single fp16, [b,h,d,s]
                    size_t base0 = (size_t)(b0i*NHEAD+hh)*HDIM*SEQ;
                    size_t base1 = (size_t)(b1i*NHEAD+hh)*HDIM*SEQ;
                    g_vf[base0 + (size_t)d * SEQ + s0i]     = __float2half_rn(v0);
                    g_vf[base0 + (size_t)(d+1) * SEQ + s0i] = __float2half_rn(v1);
                    g_vf[base1 + (size_t)d * SEQ + s1i]     = __float2half_rn(v2);
                    g_vf[base1 + (size_t)(d+1) * SEQ + s1i] = __float2half_rn(v3);
                }
            }
        }
    }
}

extern "C" __global__ void __launch_bounds__(256, 1)
qkv_mma_kernel(const float* __restrict__ bq, const float* __restrict__ bk,
               const float* __restrict__ bv)
{
    const int z = blockIdx.z;
    const __half* B = g_wf + (size_t)z * EMBED * EMBED;
    const float* bias = (z == 0) ? bq : (z == 1) ? bk : bv;
    int mode = (z == 0) ? 1 : (z == 1) ? 2 : 3;
    float scale = (z == 0) ? QSCALE : 1.0f;
    gemm_mma_body(g_xfh, g_xfl, B, bias, mode, nullptr, scale);
}

extern "C" __global__ void __launch_bounds__(256, 1)
oproj_mma_kernel(const float* __restrict__ bo, float* __restrict__ out)
{
    gemm_mma_body(g_cfh, g_cfl, g_wf + (size_t)3 * EMBED * EMBED,
                  bo, 0, out, 1.0f);
}

// ---------------------------------------------------------------------------
// Flash attention (unchanged from R7 except ctx epilogue -> fp16 hi/lo):
//   S = (Qh + Ql)·K ;  O += (Ph + Pl)·V
// ---------------------------------------------------------------------------
#define KW (128*36)
#define VW (64*68)
#define ABUFW (KW + VW)
#define ASMEM2 ((2*ABUFW + SEQ)*4)

__device__ __forceinline__ void attn_stage_kv(
    uint32_t swb, int buf, int tid,
    const __half* kf, const __half* vf, int s0)
{
    const uint32_t dbase = swb + (uint32_t)(buf * ABUFW) * 4;
#pragma unroll
    for (int j = 0; j < 4; j++) {
        int idx = tid + j * 256;
        {
            int r = idx >> 3, c = idx & 7;
            uint32_t doff = (uint32_t)(r * 36 + c * 4) * 4;
            CP_ASYNC16(dbase + doff, kf + (size_t)(s0 + r) * HDIM + c * 8);
        }
        {
            int d = idx >> 4, c = idx & 15;
            uint32_t doff = (uint32_t)(KW + d * 68 + c * 4) * 4;
            CP_ASYNC16(dbase + doff, vf + (size_t)d * SEQ + s0 + c * 8);
        }
    }
}

extern "C" __global__ void __launch_bounds__(256, 1)
attn_mma_kernel(const int* __restrict__ mask)
{
    extern __shared__ uint32_t sw[];
    const uint32_t swb = smem_u32(sw);
    float* mskf = reinterpret_cast<float*>(sw + 2 * ABUFW);

    const int tid = threadIdx.x, lane = tid & 31, wid = tid >> 5;
    const int g = lane >> 2, t = lane & 3;
    const int b = blockIdx.z, h = blockIdx.y;
    const int q0 = blockIdx.x * 128;
    const int qw = wid * 16;
    const size_t bh = (size_t)(b * NHEAD + h);
    const __half* qhp = g_qfh + bh * SEQ * HDIM;
    const __half* qlp = g_qfl + bh * SEQ * HDIM;
    const __half* kfp = g_kf  + bh * SEQ * HDIM;
    const __half* vfp = g_vf  + bh * HDIM * SEQ;
    const int* mb = mask + b * SEQ;

#pragma unroll
    for (int i = 0; i < SEQ / 256; i++)
        mskf[tid + i * 256] = (float)mb[tid + i * 256];

    // ---- stage Q (hi at sw, lo at sw+KW), extract fragments
#pragma unroll
    for (int j = 0; j < 4; j++) {
        int idx = tid + j * 256;
        int r = idx >> 3, c = idx & 7;
        uint32_t doff = (uint32_t)(r * 36 + c * 4) * 4;
        size_t soff = (size_t)(q0 + r) * HDIM + c * 8;
        CP_ASYNC16(swb + doff,                  qhp + soff);
        CP_ASYNC16(swb + (uint32_t)KW*4 + doff, qlp + soff);
    }
    CP_COMMIT();
    CP_WAIT(0);
    __syncthreads();

    uint32_t qh[4][4], ql[4][4];
    {
        uint32_t* Qh = sw;
        uint32_t* Ql = sw + KW;
#pragma unroll
        for (int ks = 0; ks < 4; ks++) {
#pragma unroll
            for (int p = 0; p < 4; p++) {
                int row = qw + g + ((p & 1) ? 8 : 0);
                int col = ks * 8 + t + ((p >= 2) ? 4 : 0);
                qh[ks][p] = Qh[row * 36 + col];
                ql[ks][p] = Ql[row * 36 + col];
            }
        }
    }
    __syncthreads();

    attn_stage_kv(swb, 0, tid, kfp, vfp, 0);
    CP_COMMIT();

    float mrow[2] = {-1e30f, -1e30f};
    float lrow[2] = {0.f, 0.f};
    float o[8][4];
#pragma unroll
    for (int i = 0; i < 8; i++)
#pragma unroll
        for (int j = 0; j < 4; j++) o[i][j] = 0.f;

    for (int it = 0; it < 16; it++) {
        const int buf = it & 1;
        const int s0 = it * 128;
        __syncthreads();
        if (it + 1 < 16) {
            attn_stage_kv(swb, buf ^ 1, tid, kfp, vfp, (it + 1) * 128);
            CP_COMMIT();
            CP_WAIT(1);
        } else {
            CP_WAIT(0);
        }
        __syncthreads();

        uint32_t* Ksh = sw + buf * ABUFW;
        uint32_t* Vth = Ksh + KW;

        // ---- S = Q K^T
        float sc[16][4];
#pragma unroll
        for (int nt = 0; nt < 16; nt++)
#pragma unroll
            for (int j = 0; j < 4; j++) sc[nt][j] = 0.f;
#pragma unroll
        for (int ks = 0; ks < 4; ks++) {
#pragma unroll
            for (int ng = 0; ng < 4; ng++) {
                uint32_t b0[4], b1[4];
#pragma unroll
                for (int q = 0; q < 4; q++) {
                    int base = ((ng * 4 + q) * 8 + g) * 36 + ks * 8 + t;
                    b0[q] = Ksh[base]; b1[q] = Ksh[base + 4];
                }
#pragma unroll
                for (int q = 0; q < 4; q++)
                    MMAF16(sc[ng*4+q], qh[ks], b0[q], b1[q]);
#pragma unroll
                for (int q = 0; q < 4; q++)
                    MMAF16(sc[ng*4+q], ql[ks], b0[q], b1[q]);
            }
        }

        // ---- mask
#pragma unroll
        for (int nt = 0; nt < 16; nt++) {
            float2 mv = *reinterpret_cast<float2*>(&mskf[s0 + nt * 8 + 2 * t]);
            if (mv.x == 0.f) { sc[nt][0] = -1e30f; sc[nt][2] = -1e30f; }
            if (mv.y == 0.f) { sc[nt][1] = -1e30f; sc[nt][3] = -1e30f; }
        }

        // ---- online softmax (base 2)
        float alpha[2];
#pragma unroll
        for (int rh = 0; rh < 2; rh++) {
            float mt_ = -1e30f;
#pragma unroll
            for (int nt = 0; nt < 16; nt++)
                mt_ = fmaxf(mt_, fmaxf(sc[nt][rh * 2 + 0], sc[nt][rh * 2 + 1]));
            mt_ = fmaxf(mt_, __shfl_xor_sync(0xffffffffu, mt_, 1));
            mt_ = fmaxf(mt_, __shfl_xor_sync(0xffffffffu, mt_, 2));
            float mn = fmaxf(mrow[rh], mt_);
            alpha[rh] = ex2(mrow[rh] - mn);
            float ls = 0.f;
#pragma unroll
            for (int nt = 0; nt < 16; nt++) {
                float p0 = ex2(sc[nt][rh * 2 + 0] - mn);
                float p1 = ex2(sc[nt][rh * 2 + 1] - mn);
                sc[nt][rh * 2 + 0] = p0;
                sc[nt][rh * 2 + 1] = p1;
                ls += p0 + p1;
            }
            ls += __shfl_xor_sync(0xffffffffu, ls, 1);
            ls += __shfl_xor_sync(0xffffffffu, ls, 2);
            lrow[rh] = lrow[rh] * alpha[rh] + ls;
            mrow[rh] = mn;
        }
#pragma unroll
        for (int dt = 0; dt < 8; dt++) {
            o[dt][0] *= alpha[0]; o[dt][1] *= alpha[0];
            o[dt][2] *= alpha[1]; o[dt][3] *= alpha[1];
        }

        // ---- O += P V
#pragma unroll
        for (int j = 0; j < 8; j++) {
            uint32_t ph[4], pl[4];
#pragma unroll
            for (int p = 0; p < 4; p++) {
                int nt = 2 * j + (p >> 1);
                int ix = (p & 1) * 2;
                float e0 = sc[nt][ix], e1 = sc[nt][ix + 1];
                __half h0 = __float2half_rn(e0);
                __half h1 = __float2half_rn(e1);
                __half2 hh(h0, h1);
                ph[p] = *reinterpret_cast<uint32_t*>(&hh);
                pl[p] = pk2h(e0 - __half2float(h0), e1 - __half2float(h1));
            }
#pragma unroll
            for (int dg = 0; dg < 2; dg++) {
                uint32_t v0[4], v1[4];
#pragma unroll
                for (int q = 0; q < 4; q++) {
                    int base = ((dg * 4 + q) * 8 + g) * 68 + j * 8 + t;
                    v0[q] = Vth[base]; v1[q] = Vth[base + 4];
                }
#pragma unroll
                for (int q = 0; q < 4; q++)
                    MMAF16(o[dg*4+q], ph, v0[q], v1[q]);
#pragma unroll
                for (int q = 0; q < 4; q++)
                    MMAF16(o[dg*4+q], pl, v0[q], v1[q]);
            }
        }
    }

    // ---- write ctx (fp16 hi/lo) [m][e]
    float inv0 = (lrow[0] > 0.f) ? (1.f / lrow[0]) : 0.f;
    float inv1 = (lrow[1] > 0.f) ? (1.f / lrow[1]) : 0.f;
    int r0 = q0 + qw + g, r1 = r0 + 8;
#pragma unroll
    for (int dt = 0; dt < 8; dt++) {
        int e = h * HDIM + dt * 8 + 2 * t;
        float v0 = o[dt][0] * inv0, v1 = o[dt][1] * inv0;
        float v2 = o[dt][2] * inv1, v3 = o[dt][3] * inv1;
        __half h0 = __float2half_rn(v0), h1 = __float2half_rn(v1);
        __half h2 = __float2half_rn(v2), h3 = __float2half_rn(v3);
        __half2 hp0(h0, h1), hp1(h2, h3);
        *reinterpret_cast<__half2*>(&g_cfh[(size_t)(b * SEQ + r0) * EMBED + e]) = hp0;
        *reinterpret_cast<uint32_t*>(&g_cfl[(size_t)(b * SEQ + r0) * EMBED + e]) =
            pk2h(v0 - __half2float(h0), v1 - __half2float(h1));
        *reinterpret_cast<__half2*>(&g_cfh[(size_t)(b * SEQ + r1) * EMBED + e]) = hp1;
        *reinterpret_cast<uint32_t*>(&g_cfl[(size_t)(b * SEQ + r1) * EMBED + e]) =
            pk2h(v2 - __half2float(h2), v3 - __half2float(h3));
    }
}

// ---------------------------------------------------------------------------
extern "C" void kernel_launch(void* const* d_in, const int* in_sizes, int n_in,
                              void* d_out, int out_size)
{
    const float* x    = (const float*)d_in[0];
    const int*   mask = (const int*)d_in[1];
    const float* Wq   = (const float*)d_in[2];
    const float* bq   = (const float*)d_in[3];
    const float* Wk   = (const float*)d_in[4];
    const float* bk   = (const float*)d_in[5];
    const float* Wv   = (const float*)d_in[6];
    const float* bv   = (const float*)d_in[7];
    const float* Wo   = (const float*)d_in[8];
    const float* bo   = (const float*)d_in[9];
    float* out = (float*)d_out;
    (void)in_sizes; (void)n_in; (void)out_size;

    cudaFuncSetAttribute(qkv_mma_kernel,
                         cudaFuncAttributeMaxDynamicSharedMemorySize, GSMEM2);
    cudaFuncSetAttribute(oproj_mma_kernel,
                         cudaFuncAttributeMaxDynamicSharedMemorySize, GSMEM2);
    cudaFuncSetAttribute(attn_mma_kernel,
                         cudaFuncAttributeMaxDynamicSharedMemorySize, ASMEM2);

    cvt_x_kernel<<<(MROWS * EMBED) / 1024, 256>>>(x);
    cvt_w_kernel<<<dim3(32, 32, 4), dim3(32, 8)>>>(Wq, Wk, Wv, Wo);

    dim3 gq(EMBED / 128, MROWS / 128, 3);
    qkv_mma_kernel<<<gq, 256, GSMEM2>>>(bq, bk, bv);

    dim3 ga(SEQ / 128, NHEAD, BATCH);
    attn_mma_kernel<<<ga, 256, ASMEM2>>>(mask);

    dim3 go(EMBED / 128, MROWS / 128, 1);
    oproj_mma_kernel<<<go, 256, GSMEM2>>>(bo, out);
}

// round 9
// speedup vs baseline: 1.9050x; 1.1732x over previous
#include <cuda_runtime.h>
#include <cuda_bf16.h>
#include <cuda_fp16.h>
#include <cstdint>

#define EMBED 1024
#define NHEAD 16
#define HDIM  64
#define BATCH 2
#define SEQ   2048
#define MROWS (BATCH*SEQ)   // 4096

// ---------------------------------------------------------------------------
// Device-global scratch (fp16):
//  - x, ctx: hi/lo split (2-product projections)
//  - weights, Q, K, Vt: single fp16 (Q pre-scaled by 0.125*log2e)
// ---------------------------------------------------------------------------
__device__ __half g_xfh[MROWS*EMBED],          g_xfl[MROWS*EMBED];
__device__ __half g_wf [4*EMBED*EMBED];                         // W^T [4][n][k]
__device__ __half g_qf [BATCH*NHEAD*SEQ*HDIM];                  // [b,h,s,d]
__device__ __half g_kf [BATCH*NHEAD*SEQ*HDIM];                  // [b,h,s,d]
__device__ __half g_vf [BATCH*NHEAD*HDIM*SEQ];                  // [b,h,d,s]
__device__ __half g_cfh[MROWS*EMBED],          g_cfl[MROWS*EMBED];

// ---------------------------------------------------------------------------
// Helpers
// ---------------------------------------------------------------------------
__device__ __forceinline__ uint32_t smem_u32(const void* p) {
    uint32_t a;
    asm("{ .reg .u64 t; cvta.to.shared.u64 t, %1; cvt.u32.u64 %0, t; }"
        : "=r"(a) : "l"(p));
    return a;
}
__device__ __forceinline__ uint32_t pk2h(float e0, float e1) {  // f16x2, e0 low
    uint32_t d;
    asm("cvt.rn.f16x2.f32 %0, %1, %2;" : "=r"(d) : "f"(e1), "f"(e0));
    return d;
}
__device__ __forceinline__ float ex2(float x) {
    float r;
    asm("ex2.approx.f32 %0, %1;" : "=f"(r) : "f"(x));
    return r;
}

#define MMAF16(c, a, b0, b1)                                                \
    asm("mma.sync.aligned.m16n8k16.row.col.f32.f16.f16.f32 "                \
        "{%0,%1,%2,%3}, {%4,%5,%6,%7}, {%8,%9}, {%0,%1,%2,%3};"             \
        : "+f"((c)[0]), "+f"((c)[1]), "+f"((c)[2]), "+f"((c)[3])            \
        : "r"((a)[0]), "r"((a)[1]), "r"((a)[2]), "r"((a)[3]),               \
          "r"(b0), "r"(b1))

#define CP_ASYNC16(dst, src)                                                \
    asm volatile("cp.async.cg.shared.global [%0], [%1], 16;"                \
        :: "r"(dst), "l"(src) : "memory")
#define CP_COMMIT() asm volatile("cp.async.commit_group;" ::: "memory")
#define CP_WAIT(n)  asm volatile("cp.async.wait_group %0;" :: "n"(n) : "memory")

#define QSCALE 0.180336880111120419f   // 0.125 * log2(e): base-2 softmax

// ---------------------------------------------------------------------------
// Conversion kernels
// ---------------------------------------------------------------------------
extern "C" __global__ void __launch_bounds__(256)
cvt_x_kernel(const float* __restrict__ src)
{
    int i = (blockIdx.x * 256 + threadIdx.x) * 4;
    float4 v = *reinterpret_cast<const float4*>(src + i);
    float vv[4] = {v.x, v.y, v.z, v.w};
    uint32_t hw[2], lw[2];
#pragma unroll
    for (int p = 0; p < 2; p++) {
        float a = vv[2*p], b = vv[2*p+1];
        __half ha = __float2half_rn(a), hb = __float2half_rn(b);
        __half2 hh(ha, hb);
        hw[p] = *reinterpret_cast<uint32_t*>(&hh);
        lw[p] = pk2h(a - __half2float(ha), b - __half2float(hb));
    }
    *reinterpret_cast<uint2*>(g_xfh + i) = make_uint2(hw[0], hw[1]);
    *reinterpret_cast<uint2*>(g_xfl + i) = make_uint2(lw[0], lw[1]);
}

extern "C" __global__ void __launch_bounds__(256)
cvt_w_kernel(const float* __restrict__ Wq, const float* __restrict__ Wk,
             const float* __restrict__ Wv, const float* __restrict__ Wo)
{
    __shared__ float t[32][33];
    const float* W = (blockIdx.z == 0) ? Wq : (blockIdx.z == 1) ? Wk :
                     (blockIdx.z == 2) ? Wv : Wo;
    __half* of = g_wf + (size_t)blockIdx.z * EMBED * EMBED;
    int bx = blockIdx.x * 32;  // n base
    int by = blockIdx.y * 32;  // k base
    int tx = threadIdx.x, ty = threadIdx.y;
#pragma unroll
    for (int i = 0; i < 4; i++) {
        int r = ty + i * 8;
        t[r][tx] = W[(size_t)(by + r) * EMBED + bx + tx];
    }
    __syncthreads();
#pragma unroll
    for (int i = 0; i < 4; i++) {
        int r = ty + i * 8;
        of[(size_t)(bx + r) * EMBED + by + tx] = __float2half_rn(t[tx][r]);
    }
}

// ---------------------------------------------------------------------------
// fp16 2-product GEMM (projections): C = (Ah+Al) @ B^T(+bias)
// 128x128 tile, BK=64, 8 warps (4m x 2n). cp.async double-buffered, 3 arrays.
// mode 0: fp32 out; 1: Q (fp16, QSCALE); 2: K (fp16); 3: Vt (fp16)
// ---------------------------------------------------------------------------
#define GW (128*36)
#define GSMEM2 (2*3*GW*4)            // 110592 B

__device__ __forceinline__ void gemm_stage(
    uint32_t swb, int buf, int tid,
    const __half* sAh, const __half* sAl, const __half* sB, int k0)
{
    const uint32_t dbase = swb + (uint32_t)(buf * 3 * GW) * 4;
#pragma unroll
    for (int j = 0; j < 4; j++) {
        int idx = tid + j * 256;
        int r = idx >> 3, c = idx & 7;
        uint32_t doff = (uint32_t)(r * 36 + c * 4) * 4;
        size_t soff = (size_t)r * EMBED + k0 + c * 8;
        CP_ASYNC16(dbase + doff,                  sAh + soff);
        CP_ASYNC16(dbase + (uint32_t)GW*4 + doff, sAl + soff);
        CP_ASYNC16(dbase + (uint32_t)2*GW*4 + doff, sB + soff);
    }
}

__device__ __forceinline__ void gemm_mma_body(
    const __half* __restrict__ Ah, const __half* __restrict__ Al,
    const __half* __restrict__ B,
    const float* __restrict__ bias, int mode, float* __restrict__ outf, float scale)
{
    extern __shared__ uint32_t sw[];
    const uint32_t swb = smem_u32(sw);
    const int tid = threadIdx.x;
    const int lane = tid & 31, wid = tid >> 5;
    const int g = lane >> 2, t = lane & 3;
    const int wm = wid & 3, wn = wid >> 2;
    const int m0 = blockIdx.y * 128, n0 = blockIdx.x * 128;

    const __half* sAh = Ah + (size_t)m0 * EMBED;
    const __half* sAl = Al + (size_t)m0 * EMBED;
    const __half* sB  = B  + (size_t)n0 * EMBED;

    float acc[2][8][4];
#pragma unroll
    for (int a = 0; a < 2; a++)
#pragma unroll
        for (int b = 0; b < 8; b++)
#pragma unroll
            for (int c = 0; c < 4; c++) acc[a][b][c] = 0.f;

    gemm_stage(swb, 0, tid, sAh, sAl, sB, 0);
    CP_COMMIT();

    for (int it = 0; it < 16; it++) {
        const int buf = it & 1;
        __syncthreads();
        if (it + 1 < 16) {
            gemm_stage(swb, buf ^ 1, tid, sAh, sAl, sB, (it + 1) * 64);
            CP_COMMIT();
            CP_WAIT(1);
        } else {
            CP_WAIT(0);
        }
        __syncthreads();

        uint32_t* Ash = sw + buf * 3 * GW;
        uint32_t* Asl = Ash + GW;
        uint32_t* Bs  = Ash + 2 * GW;

#pragma unroll
        for (int ks = 0; ks < 4; ks++) {
            uint32_t ah[2][4], al[2][4];
#pragma unroll
            for (int mt = 0; mt < 2; mt++) {
                int r = wm * 32 + mt * 16 + g;
                int base = r * 36 + ks * 8 + t;
                ah[mt][0] = Ash[base];     ah[mt][1] = Ash[base + 8*36];
                ah[mt][2] = Ash[base + 4]; ah[mt][3] = Ash[base + 8*36 + 4];
                al[mt][0] = Asl[base];     al[mt][1] = Asl[base + 8*36];
                al[mt][2] = Asl[base + 4]; al[mt][3] = Asl[base + 8*36 + 4];
            }
#pragma unroll
            for (int ntp = 0; ntp < 4; ntp++) {
                uint32_t b0[2], b1[2];
#pragma unroll
                for (int q = 0; q < 2; q++) {
                    int n = wn * 64 + (2 * ntp + q) * 8 + g;
                    int base = n * 36 + ks * 8 + t;
                    b0[q] = Bs[base]; b1[q] = Bs[base + 4];
                }
#pragma unroll
                for (int q = 0; q < 2; q++)
#pragma unroll
                    for (int mt = 0; mt < 2; mt++)
                        MMAF16(acc[mt][2*ntp+q], ah[mt], b0[q], b1[q]);
#pragma unroll
                for (int q = 0; q < 2; q++)
#pragma unroll
                    for (int mt = 0; mt < 2; mt++)
                        MMAF16(acc[mt][2*ntp+q], al[mt], b0[q], b1[q]);
            }
        }
    }

    // epilogue
#pragma unroll
    for (int mt = 0; mt < 2; mt++) {
#pragma unroll
        for (int nt = 0; nt < 8; nt++) {
            int r0 = m0 + wm * 32 + mt * 16 + g;
            int r1 = r0 + 8;
            int c0 = n0 + wn * 64 + nt * 8 + 2 * t;
            float2 bb = *reinterpret_cast<const float2*>(&bias[c0]);
            float v0 = (acc[mt][nt][0] + bb.x) * scale;
            float v1 = (acc[mt][nt][1] + bb.y) * scale;
            float v2 = (acc[mt][nt][2] + bb.x) * scale;
            float v3 = (acc[mt][nt][3] + bb.y) * scale;
            if (mode == 0) {
                *reinterpret_cast<float2*>(&outf[(size_t)r0 * EMBED + c0]) = make_float2(v0, v1);
                *reinterpret_cast<float2*>(&outf[(size_t)r1 * EMBED + c0]) = make_float2(v2, v3);
            } else {
                int hh = c0 >> 6, d = c0 & 63;
                int b0i = r0 >> 11, s0i = r0 & (SEQ - 1);
                int b1i = r1 >> 11, s1i = r1 & (SEQ - 1);
                if (mode <= 2) {          // Q or K: single fp16 [b,h,s,d]
                    __half* dst = (mode == 1) ? g_qf : g_kf;
                    size_t o0 = ((size_t)(b0i*NHEAD+hh)*SEQ + s0i)*HDIM + d;
                    size_t o1 = ((size_t)(b1i*NHEAD+hh)*SEQ + s1i)*HDIM + d;
                    *reinterpret_cast<uint32_t*>(dst + o0) = pk2h(v0, v1);
                    *reinterpret_cast<uint32_t*>(dst + o1) = pk2h(v2, v3);
                } else {                  // Vt: single fp16, [b,h,d,s]
                    size_t base0 = (size_t)(b0i*NHEAD+hh)*HDIM*SEQ;
                    size_t base1 = (size_t)(b1i*NHEAD+hh)*HDIM*SEQ;
                    g_vf[base0 + (size_t)d * SEQ + s0i]     = __float2half_rn(v0);
                    g_vf[base0 + (size_t)(d+1) * SEQ + s0i] = __float2half_rn(v1);
                    g_vf[base1 + (size_t)d * SEQ + s1i]     = __float2half_rn(v2);
                    g_vf[base1 + (size_t)(d+1) * SEQ + s1i] = __float2half_rn(v3);
                }
            }
        }
    }
}

extern "C" __global__ void __launch_bounds__(256, 1)
qkv_mma_kernel(const float* __restrict__ bq, const float* __restrict__ bk,
               const float* __restrict__ bv)
{
    const int z = blockIdx.z;
    const __half* B = g_wf + (size_t)z * EMBED * EMBED;
    const float* bias = (z == 0) ? bq : (z == 1) ? bk : bv;
    int mode = (z == 0) ? 1 : (z == 1) ? 2 : 3;
    float scale = (z == 0) ? QSCALE : 1.0f;
    gemm_mma_body(g_xfh, g_xfl, B, bias, mode, nullptr, scale);
}

extern "C" __global__ void __launch_bounds__(256, 1)
oproj_mma_kernel(const float* __restrict__ bo, float* __restrict__ out)
{
    gemm_mma_body(g_cfh, g_cfl, g_wf + (size_t)3 * EMBED * EMBED,
                  bo, 0, out, 1.0f);
}

// ---------------------------------------------------------------------------
// Flash attention, single-product fp16 MMAs:
//   S = Q·K ;  O += P·V   (Q pre-scaled; P rounded to fp16)
// cp.async double-buffered K/V, base-2 online softmax.
// ---------------------------------------------------------------------------
#define KW (128*36)
#define VW (64*68)
#define ABUFW (KW + VW)
#define ASMEM2 ((2*ABUFW + SEQ)*4)

__device__ __forceinline__ void attn_stage_kv(
    uint32_t swb, int buf, int tid,
    const __half* kf, const __half* vf, int s0)
{
    const uint32_t dbase = swb + (uint32_t)(buf * ABUFW) * 4;
#pragma unroll
    for (int j = 0; j < 4; j++) {
        int idx = tid + j * 256;
        {
            int r = idx >> 3, c = idx & 7;
            uint32_t doff = (uint32_t)(r * 36 + c * 4) * 4;
            CP_ASYNC16(dbase + doff, kf + (size_t)(s0 + r) * HDIM + c * 8);
        }
        {
            int d = idx >> 4, c = idx & 15;
            uint32_t doff = (uint32_t)(KW + d * 68 + c * 4) * 4;
            CP_ASYNC16(dbase + doff, vf + (size_t)d * SEQ + s0 + c * 8);
        }
    }
}

extern "C" __global__ void __launch_bounds__(256, 1)
attn_mma_kernel(const int* __restrict__ mask)
{
    extern __shared__ uint32_t sw[];
    const uint32_t swb = smem_u32(sw);
    float* mskf = reinterpret_cast<float*>(sw + 2 * ABUFW);

    const int tid = threadIdx.x, lane = tid & 31, wid = tid >> 5;
    const int g = lane >> 2, t = lane & 3;
    const int b = blockIdx.z, h = blockIdx.y;
    const int q0 = blockIdx.x * 128;
    const int qw = wid * 16;
    const size_t bh = (size_t)(b * NHEAD + h);
    const __half* qfp = g_qf + bh * SEQ * HDIM;
    const __half* kfp = g_kf + bh * SEQ * HDIM;
    const __half* vfp = g_vf + bh * HDIM * SEQ;
    const int* mb = mask + b * SEQ;

#pragma unroll
    for (int i = 0; i < SEQ / 256; i++)
        mskf[tid + i * 256] = (float)mb[tid + i * 256];

    // ---- stage Q into buffer0 K-area, extract fragments
#pragma unroll
    for (int j = 0; j < 4; j++) {
        int idx = tid + j * 256;
        int r = idx >> 3, c = idx & 7;
        uint32_t doff = (uint32_t)(r * 36 + c * 4) * 4;
        CP_ASYNC16(swb + doff, qfp + (size_t)(q0 + r) * HDIM + c * 8);
    }
    CP_COMMIT();
    CP_WAIT(0);
    __syncthreads();

    uint32_t qh[4][4];
    {
        uint32_t* Qh = sw;
#pragma unroll
        for (int ks = 0; ks < 4; ks++) {
#pragma unroll
            for (int p = 0; p < 4; p++) {
                int row = qw + g + ((p & 1) ? 8 : 0);
                int col = ks * 8 + t + ((p >= 2) ? 4 : 0);
                qh[ks][p] = Qh[row * 36 + col];
            }
        }
    }
    __syncthreads();

    attn_stage_kv(swb, 0, tid, kfp, vfp, 0);
    CP_COMMIT();

    float mrow[2] = {-1e30f, -1e30f};
    float lrow[2] = {0.f, 0.f};
    float o[8][4];
#pragma unroll
    for (int i = 0; i < 8; i++)
#pragma unroll
        for (int j = 0; j < 4; j++) o[i][j] = 0.f;

    for (int it = 0; it < 16; it++) {
        const int buf = it & 1;
        const int s0 = it * 128;
        __syncthreads();
        if (it + 1 < 16) {
            attn_stage_kv(swb, buf ^ 1, tid, kfp, vfp, (it + 1) * 128);
            CP_COMMIT();
            CP_WAIT(1);
        } else {
            CP_WAIT(0);
        }
        __syncthreads();

        uint32_t* Ksh = sw + buf * ABUFW;
        uint32_t* Vth = Ksh + KW;

        // ---- S = Q K^T (single product)
        float sc[16][4];
#pragma unroll
        for (int nt = 0; nt < 16; nt++)
#pragma unroll
            for (int j = 0; j < 4; j++) sc[nt][j] = 0.f;
#pragma unroll
        for (int ks = 0; ks < 4; ks++) {
#pragma unroll
            for (int ng = 0; ng < 4; ng++) {
                uint32_t b0[4], b1[4];
#pragma unroll
                for (int q = 0; q < 4; q++) {
                    int base = ((ng * 4 + q) * 8 + g) * 36 + ks * 8 + t;
                    b0[q] = Ksh[base]; b1[q] = Ksh[base + 4];
                }
#pragma unroll
                for (int q = 0; q < 4; q++)
                    MMAF16(sc[ng*4+q], qh[ks], b0[q], b1[q]);
            }
        }

        // ---- mask
#pragma unroll
        for (int nt = 0; nt < 16; nt++) {
            float2 mv = *reinterpret_cast<float2*>(&mskf[s0 + nt * 8 + 2 * t]);
            if (mv.x == 0.f) { sc[nt][0] = -1e30f; sc[nt][2] = -1e30f; }
            if (mv.y == 0.f) { sc[nt][1] = -1e30f; sc[nt][3] = -1e30f; }
        }

        // ---- online softmax (base 2)
        float alpha[2];
#pragma unroll
        for (int rh = 0; rh < 2; rh++) {
            float mt_ = -1e30f;
#pragma unroll
            for (int nt = 0; nt < 16; nt++)
                mt_ = fmaxf(mt_, fmaxf(sc[nt][rh * 2 + 0], sc[nt][rh * 2 + 1]));
            mt_ = fmaxf(mt_, __shfl_xor_sync(0xffffffffu, mt_, 1));
            mt_ = fmaxf(mt_, __shfl_xor_sync(0xffffffffu, mt_, 2));
            float mn = fmaxf(mrow[rh], mt_);
            alpha[rh] = ex2(mrow[rh] - mn);
            float ls = 0.f;
#pragma unroll
            for (int nt = 0; nt < 16; nt++) {
                float p0 = ex2(sc[nt][rh * 2 + 0] - mn);
                float p1 = ex2(sc[nt][rh * 2 + 1] - mn);
                sc[nt][rh * 2 + 0] = p0;
                sc[nt][rh * 2 + 1] = p1;
                ls += p0 + p1;
            }
            ls += __shfl_xor_sync(0xffffffffu, ls, 1);
            ls += __shfl_xor_sync(0xffffffffu, ls, 2);
            lrow[rh] = lrow[rh] * alpha[rh] + ls;
            mrow[rh] = mn;
        }
#pragma unroll
        for (int dt = 0; dt < 8; dt++) {
            o[dt][0] *= alpha[0]; o[dt][1] *= alpha[0];
            o[dt][2] *= alpha[1]; o[dt][3] *= alpha[1];
        }

        // ---- O += P V (single product; P rounded to fp16)
#pragma unroll
        for (int j = 0; j < 8; j++) {
            uint32_t ph[4];
#pragma unroll
            for (int p = 0; p < 4; p++) {
                int nt = 2 * j + (p >> 1);
                int ix = (p & 1) * 2;
                ph[p] = pk2h(sc[nt][ix], sc[nt][ix + 1]);
            }
#pragma unroll
            for (int dg = 0; dg < 2; dg++) {
                uint32_t v0[4], v1[4];
#pragma unroll
                for (int q = 0; q < 4; q++) {
                    int base = ((dg * 4 + q) * 8 + g) * 68 + j * 8 + t;
                    v0[q] = Vth[base]; v1[q] = Vth[base + 4];
                }
#pragma unroll
                for (int q = 0; q < 4; q++)
                    MMAF16(o[dg*4+q], ph, v0[q], v1[q]);
            }
        }
    }

    // ---- write ctx (fp16 hi/lo) [m][e]
    float inv0 = (lrow[0] > 0.f) ? (1.f / lrow[0]) : 0.f;
    float inv1 = (lrow[1] > 0.f) ? (1.f / lrow[1]) : 0.f;
    int r0 = q0 + qw + g, r1 = r0 + 8;
#pragma unroll
    for (int dt = 0; dt < 8; dt++) {
        int e = h * HDIM + dt * 8 + 2 * t;
        float v0 = o[dt][0] * inv0, v1 = o[dt][1] * inv0;
        float v2 = o[dt][2] * inv1, v3 = o[dt][3] * inv1;
        __half h0 = __float2half_rn(v0), h1 = __float2half_rn(v1);
        __half h2 = __float2half_rn(v2), h3 = __float2half_rn(v3);
        __half2 hp0(h0, h1), hp1(h2, h3);
        *reinterpret_cast<__half2*>(&g_cfh[(size_t)(b * SEQ + r0) * EMBED + e]) = hp0;
        *reinterpret_cast<uint32_t*>(&g_cfl[(size_t)(b * SEQ + r0) * EMBED + e]) =
            pk2h(v0 - __half2float(h0), v1 - __half2float(h1));
        *reinterpret_cast<__half2*>(&g_cfh[(size_t)(b * SEQ + r1) * EMBED + e]) = hp1;
        *reinterpret_cast<uint32_t*>(&g_cfl[(size_t)(b * SEQ + r1) * EMBED + e]) =
            pk2h(v2 - __half2float(h2), v3 - __half2float(h3));
    }
}

// ---------------------------------------------------------------------------
extern "C" void kernel_launch(void* const* d_in, const int* in_sizes, int n_in,
                              void* d_out, int out_size)
{
    const float* x    = (const float*)d_in[0];
    const int*   mask = (const int*)d_in[1];
    const float* Wq   = (const float*)d_in[2];
    const float* bq   = (const float*)d_in[3];
    const float* Wk   = (const float*)d_in[4];
    const float* bk   = (const float*)d_in[5];
    const float* Wv   = (const float*)d_in[6];
    const float* bv   = (const float*)d_in[7];
    const float* Wo   = (const float*)d_in[8];
    const float* bo   = (const float*)d_in[9];
    float* out = (float*)d_out;
    (void)in_sizes; (void)n_in; (void)out_size;

    cudaFuncSetAttribute(qkv_mma_kernel,
                         cudaFuncAttributeMaxDynamicSharedMemorySize, GSMEM2);
    cudaFuncSetAttribute(oproj_mma_kernel,
                         cudaFuncAttributeMaxDynamicSharedMemorySize, GSMEM2);
    cudaFuncSetAttribute(attn_mma_kernel,
                         cudaFuncAttributeMaxDynamicSharedMemorySize, ASMEM2);

    cvt_x_kernel<<<(MROWS * EMBED) / 1024, 256>>>(x);
    cvt_w_kernel<<<dim3(32, 32, 4), dim3(32, 8)>>>(Wq, Wk, Wv, Wo);

    dim3 gq(EMBED / 128, MROWS / 128, 3);
    qkv_mma_kernel<<<gq, 256, GSMEM2>>>(bq, bk, bv);

    dim3 ga(SEQ / 128, NHEAD, BATCH);
    attn_mma_kernel<<<ga, 256, ASMEM2>>>(mask);

    dim3 go(EMBED / 128, MROWS / 128, 1);
    oproj_mma_kernel<<<go, 256, GSMEM2>>>(bo, out);
}

// round 10
// speedup vs baseline: 2.4548x; 1.2886x over previous
#include <cuda_runtime.h>
#include <cuda_bf16.h>
#include <cuda_fp16.h>
#include <cstdint>

#define EMBED 1024
#define NHEAD 16
#define HDIM  64
#define BATCH 2
#define SEQ   2048
#define MROWS (BATCH*SEQ)   // 4096

// ---------------------------------------------------------------------------
// Device-global scratch — single fp16 everywhere.
// Q pre-scaled by 0.125*log2(e) (base-2 softmax domain).
// ---------------------------------------------------------------------------
__device__ __half g_xf [MROWS*EMBED];                           // x  [m][k]
__device__ __half g_wf [4*EMBED*EMBED];                         // W^T [4][n][k]
__device__ __half g_qf [BATCH*NHEAD*SEQ*HDIM];                  // [b,h,s,d]
__device__ __half g_kf [BATCH*NHEAD*SEQ*HDIM];                  // [b,h,s,d]
__device__ __half g_vf [BATCH*NHEAD*HDIM*SEQ];                  // [b,h,d,s]
__device__ __half g_cf [MROWS*EMBED];                           // ctx [m][e]

// ---------------------------------------------------------------------------
// Helpers
// ---------------------------------------------------------------------------
__device__ __forceinline__ uint32_t smem_u32(const void* p) {
    uint32_t a;
    asm("{ .reg .u64 t; cvta.to.shared.u64 t, %1; cvt.u32.u64 %0, t; }"
        : "=r"(a) : "l"(p));
    return a;
}
__device__ __forceinline__ uint32_t pk2h(float e0, float e1) {  // f16x2, e0 low
    uint32_t d;
    asm("cvt.rn.f16x2.f32 %0, %1, %2;" : "=r"(d) : "f"(e1), "f"(e0));
    return d;
}
__device__ __forceinline__ float ex2(float x) {
    float r;
    asm("ex2.approx.f32 %0, %1;" : "=f"(r) : "f"(x));
    return r;
}

#define MMAF16(c, a, b0, b1)                                                \
    asm("mma.sync.aligned.m16n8k16.row.col.f32.f16.f16.f32 "                \
        "{%0,%1,%2,%3}, {%4,%5,%6,%7}, {%8,%9}, {%0,%1,%2,%3};"             \
        : "+f"((c)[0]), "+f"((c)[1]), "+f"((c)[2]), "+f"((c)[3])            \
        : "r"((a)[0]), "r"((a)[1]), "r"((a)[2]), "r"((a)[3]),               \
          "r"(b0), "r"(b1))

#define CP_ASYNC16(dst, src)                                                \
    asm volatile("cp.async.cg.shared.global [%0], [%1], 16;"                \
        :: "r"(dst), "l"(src) : "memory")
#define CP_COMMIT() asm volatile("cp.async.commit_group;" ::: "memory")
#define CP_WAIT(n)  asm volatile("cp.async.wait_group %0;" :: "n"(n) : "memory")

#define QSCALE 0.180336880111120419f   // 0.125 * log2(e)

// ---------------------------------------------------------------------------
// Conversion kernels
// ---------------------------------------------------------------------------
extern "C" __global__ void __launch_bounds__(256)
cvt_x_kernel(const float* __restrict__ src)
{
    int i = (blockIdx.x * 256 + threadIdx.x) * 4;
    float4 v = *reinterpret_cast<const float4*>(src + i);
    *reinterpret_cast<uint2*>(g_xf + i) =
        make_uint2(pk2h(v.x, v.y), pk2h(v.z, v.w));
}

extern "C" __global__ void __launch_bounds__(256)
cvt_w_kernel(const float* __restrict__ Wq, const float* __restrict__ Wk,
             const float* __restrict__ Wv, const float* __restrict__ Wo)
{
    __shared__ float t[32][33];
    const float* W = (blockIdx.z == 0) ? Wq : (blockIdx.z == 1) ? Wk :
                     (blockIdx.z == 2) ? Wv : Wo;
    __half* of = g_wf + (size_t)blockIdx.z * EMBED * EMBED;
    int bx = blockIdx.x * 32;  // n base
    int by = blockIdx.y * 32;  // k base
    int tx = threadIdx.x, ty = threadIdx.y;
#pragma unroll
    for (int i = 0; i < 4; i++) {
        int r = ty + i * 8;
        t[r][tx] = W[(size_t)(by + r) * EMBED + bx + tx];
    }
    __syncthreads();
#pragma unroll
    for (int i = 0; i < 4; i++) {
        int r = ty + i * 8;
        of[(size_t)(bx + r) * EMBED + by + tx] = __float2half_rn(t[tx][r]);
    }
}

// ---------------------------------------------------------------------------
// fp16 single-product GEMM (projections): C = A @ B^T (+bias)
// 128x128 tile, BK=64, 8 warps (4m x 2n). cp.async double-buffered, 2 arrays.
// mode 0: fp32 out; 1: Q (fp16, QSCALE); 2: K (fp16); 3: Vt (fp16)
// ---------------------------------------------------------------------------
#define GW (128*36)
#define GSMEM2 (2*2*GW*4)            // 73728 B

__device__ __forceinline__ void gemm_stage(
    uint32_t swb, int buf, int tid,
    const __half* sA, const __half* sB, int k0)
{
    const uint32_t dbase = swb + (uint32_t)(buf * 2 * GW) * 4;
#pragma unroll
    for (int j = 0; j < 4; j++) {
        int idx = tid + j * 256;
        int r = idx >> 3, c = idx & 7;
        uint32_t doff = (uint32_t)(r * 36 + c * 4) * 4;
        size_t soff = (size_t)r * EMBED + k0 + c * 8;
        CP_ASYNC16(dbase + doff,                  sA + soff);
        CP_ASYNC16(dbase + (uint32_t)GW*4 + doff, sB + soff);
    }
}

__device__ __forceinline__ void gemm_mma_body(
    const __half* __restrict__ A, const __half* __restrict__ B,
    const float* __restrict__ bias, int mode, float* __restrict__ outf, float scale)
{
    extern __shared__ uint32_t sw[];
    const uint32_t swb = smem_u32(sw);
    const int tid = threadIdx.x;
    const int lane = tid & 31, wid = tid >> 5;
    const int g = lane >> 2, t = lane & 3;
    const int wm = wid & 3, wn = wid >> 2;
    const int m0 = blockIdx.y * 128, n0 = blockIdx.x * 128;

    const __half* sA = A + (size_t)m0 * EMBED;
    const __half* sB = B + (size_t)n0 * EMBED;

    float acc[2][8][4];
#pragma unroll
    for (int a = 0; a < 2; a++)
#pragma unroll
        for (int b = 0; b < 8; b++)
#pragma unroll
            for (int c = 0; c < 4; c++) acc[a][b][c] = 0.f;

    gemm_stage(swb, 0, tid, sA, sB, 0);
    CP_COMMIT();

    for (int it = 0; it < 16; it++) {
        const int buf = it & 1;
        __syncthreads();
        if (it + 1 < 16) {
            gemm_stage(swb, buf ^ 1, tid, sA, sB, (it + 1) * 64);
            CP_COMMIT();
            CP_WAIT(1);
        } else {
            CP_WAIT(0);
        }
        __syncthreads();

        uint32_t* As = sw + buf * 2 * GW;
        uint32_t* Bs = As + GW;

#pragma unroll
        for (int ks = 0; ks < 4; ks++) {
            uint32_t ah[2][4];
#pragma unroll
            for (int mt = 0; mt < 2; mt++) {
                int r = wm * 32 + mt * 16 + g;
                int base = r * 36 + ks * 8 + t;
                ah[mt][0] = As[base];     ah[mt][1] = As[base + 8*36];
                ah[mt][2] = As[base + 4]; ah[mt][3] = As[base + 8*36 + 4];
            }
#pragma unroll
            for (int ntp = 0; ntp < 4; ntp++) {
                uint32_t b0[2], b1[2];
#pragma unroll
                for (int q = 0; q < 2; q++) {
                    int n = wn * 64 + (2 * ntp + q) * 8 + g;
                    int base = n * 36 + ks * 8 + t;
                    b0[q] = Bs[base]; b1[q] = Bs[base + 4];
                }
#pragma unroll
                for (int q = 0; q < 2; q++)
#pragma unroll
                    for (int mt = 0; mt < 2; mt++)
                        MMAF16(acc[mt][2*ntp+q], ah[mt], b0[q], b1[q]);
            }
        }
    }

    // epilogue
#pragma unroll
    for (int mt = 0; mt < 2; mt++) {
#pragma unroll
        for (int nt = 0; nt < 8; nt++) {
            int r0 = m0 + wm * 32 + mt * 16 + g;
            int r1 = r0 + 8;
            int c0 = n0 + wn * 64 + nt * 8 + 2 * t;
            float2 bb = *reinterpret_cast<const float2*>(&bias[c0]);
            float v0 = (acc[mt][nt][0] + bb.x) * scale;
            float v1 = (acc[mt][nt][1] + bb.y) * scale;
            float v2 = (acc[mt][nt][2] + bb.x) * scale;
            float v3 = (acc[mt][nt][3] + bb.y) * scale;
            if (mode == 0) {
                *reinterpret_cast<float2*>(&outf[(size_t)r0 * EMBED + c0]) = make_float2(v0, v1);
                *reinterpret_cast<float2*>(&outf[(size_t)r1 * EMBED + c0]) = make_float2(v2, v3);
            } else {
                int hh = c0 >> 6, d = c0 & 63;
                int b0i = r0 >> 11, s0i = r0 & (SEQ - 1);
                int b1i = r1 >> 11, s1i = r1 & (SEQ - 1);
                if (mode <= 2) {          // Q or K: fp16 [b,h,s,d]
                    __half* dst = (mode == 1) ? g_qf : g_kf;
                    size_t o0 = ((size_t)(b0i*NHEAD+hh)*SEQ + s0i)*HDIM + d;
                    size_t o1 = ((size_t)(b1i*NHEAD+hh)*SEQ + s1i)*HDIM + d;
                    *reinterpret_cast<uint32_t*>(dst + o0) = pk2h(v0, v1);
                    *reinterpret_cast<uint32_t*>(dst + o1) = pk2h(v2, v3);
                } else {                  // Vt: fp16, [b,h,d,s]
                    size_t base0 = (size_t)(b0i*NHEAD+hh)*HDIM*SEQ;
                    size_t base1 = (size_t)(b1i*NHEAD+hh)*HDIM*SEQ;
                    g_vf[base0 + (size_t)d * SEQ + s0i]     = __float2half_rn(v0);
                    g_vf[base0 + (size_t)(d+1) * SEQ + s0i] = __float2half_rn(v1);
                    g_vf[base1 + (size_t)d * SEQ + s1i]     = __float2half_rn(v2);
                    g_vf[base1 + (size_t)(d+1) * SEQ + s1i] = __float2half_rn(v3);
                }
            }
        }
    }
}

extern "C" __global__ void __launch_bounds__(256, 1)
qkv_mma_kernel(const float* __restrict__ bq, const float* __restrict__ bk,
               const float* __restrict__ bv)
{
    const int z = blockIdx.z;
    const __half* B = g_wf + (size_t)z * EMBED * EMBED;
    const float* bias = (z == 0) ? bq : (z == 1) ? bk : bv;
    int mode = (z == 0) ? 1 : (z == 1) ? 2 : 3;
    float scale = (z == 0) ? QSCALE : 1.0f;
    gemm_mma_body(g_xf, B, bias, mode, nullptr, scale);
}

extern "C" __global__ void __launch_bounds__(256, 1)
oproj_mma_kernel(const float* __restrict__ bo, float* __restrict__ out)
{
    gemm_mma_body(g_cf, g_wf + (size_t)3 * EMBED * EMBED, bo, 0, out, 1.0f);
}

// ---------------------------------------------------------------------------
// Flash attention (single-product fp16 MMAs, unchanged from R9 except ctx
// epilogue writes single fp16).
// ---------------------------------------------------------------------------
#define KW (128*36)
#define VW (64*68)
#define ABUFW (KW + VW)
#define ASMEM2 ((2*ABUFW + SEQ)*4)

__device__ __forceinline__ void attn_stage_kv(
    uint32_t swb, int buf, int tid,
    const __half* kf, const __half* vf, int s0)
{
    const uint32_t dbase = swb + (uint32_t)(buf * ABUFW) * 4;
#pragma unroll
    for (int j = 0; j < 4; j++) {
        int idx = tid + j * 256;
        {
            int r = idx >> 3, c = idx & 7;
            uint32_t doff = (uint32_t)(r * 36 + c * 4) * 4;
            CP_ASYNC16(dbase + doff, kf + (size_t)(s0 + r) * HDIM + c * 8);
        }
        {
            int d = idx >> 4, c = idx & 15;
            uint32_t doff = (uint32_t)(KW + d * 68 + c * 4) * 4;
            CP_ASYNC16(dbase + doff, vf + (size_t)d * SEQ + s0 + c * 8);
        }
    }
}

extern "C" __global__ void __launch_bounds__(256, 1)
attn_mma_kernel(const int* __restrict__ mask)
{
    extern __shared__ uint32_t sw[];
    const uint32_t swb = smem_u32(sw);
    float* mskf = reinterpret_cast<float*>(sw + 2 * ABUFW);

    const int tid = threadIdx.x, lane = tid & 31, wid = tid >> 5;
    const int g = lane >> 2, t = lane & 3;
    const int b = blockIdx.z, h = blockIdx.y;
    const int q0 = blockIdx.x * 128;
    const int qw = wid * 16;
    const size_t bh = (size_t)(b * NHEAD + h);
    const __half* qfp = g_qf + bh * SEQ * HDIM;
    const __half* kfp = g_kf + bh * SEQ * HDIM;
    const __half* vfp = g_vf + bh * HDIM * SEQ;
    const int* mb = mask + b * SEQ;

#pragma unroll
    for (int i = 0; i < SEQ / 256; i++)
        mskf[tid + i * 256] = (float)mb[tid + i * 256];

    // ---- stage Q into buffer0 K-area, extract fragments
#pragma unroll
    for (int j = 0; j < 4; j++) {
        int idx = tid + j * 256;
        int r = idx >> 3, c = idx & 7;
        uint32_t doff = (uint32_t)(r * 36 + c * 4) * 4;
        CP_ASYNC16(swb + doff, qfp + (size_t)(q0 + r) * HDIM + c * 8);
    }
    CP_COMMIT();
    CP_WAIT(0);
    __syncthreads();

    uint32_t qh[4][4];
    {
        uint32_t* Qh = sw;
#pragma unroll
        for (int ks = 0; ks < 4; ks++) {
#pragma unroll
            for (int p = 0; p < 4; p++) {
                int row = qw + g + ((p & 1) ? 8 : 0);
                int col = ks * 8 + t + ((p >= 2) ? 4 : 0);
                qh[ks][p] = Qh[row * 36 + col];
            }
        }
    }
    __syncthreads();

    attn_stage_kv(swb, 0, tid, kfp, vfp, 0);
    CP_COMMIT();

    float mrow[2] = {-1e30f, -1e30f};
    float lrow[2] = {0.f, 0.f};
    float o[8][4];
#pragma unroll
    for (int i = 0; i < 8; i++)
#pragma unroll
        for (int j = 0; j < 4; j++) o[i][j] = 0.f;

    for (int it = 0; it < 16; it++) {
        const int buf = it & 1;
        const int s0 = it * 128;
        __syncthreads();
        if (it + 1 < 16) {
            attn_stage_kv(swb, buf ^ 1, tid, kfp, vfp, (it + 1) * 128);
            CP_COMMIT();
            CP_WAIT(1);
        } else {
            CP_WAIT(0);
        }
        __syncthreads();

        uint32_t* Ksh = sw + buf * ABUFW;
        uint32_t* Vth = Ksh + KW;

        // ---- S = Q K^T
        float sc[16][4];
#pragma unroll
        for (int nt = 0; nt < 16; nt++)
#pragma unroll
            for (int j = 0; j < 4; j++) sc[nt][j] = 0.f;
#pragma unroll
        for (int ks = 0; ks < 4; ks++) {
#pragma unroll
            for (int ng = 0; ng < 4; ng++) {
                uint32_t b0[4], b1[4];
#pragma unroll
                for (int q = 0; q < 4; q++) {
                    int base = ((ng * 4 + q) * 8 + g) * 36 + ks * 8 + t;
                    b0[q] = Ksh[base]; b1[q] = Ksh[base + 4];
                }
#pragma unroll
                for (int q = 0; q < 4; q++)
                    MMAF16(sc[ng*4+q], qh[ks], b0[q], b1[q]);
            }
        }

        // ---- mask
#pragma unroll
        for (int nt = 0; nt < 16; nt++) {
            float2 mv = *reinterpret_cast<float2*>(&mskf[s0 + nt * 8 + 2 * t]);
            if (mv.x == 0.f) { sc[nt][0] = -1e30f; sc[nt][2] = -1e30f; }
            if (mv.y == 0.f) { sc[nt][1] = -1e30f; sc[nt][3] = -1e30f; }
        }

        // ---- online softmax (base 2)
        float alpha[2];
#pragma unroll
        for (int rh = 0; rh < 2; rh++) {
            float mt_ = -1e30f;
#pragma unroll
            for (int nt = 0; nt < 16; nt++)
                mt_ = fmaxf(mt_, fmaxf(sc[nt][rh * 2 + 0], sc[nt][rh * 2 + 1]));
            mt_ = fmaxf(mt_, __shfl_xor_sync(0xffffffffu, mt_, 1));
            mt_ = fmaxf(mt_, __shfl_xor_sync(0xffffffffu, mt_, 2));
            float mn = fmaxf(mrow[rh], mt_);
            alpha[rh] = ex2(mrow[rh] - mn);
            float ls = 0.f;
#pragma unroll
            for (int nt = 0; nt < 16; nt++) {
                float p0 = ex2(sc[nt][rh * 2 + 0] - mn);
                float p1 = ex2(sc[nt][rh * 2 + 1] - mn);
                sc[nt][rh * 2 + 0] = p0;
                sc[nt][rh * 2 + 1] = p1;
                ls += p0 + p1;
            }
            ls += __shfl_xor_sync(0xffffffffu, ls, 1);
            ls += __shfl_xor_sync(0xffffffffu, ls, 2);
            lrow[rh] = lrow[rh] * alpha[rh] + ls;
            mrow[rh] = mn;
        }
#pragma unroll
        for (int dt = 0; dt < 8; dt++) {
            o[dt][0] *= alpha[0]; o[dt][1] *= alpha[0];
            o[dt][2] *= alpha[1]; o[dt][3] *= alpha[1];
        }

        // ---- O += P V
#pragma unroll
        for (int j = 0; j < 8; j++) {
            uint32_t ph[4];
#pragma unroll
            for (int p = 0; p < 4; p++) {
                int nt = 2 * j + (p >> 1);
                int ix = (p & 1) * 2;
                ph[p] = pk2h(sc[nt][ix], sc[nt][ix + 1]);
            }
#pragma unroll
            for (int dg = 0; dg < 2; dg++) {
                uint32_t v0[4], v1[4];
#pragma unroll
                for (int q = 0; q < 4; q++) {
                    int base = ((dg * 4 + q) * 8 + g) * 68 + j * 8 + t;
                    v0[q] = Vth[base]; v1[q] = Vth[base + 4];
                }
#pragma unroll
                for (int q = 0; q < 4; q++)
                    MMAF16(o[dg*4+q], ph, v0[q], v1[q]);
            }
        }
    }

    // ---- write ctx (single fp16) [m][e]
    float inv0 = (lrow[0] > 0.f) ? (1.f / lrow[0]) : 0.f;
    float inv1 = (lrow[1] > 0.f) ? (1.f / lrow[1]) : 0.f;
    int r0 = q0 + qw + g, r1 = r0 + 8;
#pragma unroll
    for (int dt = 0; dt < 8; dt++) {
        int e = h * HDIM + dt * 8 + 2 * t;
        *reinterpret_cast<uint32_t*>(&g_cf[(size_t)(b * SEQ + r0) * EMBED + e]) =
            pk2h(o[dt][0] * inv0, o[dt][1] * inv0);
        *reinterpret_cast<uint32_t*>(&g_cf[(size_t)(b * SEQ + r1) * EMBED + e]) =
            pk2h(o[dt][2] * inv1, o[dt][3] * inv1);
    }
}

// ---------------------------------------------------------------------------
extern "C" void kernel_launch(void* const* d_in, const int* in_sizes, int n_in,
                              void* d_out, int out_size)
{
    const float* x    = (const float*)d_in[0];
    const int*   mask = (const int*)d_in[1];
    const float* Wq   = (const float*)d_in[2];
    const float* bq   = (const float*)d_in[3];
    const float* Wk   = (const float*)d_in[4];
    const float* bk   = (const float*)d_in[5];
    const float* Wv   = (const float*)d_in[6];
    const float* bv   = (const float*)d_in[7];
    const float* Wo   = (const float*)d_in[8];
    const float* bo   = (const float*)d_in[9];
    float* out = (float*)d_out;
    (void)in_sizes; (void)n_in; (void)out_size;

    cudaFuncSetAttribute(qkv_mma_kernel,
                         cudaFuncAttributeMaxDynamicSharedMemorySize, GSMEM2);
    cudaFuncSetAttribute(oproj_mma_kernel,
                         cudaFuncAttributeMaxDynamicSharedMemorySize, GSMEM2);
    cudaFuncSetAttribute(attn_mma_kernel,
                         cudaFuncAttributeMaxDynamicSharedMemorySize, ASMEM2);

    cvt_x_kernel<<<(MROWS * EMBED) / 1024, 256>>>(x);
    cvt_w_kernel<<<dim3(32, 32, 4), dim3(32, 8)>>>(Wq, Wk, Wv, Wo);

    dim3 gq(EMBED / 128, MROWS / 128, 3);
    qkv_mma_kernel<<<gq, 256, GSMEM2>>>(bq, bk, bv);

    dim3 ga(SEQ / 128, NHEAD, BATCH);
    attn_mma_kernel<<<ga, 256, ASMEM2>>>(mask);

    dim3 go(EMBED / 128, MROWS / 128, 1);
    oproj_mma_kernel<<<go, 256, GSMEM2>>>(bo, out);
}

// round 11
// speedup vs baseline: 2.5402x; 1.0348x over previous
#include <cuda_runtime.h>
#include <cuda_bf16.h>
#include <cuda_fp16.h>
#include <cstdint>

#define EMBED 1024
#define NHEAD 16
#define HDIM  64
#define BATCH 2
#define SEQ   2048
#define MROWS (BATCH*SEQ)   // 4096

// ---------------------------------------------------------------------------
// Device-global scratch — single fp16 everywhere.
// Q pre-scaled by 0.125*log2(e) (base-2 softmax domain).
// ---------------------------------------------------------------------------
__device__ __half g_xf [MROWS*EMBED];                           // x  [m][k]
__device__ __half g_wf [4*EMBED*EMBED];                         // W^T [4][n][k]
__device__ __half g_qf [BATCH*NHEAD*SEQ*HDIM];                  // [b,h,s,d]
__device__ __half g_kf [BATCH*NHEAD*SEQ*HDIM];                  // [b,h,s,d]
__device__ __half g_vf [BATCH*NHEAD*HDIM*SEQ];                  // [b,h,d,s]
__device__ __half g_cf [MROWS*EMBED];                           // ctx [m][e]

// ---------------------------------------------------------------------------
// Helpers
// ---------------------------------------------------------------------------
__device__ __forceinline__ uint32_t smem_u32(const void* p) {
    uint32_t a;
    asm("{ .reg .u64 t; cvta.to.shared.u64 t, %1; cvt.u32.u64 %0, t; }"
        : "=r"(a) : "l"(p));
    return a;
}
__device__ __forceinline__ uint32_t pk2h(float e0, float e1) {  // f16x2, e0 low
    uint32_t d;
    asm("cvt.rn.f16x2.f32 %0, %1, %2;" : "=r"(d) : "f"(e1), "f"(e0));
    return d;
}
__device__ __forceinline__ float ex2(float x) {
    float r;
    asm("ex2.approx.f32 %0, %1;" : "=f"(r) : "f"(x));
    return r;
}
__device__ __forceinline__ uint32_t ex2h2(uint32_t x) {         // 2x fp16 exp2
    uint32_t d;
    asm("ex2.approx.f16x2 %0, %1;" : "=r"(d) : "r"(x));
    return d;
}

#define MMAF16(c, a, b0, b1)                                                \
    asm("mma.sync.aligned.m16n8k16.row.col.f32.f16.f16.f32 "                \
        "{%0,%1,%2,%3}, {%4,%5,%6,%7}, {%8,%9}, {%0,%1,%2,%3};"             \
        : "+f"((c)[0]), "+f"((c)[1]), "+f"((c)[2]), "+f"((c)[3])            \
        : "r"((a)[0]), "r"((a)[1]), "r"((a)[2]), "r"((a)[3]),               \
          "r"(b0), "r"(b1))

#define CP_ASYNC16(dst, src)                                                \
    asm volatile("cp.async.cg.shared.global [%0], [%1], 16;"                \
        :: "r"(dst), "l"(src) : "memory")
#define CP_COMMIT() asm volatile("cp.async.commit_group;" ::: "memory")
#define CP_WAIT(n)  asm volatile("cp.async.wait_group %0;" :: "n"(n) : "memory")

#define QSCALE 0.180336880111120419f   // 0.125 * log2(e)

// ---------------------------------------------------------------------------
// Conversion kernels
// ---------------------------------------------------------------------------
extern "C" __global__ void __launch_bounds__(256)
cvt_x_kernel(const float* __restrict__ src)
{
    int i = (blockIdx.x * 256 + threadIdx.x) * 4;
    float4 v = *reinterpret_cast<const float4*>(src + i);
    *reinterpret_cast<uint2*>(g_xf + i) =
        make_uint2(pk2h(v.x, v.y), pk2h(v.z, v.w));
}

extern "C" __global__ void __launch_bounds__(256)
cvt_w_kernel(const float* __restrict__ Wq, const float* __restrict__ Wk,
             const float* __restrict__ Wv, const float* __restrict__ Wo)
{
    __shared__ float t[32][33];
    const float* W = (blockIdx.z == 0) ? Wq : (blockIdx.z == 1) ? Wk :
                     (blockIdx.z == 2) ? Wv : Wo;
    __half* of = g_wf + (size_t)blockIdx.z * EMBED * EMBED;
    int bx = blockIdx.x * 32;  // n base
    int by = blockIdx.y * 32;  // k base
    int tx = threadIdx.x, ty = threadIdx.y;
#pragma unroll
    for (int i = 0; i < 4; i++) {
        int r = ty + i * 8;
        t[r][tx] = W[(size_t)(by + r) * EMBED + bx + tx];
    }
    __syncthreads();
#pragma unroll
    for (int i = 0; i < 4; i++) {
        int r = ty + i * 8;
        of[(size_t)(bx + r) * EMBED + by + tx] = __float2half_rn(t[tx][r]);
    }
}

// ---------------------------------------------------------------------------
// fp16 single-product GEMM (projections) — unchanged from R10 (at mma roofline)
// ---------------------------------------------------------------------------
#define GW (128*36)
#define GSMEM2 (2*2*GW*4)            // 73728 B

__device__ __forceinline__ void gemm_stage(
    uint32_t swb, int buf, int tid,
    const __half* sA, const __half* sB, int k0)
{
    const uint32_t dbase = swb + (uint32_t)(buf * 2 * GW) * 4;
#pragma unroll
    for (int j = 0; j < 4; j++) {
        int idx = tid + j * 256;
        int r = idx >> 3, c = idx & 7;
        uint32_t doff = (uint32_t)(r * 36 + c * 4) * 4;
        size_t soff = (size_t)r * EMBED + k0 + c * 8;
        CP_ASYNC16(dbase + doff,                  sA + soff);
        CP_ASYNC16(dbase + (uint32_t)GW*4 + doff, sB + soff);
    }
}

__device__ __forceinline__ void gemm_mma_body(
    const __half* __restrict__ A, const __half* __restrict__ B,
    const float* __restrict__ bias, int mode, float* __restrict__ outf, float scale)
{
    extern __shared__ uint32_t sw[];
    const uint32_t swb = smem_u32(sw);
    const int tid = threadIdx.x;
    const int lane = tid & 31, wid = tid >> 5;
    const int g = lane >> 2, t = lane & 3;
    const int wm = wid & 3, wn = wid >> 2;
    const int m0 = blockIdx.y * 128, n0 = blockIdx.x * 128;

    const __half* sA = A + (size_t)m0 * EMBED;
    const __half* sB = B + (size_t)n0 * EMBED;

    float acc[2][8][4];
#pragma unroll
    for (int a = 0; a < 2; a++)
#pragma unroll
        for (int b = 0; b < 8; b++)
#pragma unroll
            for (int c = 0; c < 4; c++) acc[a][b][c] = 0.f;

    gemm_stage(swb, 0, tid, sA, sB, 0);
    CP_COMMIT();

    for (int it = 0; it < 16; it++) {
        const int buf = it & 1;
        __syncthreads();
        if (it + 1 < 16) {
            gemm_stage(swb, buf ^ 1, tid, sA, sB, (it + 1) * 64);
            CP_COMMIT();
            CP_WAIT(1);
        } else {
            CP_WAIT(0);
        }
        __syncthreads();

        uint32_t* As = sw + buf * 2 * GW;
        uint32_t* Bs = As + GW;

#pragma unroll
        for (int ks = 0; ks < 4; ks++) {
            uint32_t ah[2][4];
#pragma unroll
            for (int mt = 0; mt < 2; mt++) {
                int r = wm * 32 + mt * 16 + g;
                int base = r * 36 + ks * 8 + t;
                ah[mt][0] = As[base];     ah[mt][1] = As[base + 8*36];
                ah[mt][2] = As[base + 4]; ah[mt][3] = As[base + 8*36 + 4];
            }
#pragma unroll
            for (int ntp = 0; ntp < 4; ntp++) {
                uint32_t b0[2], b1[2];
#pragma unroll
                for (int q = 0; q < 2; q++) {
                    int n = wn * 64 + (2 * ntp + q) * 8 + g;
                    int base = n * 36 + ks * 8 + t;
                    b0[q] = Bs[base]; b1[q] = Bs[base + 4];
                }
#pragma unroll
                for (int q = 0; q < 2; q++)
#pragma unroll
                    for (int mt = 0; mt < 2; mt++)
                        MMAF16(acc[mt][2*ntp+q], ah[mt], b0[q], b1[q]);
            }
        }
    }

    // epilogue
#pragma unroll
    for (int mt = 0; mt < 2; mt++) {
#pragma unroll
        for (int nt = 0; nt < 8; nt++) {
            int r0 = m0 + wm * 32 + mt * 16 + g;
            int r1 = r0 + 8;
            int c0 = n0 + wn * 64 + nt * 8 + 2 * t;
            float2 bb = *reinterpret_cast<const float2*>(&bias[c0]);
            float v0 = (acc[mt][nt][0] + bb.x) * scale;
            float v1 = (acc[mt][nt][1] + bb.y) * scale;
            float v2 = (acc[mt][nt][2] + bb.x) * scale;
            float v3 = (acc[mt][nt][3] + bb.y) * scale;
            if (mode == 0) {
                *reinterpret_cast<float2*>(&outf[(size_t)r0 * EMBED + c0]) = make_float2(v0, v1);
                *reinterpret_cast<float2*>(&outf[(size_t)r1 * EMBED + c0]) = make_float2(v2, v3);
            } else {
                int hh = c0 >> 6, d = c0 & 63;
                int b0i = r0 >> 11, s0i = r0 & (SEQ - 1);
                int b1i = r1 >> 11, s1i = r1 & (SEQ - 1);
                if (mode <= 2) {          // Q or K: fp16 [b,h,s,d]
                    __half* dst = (mode == 1) ? g_qf : g_kf;
                    size_t o0 = ((size_t)(b0i*NHEAD+hh)*SEQ + s0i)*HDIM + d;
                    size_t o1 = ((size_t)(b1i*NHEAD+hh)*SEQ + s1i)*HDIM + d;
                    *reinterpret_cast<uint32_t*>(dst + o0) = pk2h(v0, v1);
                    *reinterpret_cast<uint32_t*>(dst + o1) = pk2h(v2, v3);
                } else {                  // Vt: fp16, [b,h,d,s]
                    size_t base0 = (size_t)(b0i*NHEAD+hh)*HDIM*SEQ;
                    size_t base1 = (size_t)(b1i*NHEAD+hh)*HDIM*SEQ;
                    g_vf[base0 + (size_t)d * SEQ + s0i]     = __float2half_rn(v0);
                    g_vf[base0 + (size_t)(d+1) * SEQ + s0i] = __float2half_rn(v1);
                    g_vf[base1 + (size_t)d * SEQ + s1i]     = __float2half_rn(v2);
                    g_vf[base1 + (size_t)(d+1) * SEQ + s1i] = __float2half_rn(v3);
                }
            }
        }
    }
}

extern "C" __global__ void __launch_bounds__(256, 1)
qkv_mma_kernel(const float* __restrict__ bq, const float* __restrict__ bk,
               const float* __restrict__ bv)
{
    const int z = blockIdx.z;
    const __half* B = g_wf + (size_t)z * EMBED * EMBED;
    const float* bias = (z == 0) ? bq : (z == 1) ? bk : bv;
    int mode = (z == 0) ? 1 : (z == 1) ? 2 : 3;
    float scale = (z == 0) ? QSCALE : 1.0f;
    gemm_mma_body(g_xf, B, bias, mode, nullptr, scale);
}

extern "C" __global__ void __launch_bounds__(256, 1)
oproj_mma_kernel(const float* __restrict__ bo, float* __restrict__ out)
{
    gemm_mma_body(g_cf, g_wf + (size_t)3 * EMBED * EMBED, bo, 0, out, 1.0f);
}

// ---------------------------------------------------------------------------
// Flash attention:
//   - 3-stage cp.async pipeline, ONE __syncthreads per iteration
//   - l computed by PV MMA via ones-row appended to V (row 64 of V tile)
//   - P fragments via ex2.approx.f16x2 directly (no fp32 exp, no writeback)
// ---------------------------------------------------------------------------
#define KW (128*36)
#define VW2 (72*68)                       // 64 data rows + ones row + 7 zero rows
#define ABUFW (KW + VW2)                  // 9504 words per buffer
#define NBUF 3
#define ASMEM2 ((NBUF*ABUFW + SEQ)*4)     // 122240 B

__device__ __forceinline__ void attn_stage_kv(
    uint32_t swb, int buf, int tid,
    const __half* kf, const __half* vf, int s0)
{
    const uint32_t dbase = swb + (uint32_t)(buf * ABUFW) * 4;
#pragma unroll
    for (int j = 0; j < 4; j++) {
        int idx = tid + j * 256;
        {
            int r = idx >> 3, c = idx & 7;
            uint32_t doff = (uint32_t)(r * 36 + c * 4) * 4;
            CP_ASYNC16(dbase + doff, kf + (size_t)(s0 + r) * HDIM + c * 8);
        }
        {
            int d = idx >> 4, c = idx & 15;                 // d in [0,64)
            uint32_t doff = (uint32_t)(KW + d * 68 + c * 4) * 4;
            CP_ASYNC16(dbase + doff, vf + (size_t)d * SEQ + s0 + c * 8);
        }
    }
}

extern "C" __global__ void __launch_bounds__(256, 1)
attn_mma_kernel(const int* __restrict__ mask)
{
    extern __shared__ uint32_t sw[];
    const uint32_t swb = smem_u32(sw);
    float* mskf = reinterpret_cast<float*>(sw + NBUF * ABUFW);

    const int tid = threadIdx.x, lane = tid & 31, wid = tid >> 5;
    const int g = lane >> 2, t = lane & 3;
    const int b = blockIdx.z, h = blockIdx.y;
    const int q0 = blockIdx.x * 128;
    const int qw = wid * 16;
    const size_t bh = (size_t)(b * NHEAD + h);
    const __half* qfp = g_qf + bh * SEQ * HDIM;
    const __half* kfp = g_kf + bh * SEQ * HDIM;
    const __half* vfp = g_vf + bh * HDIM * SEQ;
    const int* mb = mask + b * SEQ;

    // mask row to smem (once)
#pragma unroll
    for (int i = 0; i < SEQ / 256; i++)
        mskf[tid + i * 256] = (float)mb[tid + i * 256];

    // ones-row (row 64 = 1.0) and zero rows (65..71) of V region, all buffers
    for (int i = tid; i < NBUF * 8 * 68; i += 256) {
        int bufi = i / (8 * 68);
        int rr = (i / 68) % 8;
        int cc = i % 68;
        sw[bufi * ABUFW + KW + (64 + rr) * 68 + cc] =
            (rr == 0) ? 0x3C003C00u : 0u;
    }

    // ---- stage Q into buf0 K-area, extract fragments
#pragma unroll
    for (int j = 0; j < 4; j++) {
        int idx = tid + j * 256;
        int r = idx >> 3, c = idx & 7;
        uint32_t doff = (uint32_t)(r * 36 + c * 4) * 4;
        CP_ASYNC16(swb + doff, qfp + (size_t)(q0 + r) * HDIM + c * 8);
    }
    CP_COMMIT();
    CP_WAIT(0);
    __syncthreads();

    uint32_t qh[4][4];
#pragma unroll
    for (int ks = 0; ks < 4; ks++) {
#pragma unroll
        for (int p = 0; p < 4; p++) {
            int row = qw + g + ((p & 1) ? 8 : 0);
            int col = ks * 8 + t + ((p >= 2) ? 4 : 0);
            qh[ks][p] = sw[row * 36 + col];
        }
    }
    __syncthreads();

    // ---- prologue: prefetch tiles 0 and 1
    attn_stage_kv(swb, 0, tid, kfp, vfp, 0);
    CP_COMMIT();
    attn_stage_kv(swb, 1, tid, kfp, vfp, 128);
    CP_COMMIT();

    float mrow[2] = {-1e30f, -1e30f};
    float o[8][4], ol[4];
#pragma unroll
    for (int i = 0; i < 8; i++)
#pragma unroll
        for (int j = 0; j < 4; j++) o[i][j] = 0.f;
#pragma unroll
    for (int j = 0; j < 4; j++) ol[j] = 0.f;

    for (int it = 0; it < 16; it++) {
        const int buf = it % 3;
        const int s0 = it * 128;
        CP_WAIT(1);        // tile `it` landed (tile it+1 may still be in flight)
        __syncthreads();   // visible to all; also gates buffer reuse

        uint32_t* Ksh = sw + buf * ABUFW;
        uint32_t* Vth = Ksh + KW;

        // ---- S = Q K^T
        float sc[16][4];
#pragma unroll
        for (int nt = 0; nt < 16; nt++)
#pragma unroll
            for (int j = 0; j < 4; j++) sc[nt][j] = 0.f;
#pragma unroll
        for (int ks = 0; ks < 4; ks++) {
#pragma unroll
            for (int ng = 0; ng < 4; ng++) {
                uint32_t b0[4], b1[4];
#pragma unroll
                for (int q = 0; q < 4; q++) {
                    int base = ((ng * 4 + q) * 8 + g) * 36 + ks * 8 + t;
                    b0[q] = Ksh[base]; b1[q] = Ksh[base + 4];
                }
#pragma unroll
                for (int q = 0; q < 4; q++)
                    MMAF16(sc[ng*4+q], qh[ks], b0[q], b1[q]);
            }
        }

        // ---- mask
#pragma unroll
        for (int nt = 0; nt < 16; nt++) {
            float2 mv = *reinterpret_cast<float2*>(&mskf[s0 + nt * 8 + 2 * t]);
            if (mv.x == 0.f) { sc[nt][0] = -1e30f; sc[nt][2] = -1e30f; }
            if (mv.y == 0.f) { sc[nt][1] = -1e30f; sc[nt][3] = -1e30f; }
        }

        // ---- online max + rescale (sum comes from the MMA ones-column)
        float alpha[2];
#pragma unroll
        for (int rh = 0; rh < 2; rh++) {
            float mt_ = -1e30f;
#pragma unroll
            for (int nt = 0; nt < 16; nt++)
                mt_ = fmaxf(mt_, fmaxf(sc[nt][rh * 2 + 0], sc[nt][rh * 2 + 1]));
            mt_ = fmaxf(mt_, __shfl_xor_sync(0xffffffffu, mt_, 1));
            mt_ = fmaxf(mt_, __shfl_xor_sync(0xffffffffu, mt_, 2));
            float mn = fmaxf(mrow[rh], mt_);
            alpha[rh] = ex2(mrow[rh] - mn);
            mrow[rh] = mn;
        }
#pragma unroll
        for (int dt = 0; dt < 8; dt++) {
            o[dt][0] *= alpha[0]; o[dt][1] *= alpha[0];
            o[dt][2] *= alpha[1]; o[dt][3] *= alpha[1];
        }
        ol[0] *= alpha[0]; ol[1] *= alpha[0];
        ol[2] *= alpha[1]; ol[3] *= alpha[1];

        // ---- O += P V ; l accumulates in ones-column tile (ol)
#pragma unroll
        for (int j = 0; j < 8; j++) {
            uint32_t ph[4];
#pragma unroll
            for (int p = 0; p < 4; p++) {
                int nt = 2 * j + (p >> 1);
                int rh = p & 1;
                int ix = rh * 2;
                ph[p] = ex2h2(pk2h(sc[nt][ix]     - mrow[rh],
                                   sc[nt][ix + 1] - mrow[rh]));
            }
#pragma unroll
            for (int dg = 0; dg < 2; dg++) {
                uint32_t v0[4], v1[4];
#pragma unroll
                for (int q = 0; q < 4; q++) {
                    int base = ((dg * 4 + q) * 8 + g) * 68 + j * 8 + t;
                    v0[q] = Vth[base]; v1[q] = Vth[base + 4];
                }
#pragma unroll
                for (int q = 0; q < 4; q++)
                    MMAF16(o[dg*4+q], ph, v0[q], v1[q]);
            }
            {   // l tile: rows 64..71 (64 = ones, rest zero)
                int base = (64 + g) * 68 + j * 8 + t;
                uint32_t v0l = Vth[base], v1l = Vth[base + 4];
                MMAF16(ol, ph, v0l, v1l);
            }
        }

        // ---- prefetch tile it+2 (empty commit keeps group accounting uniform)
        if (it + 2 < 16)
            attn_stage_kv(swb, (it + 2) % 3, tid, kfp, vfp, (it + 2) * 128);
        CP_COMMIT();
    }

    // ---- l lives in column 64 (t==0 lanes); broadcast within quad
    float l0 = __shfl_sync(0xffffffffu, ol[0], lane & 28);
    float l1 = __shfl_sync(0xffffffffu, ol[2], lane & 28);
    float inv0 = (l0 > 0.f) ? (1.f / l0) : 0.f;
    float inv1 = (l1 > 0.f) ? (1.f / l1) : 0.f;
    int r0 = q0 + qw + g, r1 = r0 + 8;
#pragma unroll
    for (int dt = 0; dt < 8; dt++) {
        int e = h * HDIM + dt * 8 + 2 * t;
        *reinterpret_cast<uint32_t*>(&g_cf[(size_t)(b * SEQ + r0) * EMBED + e]) =
            pk2h(o[dt][0] * inv0, o[dt][1] * inv0);
        *reinterpret_cast<uint32_t*>(&g_cf[(size_t)(b * SEQ + r1) * EMBED + e]) =
            pk2h(o[dt][2] * inv1, o[dt][3] * inv1);
    }
}

// ---------------------------------------------------------------------------
extern "C" void kernel_launch(void* const* d_in, const int* in_sizes, int n_in,
                              void* d_out, int out_size)
{
    const float* x    = (const float*)d_in[0];
    const int*   mask = (const int*)d_in[1];
    const float* Wq   = (const float*)d_in[2];
    const float* bq   = (const float*)d_in[3];
    const float* Wk   = (const float*)d_in[4];
    const float* bk   = (const float*)d_in[5];
    const float* Wv   = (const float*)d_in[6];
    const float* bv   = (const float*)d_in[7];
    const float* Wo   = (const float*)d_in[8];
    const float* bo   = (const float*)d_in[9];
    float* out = (float*)d_out;
    (void)in_sizes; (void)n_in; (void)out_size;

    cudaFuncSetAttribute(qkv_mma_kernel,
                         cudaFuncAttributeMaxDynamicSharedMemorySize, GSMEM2);
    cudaFuncSetAttribute(oproj_mma_kernel,
                         cudaFuncAttributeMaxDynamicSharedMemorySize, GSMEM2);
    cudaFuncSetAttribute(attn_mma_kernel,
                         cudaFuncAttributeMaxDynamicSharedMemorySize, ASMEM2);

    cvt_x_kernel<<<(MROWS * EMBED) / 1024, 256>>>(x);
    cvt_w_kernel<<<dim3(32, 32, 4), dim3(32, 8)>>>(Wq, Wk, Wv, Wo);

    dim3 gq(EMBED / 128, MROWS / 128, 3);
    qkv_mma_kernel<<<gq, 256, GSMEM2>>>(bq, bk, bv);

    dim3 ga(SEQ / 128, NHEAD, BATCH);
    attn_mma_kernel<<<ga, 256, ASMEM2>>>(mask);

    dim3 go(EMBED / 128, MROWS / 128, 1);
    oproj_mma_kernel<<<go, 256, GSMEM2>>>(bo, out);
}

// round 12
// speedup vs baseline: 2.7409x; 1.0790x over previous
#include <cuda_runtime.h>
#include <cuda_bf16.h>
#include <cuda_fp16.h>
#include <cstdint>

#define EMBED 1024
#define NHEAD 16
#define HDIM  64
#define BATCH 2
#define SEQ   2048
#define MROWS (BATCH*SEQ)   // 4096

// ---------------------------------------------------------------------------
// Device-global scratch — single fp16 everywhere.
// Q pre-scaled by 0.125*log2(e) (base-2 softmax domain).
// ---------------------------------------------------------------------------
__device__ __half g_xf [MROWS*EMBED];                           // x  [m][k]
__device__ __half g_wf [4*EMBED*EMBED];                         // W^T [4][n][k]
__device__ __half g_qf [BATCH*NHEAD*SEQ*HDIM];                  // [b,h,s,d]
__device__ __half g_kf [BATCH*NHEAD*SEQ*HDIM];                  // [b,h,s,d]
__device__ __half g_vf [BATCH*NHEAD*HDIM*SEQ];                  // [b,h,d,s]
__device__ __half g_cf [MROWS*EMBED];                           // ctx [m][e]

// ---------------------------------------------------------------------------
// Helpers
// ---------------------------------------------------------------------------
__device__ __forceinline__ uint32_t smem_u32(const void* p) {
    uint32_t a;
    asm("{ .reg .u64 t; cvta.to.shared.u64 t, %1; cvt.u32.u64 %0, t; }"
        : "=r"(a) : "l"(p));
    return a;
}
__device__ __forceinline__ uint32_t pk2h(float e0, float e1) {  // f16x2, e0 low
    uint32_t d;
    asm("cvt.rn.f16x2.f32 %0, %1, %2;" : "=r"(d) : "f"(e1), "f"(e0));
    return d;
}
__device__ __forceinline__ float ex2(float x) {
    float r;
    asm("ex2.approx.f32 %0, %1;" : "=f"(r) : "f"(x));
    return r;
}
__device__ __forceinline__ uint32_t ex2h2(uint32_t x) {         // 2x fp16 exp2
    uint32_t d;
    asm("ex2.approx.f16x2 %0, %1;" : "=r"(d) : "r"(x));
    return d;
}

#define MMAF16(c, a, b0, b1)                                                \
    asm("mma.sync.aligned.m16n8k16.row.col.f32.f16.f16.f32 "                \
        "{%0,%1,%2,%3}, {%4,%5,%6,%7}, {%8,%9}, {%0,%1,%2,%3};"             \
        : "+f"((c)[0]), "+f"((c)[1]), "+f"((c)[2]), "+f"((c)[3])            \
        : "r"((a)[0]), "r"((a)[1]), "r"((a)[2]), "r"((a)[3]),               \
          "r"(b0), "r"(b1))

#define CP_ASYNC16(dst, src)                                                \
    asm volatile("cp.async.cg.shared.global [%0], [%1], 16;"                \
        :: "r"(dst), "l"(src) : "memory")
#define CP_COMMIT() asm volatile("cp.async.commit_group;" ::: "memory")
#define CP_WAIT(n)  asm volatile("cp.async.wait_group %0;" :: "n"(n) : "memory")

#define QSCALE 0.180336880111120419f   // 0.125 * log2(e)

// ---------------------------------------------------------------------------
// Conversion kernels
// ---------------------------------------------------------------------------
extern "C" __global__ void __launch_bounds__(256)
cvt_x_kernel(const float* __restrict__ src)
{
    int i = (blockIdx.x * 256 + threadIdx.x) * 4;
    float4 v = *reinterpret_cast<const float4*>(src + i);
    *reinterpret_cast<uint2*>(g_xf + i) =
        make_uint2(pk2h(v.x, v.y), pk2h(v.z, v.w));
}

extern "C" __global__ void __launch_bounds__(256)
cvt_w_kernel(const float* __restrict__ Wq, const float* __restrict__ Wk,
             const float* __restrict__ Wv, const float* __restrict__ Wo)
{
    __shared__ float t[32][33];
    const float* W = (blockIdx.z == 0) ? Wq : (blockIdx.z == 1) ? Wk :
                     (blockIdx.z == 2) ? Wv : Wo;
    __half* of = g_wf + (size_t)blockIdx.z * EMBED * EMBED;
    int bx = blockIdx.x * 32;  // n base
    int by = blockIdx.y * 32;  // k base
    int tx = threadIdx.x, ty = threadIdx.y;
#pragma unroll
    for (int i = 0; i < 4; i++) {
        int r = ty + i * 8;
        t[r][tx] = W[(size_t)(by + r) * EMBED + bx + tx];
    }
    __syncthreads();
#pragma unroll
    for (int i = 0; i < 4; i++) {
        int r = ty + i * 8;
        of[(size_t)(bx + r) * EMBED + by + tx] = __float2half_rn(t[tx][r]);
    }
}

// ---------------------------------------------------------------------------
// fp16 GEMM (projections): C[4096,1024] = A @ B^T (+bias)
// 256x128 block tile, BK=64, 8 warps (4m x 2n), warp tile 64x64.
// Halves L2 traffic per flop and A-fragment LDS per MMA vs 128x128.
// ---------------------------------------------------------------------------
#define GWA (256*36)
#define GWB (128*36)
#define GBUF (GWA + GWB)                 // 13824 words per buffer
#define GSMEM2 (2*GBUF*4)                // 110592 B

__device__ __forceinline__ void gemm_stage(
    uint32_t swb, int buf, int tid,
    const __half* sA, const __half* sB, int k0)
{
    const uint32_t dbase = swb + (uint32_t)(buf * GBUF) * 4;
#pragma unroll
    for (int j = 0; j < 8; j++) {        // A: 256 rows x 8 chunks
        int idx = tid + j * 256;
        int r = idx >> 3, c = idx & 7;
        uint32_t doff = (uint32_t)(r * 36 + c * 4) * 4;
        CP_ASYNC16(dbase + doff, sA + (size_t)r * EMBED + k0 + c * 8);
    }
#pragma unroll
    for (int j = 0; j < 4; j++) {        // B: 128 rows x 8 chunks
        int idx = tid + j * 256;
        int r = idx >> 3, c = idx & 7;
        uint32_t doff = (uint32_t)(GWA + r * 36 + c * 4) * 4;
        CP_ASYNC16(dbase + doff, sB + (size_t)r * EMBED + k0 + c * 8);
    }
}

__device__ __forceinline__ void gemm_mma_body(
    const __half* __restrict__ A, const __half* __restrict__ B,
    const float* __restrict__ bias, int mode, float* __restrict__ outf, float scale)
{
    extern __shared__ uint32_t sw[];
    const uint32_t swb = smem_u32(sw);
    const int tid = threadIdx.x;
    const int lane = tid & 31, wid = tid >> 5;
    const int g = lane >> 2, t = lane & 3;
    const int wm = wid & 3, wn = wid >> 2;
    const int m0 = blockIdx.y * 256, n0 = blockIdx.x * 128;

    const __half* sA = A + (size_t)m0 * EMBED;
    const __half* sB = B + (size_t)n0 * EMBED;

    float acc[4][8][4];
#pragma unroll
    for (int a = 0; a < 4; a++)
#pragma unroll
        for (int b = 0; b < 8; b++)
#pragma unroll
            for (int c = 0; c < 4; c++) acc[a][b][c] = 0.f;

    gemm_stage(swb, 0, tid, sA, sB, 0);
    CP_COMMIT();

    for (int it = 0; it < 16; it++) {
        const int buf = it & 1;
        __syncthreads();
        if (it + 1 < 16) {
            gemm_stage(swb, buf ^ 1, tid, sA, sB, (it + 1) * 64);
            CP_COMMIT();
            CP_WAIT(1);
        } else {
            CP_WAIT(0);
        }
        __syncthreads();

        uint32_t* As = sw + buf * GBUF;
        uint32_t* Bs = As + GWA;

#pragma unroll
        for (int ks = 0; ks < 4; ks++) {
            uint32_t ah[4][4];
#pragma unroll
            for (int mt = 0; mt < 4; mt++) {
                int r = wm * 64 + mt * 16 + g;
                int base = r * 36 + ks * 8 + t;
                ah[mt][0] = As[base];     ah[mt][1] = As[base + 8*36];
                ah[mt][2] = As[base + 4]; ah[mt][3] = As[base + 8*36 + 4];
            }
#pragma unroll
            for (int ntp = 0; ntp < 4; ntp++) {
                uint32_t b0[2], b1[2];
#pragma unroll
                for (int q = 0; q < 2; q++) {
                    int n = wn * 64 + (2 * ntp + q) * 8 + g;
                    int base = n * 36 + ks * 8 + t;
                    b0[q] = Bs[base]; b1[q] = Bs[base + 4];
                }
#pragma unroll
                for (int q = 0; q < 2; q++)
#pragma unroll
                    for (int mt = 0; mt < 4; mt++)
                        MMAF16(acc[mt][2*ntp+q], ah[mt], b0[q], b1[q]);
            }
        }
    }

    // epilogue
#pragma unroll
    for (int mt = 0; mt < 4; mt++) {
#pragma unroll
        for (int nt = 0; nt < 8; nt++) {
            int r0 = m0 + wm * 64 + mt * 16 + g;
            int r1 = r0 + 8;
            int c0 = n0 + wn * 64 + nt * 8 + 2 * t;
            float2 bb = *reinterpret_cast<const float2*>(&bias[c0]);
            float v0 = (acc[mt][nt][0] + bb.x) * scale;
            float v1 = (acc[mt][nt][1] + bb.y) * scale;
            float v2 = (acc[mt][nt][2] + bb.x) * scale;
            float v3 = (acc[mt][nt][3] + bb.y) * scale;
            if (mode == 0) {
                *reinterpret_cast<float2*>(&outf[(size_t)r0 * EMBED + c0]) = make_float2(v0, v1);
                *reinterpret_cast<float2*>(&outf[(size_t)r1 * EMBED + c0]) = make_float2(v2, v3);
            } else {
                int hh = c0 >> 6, d = c0 & 63;
                int b0i = r0 >> 11, s0i = r0 & (SEQ - 1);
                int b1i = r1 >> 11, s1i = r1 & (SEQ - 1);
                if (mode <= 2) {          // Q or K: fp16 [b,h,s,d]
                    __half* dst = (mode == 1) ? g_qf : g_kf;
                    size_t o0 = ((size_t)(b0i*NHEAD+hh)*SEQ + s0i)*HDIM + d;
                    size_t o1 = ((size_t)(b1i*NHEAD+hh)*SEQ + s1i)*HDIM + d;
                    *reinterpret_cast<uint32_t*>(dst + o0) = pk2h(v0, v1);
                    *reinterpret_cast<uint32_t*>(dst + o1) = pk2h(v2, v3);
                } else {                  // Vt: fp16, [b,h,d,s]
                    size_t base0 = (size_t)(b0i*NHEAD+hh)*HDIM*SEQ;
                    size_t base1 = (size_t)(b1i*NHEAD+hh)*HDIM*SEQ;
                    g_vf[base0 + (size_t)d * SEQ + s0i]     = __float2half_rn(v0);
                    g_vf[base0 + (size_t)(d+1) * SEQ + s0i] = __float2half_rn(v1);
                    g_vf[base1 + (size_t)d * SEQ + s1i]     = __float2half_rn(v2);
                    g_vf[base1 + (size_t)(d+1) * SEQ + s1i] = __float2half_rn(v3);
                }
            }
        }
    }
}

extern "C" __global__ void __launch_bounds__(256, 1)
qkv_mma_kernel(const float* __restrict__ bq, const float* __restrict__ bk,
               const float* __restrict__ bv)
{
    const int z = blockIdx.z;
    const __half* B = g_wf + (size_t)z * EMBED * EMBED;
    const float* bias = (z == 0) ? bq : (z == 1) ? bk : bv;
    int mode = (z == 0) ? 1 : (z == 1) ? 2 : 3;
    float scale = (z == 0) ? QSCALE : 1.0f;
    gemm_mma_body(g_xf, B, bias, mode, nullptr, scale);
}

extern "C" __global__ void __launch_bounds__(256, 1)
oproj_mma_kernel(const float* __restrict__ bo, float* __restrict__ out)
{
    gemm_mma_body(g_cf, g_wf + (size_t)3 * EMBED * EMBED, bo, 0, out, 1.0f);
}

// ---------------------------------------------------------------------------
// Flash attention:
//   - 3-stage cp.async pipeline, one __syncthreads per iter
//   - l via ones-row in V tile (MMA row-sum)
//   - exp via ex2.approx.f16x2, all exp work hoisted ahead of PV MMAs
//   - register-double-buffered K/V fragment prefetch inside MMA loops
// ---------------------------------------------------------------------------
#define KW (128*36)
#define VW2 (72*68)
#define ABUFW (KW + VW2)
#define NBUF 3
#define ASMEM2 ((NBUF*ABUFW + SEQ)*4)

__device__ __forceinline__ void attn_stage_kv(
    uint32_t swb, int buf, int tid,
    const __half* kf, const __half* vf, int s0)
{
    const uint32_t dbase = swb + (uint32_t)(buf * ABUFW) * 4;
#pragma unroll
    for (int j = 0; j < 4; j++) {
        int idx = tid + j * 256;
        {
            int r = idx >> 3, c = idx & 7;
            uint32_t doff = (uint32_t)(r * 36 + c * 4) * 4;
            CP_ASYNC16(dbase + doff, kf + (size_t)(s0 + r) * HDIM + c * 8);
        }
        {
            int d = idx >> 4, c = idx & 15;
            uint32_t doff = (uint32_t)(KW + d * 68 + c * 4) * 4;
            CP_ASYNC16(dbase + doff, vf + (size_t)d * SEQ + s0 + c * 8);
        }
    }
}

extern "C" __global__ void __launch_bounds__(256, 1)
attn_mma_kernel(const int* __restrict__ mask)
{
    extern __shared__ uint32_t sw[];
    const uint32_t swb = smem_u32(sw);
    float* mskf = reinterpret_cast<float*>(sw + NBUF * ABUFW);

    const int tid = threadIdx.x, lane = tid & 31, wid = tid >> 5;
    const int g = lane >> 2, t = lane & 3;
    const int b = blockIdx.z, h = blockIdx.y;
    const int q0 = blockIdx.x * 128;
    const int qw = wid * 16;
    const size_t bh = (size_t)(b * NHEAD + h);
    const __half* qfp = g_qf + bh * SEQ * HDIM;
    const __half* kfp = g_kf + bh * SEQ * HDIM;
    const __half* vfp = g_vf + bh * HDIM * SEQ;
    const int* mb = mask + b * SEQ;

#pragma unroll
    for (int i = 0; i < SEQ / 256; i++)
        mskf[tid + i * 256] = (float)mb[tid + i * 256];

    // ones-row (row 64 = 1.0) and zero rows (65..71), all buffers
    for (int i = tid; i < NBUF * 8 * 68; i += 256) {
        int bufi = i / (8 * 68);
        int rr = (i / 68) % 8;
        int cc = i % 68;
        sw[bufi * ABUFW + KW + (64 + rr) * 68 + cc] =
            (rr == 0) ? 0x3C003C00u : 0u;
    }

    // stage Q into buf0 K-area, extract fragments
#pragma unroll
    for (int j = 0; j < 4; j++) {
        int idx = tid + j * 256;
        int r = idx >> 3, c = idx & 7;
        uint32_t doff = (uint32_t)(r * 36 + c * 4) * 4;
        CP_ASYNC16(swb + doff, qfp + (size_t)(q0 + r) * HDIM + c * 8);
    }
    CP_COMMIT();
    CP_WAIT(0);
    __syncthreads();

    uint32_t qh[4][4];
#pragma unroll
    for (int ks = 0; ks < 4; ks++) {
#pragma unroll
        for (int p = 0; p < 4; p++) {
            int row = qw + g + ((p & 1) ? 8 : 0);
            int col = ks * 8 + t + ((p >= 2) ? 4 : 0);
            qh[ks][p] = sw[row * 36 + col];
        }
    }
    __syncthreads();

    attn_stage_kv(swb, 0, tid, kfp, vfp, 0);
    CP_COMMIT();
    attn_stage_kv(swb, 1, tid, kfp, vfp, 128);
    CP_COMMIT();

    float mrow[2] = {-1e30f, -1e30f};
    float o[8][4], ol[4];
#pragma unroll
    for (int i = 0; i < 8; i++)
#pragma unroll
        for (int j = 0; j < 4; j++) o[i][j] = 0.f;
#pragma unroll
    for (int j = 0; j < 4; j++) ol[j] = 0.f;

    for (int it = 0; it < 16; it++) {
        const int buf = it % 3;
        const int s0 = it * 128;
        CP_WAIT(1);
        __syncthreads();

        uint32_t* Ksh = sw + buf * ABUFW;
        uint32_t* Vth = Ksh + KW;

        // ---- S = Q K^T, fragments prefetched one group ahead
        float sc[16][4];
#pragma unroll
        for (int nt = 0; nt < 16; nt++)
#pragma unroll
            for (int j = 0; j < 4; j++) sc[nt][j] = 0.f;
        {
            uint32_t kb0[2][4], kb1[2][4];
#pragma unroll
            for (int q = 0; q < 4; q++) {            // preload group 0 (ks0,ng0)
                int base = (q * 8 + g) * 36 + t;
                kb0[0][q] = Ksh[base]; kb1[0][q] = Ksh[base + 4];
            }
#pragma unroll
            for (int idx = 0; idx < 16; idx++) {     // idx = ks*4 + ng
                const int cur = idx & 1;
                if (idx + 1 < 16) {
                    int ks1 = (idx + 1) >> 2, ng1 = (idx + 1) & 3;
#pragma unroll
                    for (int q = 0; q < 4; q++) {
                        int base = ((ng1 * 4 + q) * 8 + g) * 36 + ks1 * 8 + t;
                        kb0[cur ^ 1][q] = Ksh[base];
                        kb1[cur ^ 1][q] = Ksh[base + 4];
                    }
                }
                int ks = idx >> 2, ng = idx & 3;
#pragma unroll
                for (int q = 0; q < 4; q++)
                    MMAF16(sc[ng * 4 + q], qh[ks], kb0[cur][q], kb1[cur][q]);
            }
        }

        // ---- mask
#pragma unroll
        for (int nt = 0; nt < 16; nt++) {
            float2 mv = *reinterpret_cast<float2*>(&mskf[s0 + nt * 8 + 2 * t]);
            if (mv.x == 0.f) { sc[nt][0] = -1e30f; sc[nt][2] = -1e30f; }
            if (mv.y == 0.f) { sc[nt][1] = -1e30f; sc[nt][3] = -1e30f; }
        }

        // ---- online max + rescale
        float alpha[2];
#pragma unroll
        for (int rh = 0; rh < 2; rh++) {
            float mt_ = -1e30f;
#pragma unroll
            for (int nt = 0; nt < 16; nt++)
                mt_ = fmaxf(mt_, fmaxf(sc[nt][rh * 2 + 0], sc[nt][rh * 2 + 1]));
            mt_ = fmaxf(mt_, __shfl_xor_sync(0xffffffffu, mt_, 1));
            mt_ = fmaxf(mt_, __shfl_xor_sync(0xffffffffu, mt_, 2));
            float mn = fmaxf(mrow[rh], mt_);
            alpha[rh] = ex2(mrow[rh] - mn);
            mrow[rh] = mn;
        }
#pragma unroll
        for (int dt = 0; dt < 8; dt++) {
            o[dt][0] *= alpha[0]; o[dt][1] *= alpha[0];
            o[dt][2] *= alpha[1]; o[dt][3] *= alpha[1];
        }
        ol[0] *= alpha[0]; ol[1] *= alpha[0];
        ol[2] *= alpha[1]; ol[3] *= alpha[1];

        // ---- all exp work up front (sc dies into ph)
        uint32_t ph[8][4];
#pragma unroll
        for (int j = 0; j < 8; j++)
#pragma unroll
            for (int p = 0; p < 4; p++) {
                int nt = 2 * j + (p >> 1);
                int rh = p & 1;
                int ix = rh * 2;
                ph[j][p] = ex2h2(pk2h(sc[nt][ix]     - mrow[rh],
                                      sc[nt][ix + 1] - mrow[rh]));
            }

        // ---- O += P V, fragments prefetched one group ahead
        {
            uint32_t vb0[2][4], vb1[2][4];
#pragma unroll
            for (int q = 0; q < 4; q++) {            // preload group 0 (j0,dg0)
                int base = (q * 8 + g) * 68 + t;
                vb0[0][q] = Vth[base]; vb1[0][q] = Vth[base + 4];
            }
#pragma unroll
            for (int idx = 0; idx < 16; idx++) {     // idx = j*2 + dg
                const int cur = idx & 1;
                if (idx + 1 < 16) {
                    int j1 = (idx + 1) >> 1, dg1 = (idx + 1) & 1;
#pragma unroll
                    for (int q = 0; q < 4; q++) {
                        int base = ((dg1 * 4 + q) * 8 + g) * 68 + j1 * 8 + t;
                        vb0[cur ^ 1][q] = Vth[base];
                        vb1[cur ^ 1][q] = Vth[base + 4];
                    }
                }
                int j = idx >> 1, dg = idx & 1;
#pragma unroll
                for (int q = 0; q < 4; q++)
                    MMAF16(o[dg * 4 + q], ph[j], vb0[cur][q], vb1[cur][q]);
            }
        }
        // ---- l tiles (ones-row at 64)
#pragma unroll
        for (int j = 0; j < 8; j++) {
            int base = (64 + g) * 68 + j * 8 + t;
            MMAF16(ol, ph[j], Vth[base], Vth[base + 4]);
        }

        if (it + 2 < 16)
            attn_stage_kv(swb, (it + 2) % 3, tid, kfp, vfp, (it + 2) * 128);
        CP_COMMIT();
    }

    // ---- epilogue
    float l0 = __shfl_sync(0xffffffffu, ol[0], lane & 28);
    float l1 = __shfl_sync(0xffffffffu, ol[2], lane & 28);
    float inv0 = (l0 > 0.f) ? (1.f / l0) : 0.f;
    float inv1 = (l1 > 0.f) ? (1.f / l1) : 0.f;
    int r0 = q0 + qw + g, r1 = r0 + 8;
#pragma unroll
    for (int dt = 0; dt < 8; dt++) {
        int e = h * HDIM + dt * 8 + 2 * t;
        *reinterpret_cast<uint32_t*>(&g_cf[(size_t)(b * SEQ + r0) * EMBED + e]) =
            pk2h(o[dt][0] * inv0, o[dt][1] * inv0);
        *reinterpret_cast<uint32_t*>(&g_cf[(size_t)(b * SEQ + r1) * EMBED + e]) =
            pk2h(o[dt][2] * inv1, o[dt][3] * inv1);
    }
}

// ---------------------------------------------------------------------------
extern "C" void kernel_launch(void* const* d_in, const int* in_sizes, int n_in,
                              void* d_out, int out_size)
{
    const float* x    = (const float*)d_in[0];
    const int*   mask = (const int*)d_in[1];
    const float* Wq   = (const float*)d_in[2];
    const float* bq   = (const float*)d_in[3];
    const float* Wk   = (const float*)d_in[4];
    const float* bk   = (const float*)d_in[5];
    const float* Wv   = (const float*)d_in[6];
    const float* bv   = (const float*)d_in[7];
    const float* Wo   = (const float*)d_in[8];
    const float* bo   = (const float*)d_in[9];
    float* out = (float*)d_out;
    (void)in_sizes; (void)n_in; (void)out_size;

    cudaFuncSetAttribute(qkv_mma_kernel,
                         cudaFuncAttributeMaxDynamicSharedMemorySize, GSMEM2);
    cudaFuncSetAttribute(oproj_mma_kernel,
                         cudaFuncAttributeMaxDynamicSharedMemorySize, GSMEM2);
    cudaFuncSetAttribute(attn_mma_kernel,
                         cudaFuncAttributeMaxDynamicSharedMemorySize, ASMEM2);

    cvt_x_kernel<<<(MROWS * EMBED) / 1024, 256>>>(x);
    cvt_w_kernel<<<dim3(32, 32, 4), dim3(32, 8)>>>(Wq, Wk, Wv, Wo);

    dim3 gq(EMBED / 128, MROWS / 256, 3);   // 8 x 16 x 3
    qkv_mma_kernel<<<gq, 256, GSMEM2>>>(bq, bk, bv);

    dim3 ga(SEQ / 128, NHEAD, BATCH);
    attn_mma_kernel<<<ga, 256, ASMEM2>>>(mask);

    dim3 go(EMBED / 128, MROWS / 256, 1);   // 8 x 16
    oproj_mma_kernel<<<go, 256, GSMEM2>>>(bo, out);
}

// round 13
// speedup vs baseline: 2.8662x; 1.0457x over previous
#include <cuda_runtime.h>
#include <cuda_bf16.h>
#include <cuda_fp16.h>
#include <cstdint>

#define EMBED 1024
#define NHEAD 16
#define HDIM  64
#define BATCH 2
#define SEQ   2048
#define MROWS (BATCH*SEQ)   // 4096

// ---------------------------------------------------------------------------
// Device-global scratch — single fp16 everywhere.
// Q pre-scaled by 0.125*log2(e) (base-2 softmax domain).
// ---------------------------------------------------------------------------
__device__ __half g_xf [MROWS*EMBED];                           // x  [m][k]
__device__ __half g_wf [4*EMBED*EMBED];                         // W^T [4][n][k]
__device__ __half g_qf [BATCH*NHEAD*SEQ*HDIM];                  // [b,h,s,d]
__device__ __half g_kf [BATCH*NHEAD*SEQ*HDIM];                  // [b,h,s,d]
__device__ __half g_vf [BATCH*NHEAD*HDIM*SEQ];                  // [b,h,d,s]
__device__ __half g_cf [MROWS*EMBED];                           // ctx [m][e]

// ---------------------------------------------------------------------------
// Helpers
// ---------------------------------------------------------------------------
__device__ __forceinline__ uint32_t smem_u32(const void* p) {
    uint32_t a;
    asm("{ .reg .u64 t; cvta.to.shared.u64 t, %1; cvt.u32.u64 %0, t; }"
        : "=r"(a) : "l"(p));
    return a;
}
__device__ __forceinline__ uint32_t pk2h(float e0, float e1) {  // f16x2, e0 low
    uint32_t d;
    asm("cvt.rn.f16x2.f32 %0, %1, %2;" : "=r"(d) : "f"(e1), "f"(e0));
    return d;
}
__device__ __forceinline__ float ex2(float x) {
    float r;
    asm("ex2.approx.f32 %0, %1;" : "=f"(r) : "f"(x));
    return r;
}
__device__ __forceinline__ uint32_t ex2h2(uint32_t x) {         // 2x fp16 exp2
    uint32_t d;
    asm("ex2.approx.f16x2 %0, %1;" : "=r"(d) : "r"(x));
    return d;
}

#define MMAF16(c, a, b0, b1)                                                \
    asm("mma.sync.aligned.m16n8k16.row.col.f32.f16.f16.f32 "                \
        "{%0,%1,%2,%3}, {%4,%5,%6,%7}, {%8,%9}, {%0,%1,%2,%3};"             \
        : "+f"((c)[0]), "+f"((c)[1]), "+f"((c)[2]), "+f"((c)[3])            \
        : "r"((a)[0]), "r"((a)[1]), "r"((a)[2]), "r"((a)[3]),               \
          "r"(b0), "r"(b1))

#define CP_ASYNC16(dst, src)                                                \
    asm volatile("cp.async.cg.shared.global [%0], [%1], 16;"                \
        :: "r"(dst), "l"(src) : "memory")
#define CP_COMMIT() asm volatile("cp.async.commit_group;" ::: "memory")
#define CP_WAIT(n)  asm volatile("cp.async.wait_group %0;" :: "n"(n) : "memory")

#define QSCALE 0.180336880111120419f   // 0.125 * log2(e)

// ---------------------------------------------------------------------------
// Conversion kernels
// ---------------------------------------------------------------------------
extern "C" __global__ void __launch_bounds__(256)
cvt_x_kernel(const float* __restrict__ src)
{
    int i = (blockIdx.x * 256 + threadIdx.x) * 4;
    float4 v = *reinterpret_cast<const float4*>(src + i);
    *reinterpret_cast<uint2*>(g_xf + i) =
        make_uint2(pk2h(v.x, v.y), pk2h(v.z, v.w));
}

extern "C" __global__ void __launch_bounds__(256)
cvt_w_kernel(const float* __restrict__ Wq, const float* __restrict__ Wk,
             const float* __restrict__ Wv, const float* __restrict__ Wo)
{
    __shared__ float t[32][33];
    const float* W = (blockIdx.z == 0) ? Wq : (blockIdx.z == 1) ? Wk :
                     (blockIdx.z == 2) ? Wv : Wo;
    __half* of = g_wf + (size_t)blockIdx.z * EMBED * EMBED;
    int bx = blockIdx.x * 32;  // n base
    int by = blockIdx.y * 32;  // k base
    int tx = threadIdx.x, ty = threadIdx.y;
#pragma unroll
    for (int i = 0; i < 4; i++) {
        int r = ty + i * 8;
        t[r][tx] = W[(size_t)(by + r) * EMBED + bx + tx];
    }
    __syncthreads();
#pragma unroll
    for (int i = 0; i < 4; i++) {
        int r = ty + i * 8;
        of[(size_t)(bx + r) * EMBED + by + tx] = __float2half_rn(t[tx][r]);
    }
}

// ---------------------------------------------------------------------------
// fp16 GEMM (projections): 256x128 block tile — unchanged from R12
// ---------------------------------------------------------------------------
#define GWA (256*36)
#define GWB (128*36)
#define GBUF (GWA + GWB)
#define GSMEM2 (2*GBUF*4)                // 110592 B

__device__ __forceinline__ void gemm_stage(
    uint32_t swb, int buf, int tid,
    const __half* sA, const __half* sB, int k0)
{
    const uint32_t dbase = swb + (uint32_t)(buf * GBUF) * 4;
#pragma unroll
    for (int j = 0; j < 8; j++) {
        int idx = tid + j * 256;
        int r = idx >> 3, c = idx & 7;
        uint32_t doff = (uint32_t)(r * 36 + c * 4) * 4;
        CP_ASYNC16(dbase + doff, sA + (size_t)r * EMBED + k0 + c * 8);
    }
#pragma unroll
    for (int j = 0; j < 4; j++) {
        int idx = tid + j * 256;
        int r = idx >> 3, c = idx & 7;
        uint32_t doff = (uint32_t)(GWA + r * 36 + c * 4) * 4;
        CP_ASYNC16(dbase + doff, sB + (size_t)r * EMBED + k0 + c * 8);
    }
}

__device__ __forceinline__ void gemm_mma_body(
    const __half* __restrict__ A, const __half* __restrict__ B,
    const float* __restrict__ bias, int mode, float* __restrict__ outf, float scale)
{
    extern __shared__ uint32_t sw[];
    const uint32_t swb = smem_u32(sw);
    const int tid = threadIdx.x;
    const int lane = tid & 31, wid = tid >> 5;
    const int g = lane >> 2, t = lane & 3;
    const int wm = wid & 3, wn = wid >> 2;
    const int m0 = blockIdx.y * 256, n0 = blockIdx.x * 128;

    const __half* sA = A + (size_t)m0 * EMBED;
    const __half* sB = B + (size_t)n0 * EMBED;

    float acc[4][8][4];
#pragma unroll
    for (int a = 0; a < 4; a++)
#pragma unroll
        for (int b = 0; b < 8; b++)
#pragma unroll
            for (int c = 0; c < 4; c++) acc[a][b][c] = 0.f;

    gemm_stage(swb, 0, tid, sA, sB, 0);
    CP_COMMIT();

    for (int it = 0; it < 16; it++) {
        const int buf = it & 1;
        __syncthreads();
        if (it + 1 < 16) {
            gemm_stage(swb, buf ^ 1, tid, sA, sB, (it + 1) * 64);
            CP_COMMIT();
            CP_WAIT(1);
        } else {
            CP_WAIT(0);
        }
        __syncthreads();

        uint32_t* As = sw + buf * GBUF;
        uint32_t* Bs = As + GWA;

#pragma unroll
        for (int ks = 0; ks < 4; ks++) {
            uint32_t ah[4][4];
#pragma unroll
            for (int mt = 0; mt < 4; mt++) {
                int r = wm * 64 + mt * 16 + g;
                int base = r * 36 + ks * 8 + t;
                ah[mt][0] = As[base];     ah[mt][1] = As[base + 8*36];
                ah[mt][2] = As[base + 4]; ah[mt][3] = As[base + 8*36 + 4];
            }
#pragma unroll
            for (int ntp = 0; ntp < 4; ntp++) {
                uint32_t b0[2], b1[2];
#pragma unroll
                for (int q = 0; q < 2; q++) {
                    int n = wn * 64 + (2 * ntp + q) * 8 + g;
                    int base = n * 36 + ks * 8 + t;
                    b0[q] = Bs[base]; b1[q] = Bs[base + 4];
                }
#pragma unroll
                for (int q = 0; q < 2; q++)
#pragma unroll
                    for (int mt = 0; mt < 4; mt++)
                        MMAF16(acc[mt][2*ntp+q], ah[mt], b0[q], b1[q]);
            }
        }
    }

    // epilogue
#pragma unroll
    for (int mt = 0; mt < 4; mt++) {
#pragma unroll
        for (int nt = 0; nt < 8; nt++) {
            int r0 = m0 + wm * 64 + mt * 16 + g;
            int r1 = r0 + 8;
            int c0 = n0 + wn * 64 + nt * 8 + 2 * t;
            float2 bb = *reinterpret_cast<const float2*>(&bias[c0]);
            float v0 = (acc[mt][nt][0] + bb.x) * scale;
            float v1 = (acc[mt][nt][1] + bb.y) * scale;
            float v2 = (acc[mt][nt][2] + bb.x) * scale;
            float v3 = (acc[mt][nt][3] + bb.y) * scale;
            if (mode == 0) {
                *reinterpret_cast<float2*>(&outf[(size_t)r0 * EMBED + c0]) = make_float2(v0, v1);
                *reinterpret_cast<float2*>(&outf[(size_t)r1 * EMBED + c0]) = make_float2(v2, v3);
            } else {
                int hh = c0 >> 6, d = c0 & 63;
                int b0i = r0 >> 11, s0i = r0 & (SEQ - 1);
                int b1i = r1 >> 11, s1i = r1 & (SEQ - 1);
                if (mode <= 2) {
                    __half* dst = (mode == 1) ? g_qf : g_kf;
                    size_t o0 = ((size_t)(b0i*NHEAD+hh)*SEQ + s0i)*HDIM + d;
                    size_t o1 = ((size_t)(b1i*NHEAD+hh)*SEQ + s1i)*HDIM + d;
                    *reinterpret_cast<uint32_t*>(dst + o0) = pk2h(v0, v1);
                    *reinterpret_cast<uint32_t*>(dst + o1) = pk2h(v2, v3);
                } else {
                    size_t base0 = (size_t)(b0i*NHEAD+hh)*HDIM*SEQ;
                    size_t base1 = (size_t)(b1i*NHEAD+hh)*HDIM*SEQ;
                    g_vf[base0 + (size_t)d * SEQ + s0i]     = __float2half_rn(v0);
                    g_vf[base0 + (size_t)(d+1) * SEQ + s0i] = __float2half_rn(v1);
                    g_vf[base1 + (size_t)d * SEQ + s1i]     = __float2half_rn(v2);
                    g_vf[base1 + (size_t)(d+1) * SEQ + s1i] = __float2half_rn(v3);
                }
            }
        }
    }
}

extern "C" __global__ void __launch_bounds__(256, 1)
qkv_mma_kernel(const float* __restrict__ bq, const float* __restrict__ bk,
               const float* __restrict__ bv)
{
    const int z = blockIdx.z;
    const __half* B = g_wf + (size_t)z * EMBED * EMBED;
    const float* bias = (z == 0) ? bq : (z == 1) ? bk : bv;
    int mode = (z == 0) ? 1 : (z == 1) ? 2 : 3;
    float scale = (z == 0) ? QSCALE : 1.0f;
    gemm_mma_body(g_xf, B, bias, mode, nullptr, scale);
}

extern "C" __global__ void __launch_bounds__(256, 1)
oproj_mma_kernel(const float* __restrict__ bo, float* __restrict__ out)
{
    gemm_mma_body(g_cf, g_wf + (size_t)3 * EMBED * EMBED, bo, 0, out, 1.0f);
}

// ---------------------------------------------------------------------------
// Flash attention — 128-thread CTAs (4 warps, q-tile 64), 2 CTAs per SM.
// Per-warp math identical to R12 (m16 q-tile, ones-row l, f16x2 exp).
// Double-buffered K/V (NBUF=2) to fit two CTAs' smem on one SM.
// ---------------------------------------------------------------------------
#define ATH 128                          // threads per attention CTA
#define KW (128*36)
#define VW2 (72*68)
#define ABUFW (KW + VW2)                 // 9504 words per buffer
#define ASMEM2 ((2*ABUFW + SEQ)*4)       // 84224 B  (x2 CTAs = 168448 <= smem)

__device__ __forceinline__ void attn_stage_kv(
    uint32_t swb, int buf, int tid,
    const __half* kf, const __half* vf, int s0)
{
    const uint32_t dbase = swb + (uint32_t)(buf * ABUFW) * 4;
#pragma unroll
    for (int j = 0; j < 8; j++) {
        int idx = tid + j * ATH;
        {
            int r = idx >> 3, c = idx & 7;
            uint32_t doff = (uint32_t)(r * 36 + c * 4) * 4;
            CP_ASYNC16(dbase + doff, kf + (size_t)(s0 + r) * HDIM + c * 8);
        }
        {
            int d = idx >> 4, c = idx & 15;
            uint32_t doff = (uint32_t)(KW + d * 68 + c * 4) * 4;
            CP_ASYNC16(dbase + doff, vf + (size_t)d * SEQ + s0 + c * 8);
        }
    }
}

extern "C" __global__ void __launch_bounds__(ATH, 2)
attn_mma_kernel(const int* __restrict__ mask)
{
    extern __shared__ uint32_t sw[];
    const uint32_t swb = smem_u32(sw);
    float* mskf = reinterpret_cast<float*>(sw + 2 * ABUFW);

    const int tid = threadIdx.x, lane = tid & 31, wid = tid >> 5;
    const int g = lane >> 2, t = lane & 3;
    const int b = blockIdx.z, h = blockIdx.y;
    const int q0 = blockIdx.x * 64;            // q-tile 64
    const int qw = wid * 16;                   // 4 warps x m16
    const size_t bh = (size_t)(b * NHEAD + h);
    const __half* qfp = g_qf + bh * SEQ * HDIM;
    const __half* kfp = g_kf + bh * SEQ * HDIM;
    const __half* vfp = g_vf + bh * HDIM * SEQ;
    const int* mb = mask + b * SEQ;

    // mask row to smem
#pragma unroll
    for (int i = 0; i < SEQ / ATH; i++)
        mskf[tid + i * ATH] = (float)mb[tid + i * ATH];

    // ones-row (row 64 = 1.0) and zero rows (65..71), both buffers
    for (int i = tid; i < 2 * 8 * 68; i += ATH) {
        int bufi = i / (8 * 68);
        int rr = (i / 68) % 8;
        int cc = i % 68;
        sw[bufi * ABUFW + KW + (64 + rr) * 68 + cc] =
            (rr == 0) ? 0x3C003C00u : 0u;
    }

    // stage Q (64 rows) into buf0 K-area, extract fragments
#pragma unroll
    for (int j = 0; j < 4; j++) {
        int idx = tid + j * ATH;
        int r = idx >> 3, c = idx & 7;
        uint32_t doff = (uint32_t)(r * 36 + c * 4) * 4;
        CP_ASYNC16(swb + doff, qfp + (size_t)(q0 + r) * HDIM + c * 8);
    }
    CP_COMMIT();
    CP_WAIT(0);
    __syncthreads();

    uint32_t qh[4][4];
#pragma unroll
    for (int ks = 0; ks < 4; ks++) {
#pragma unroll
        for (int p = 0; p < 4; p++) {
            int row = qw + g + ((p & 1) ? 8 : 0);
            int col = ks * 8 + t + ((p >= 2) ? 4 : 0);
            qh[ks][p] = sw[row * 36 + col];
        }
    }
    __syncthreads();

    attn_stage_kv(swb, 0, tid, kfp, vfp, 0);
    CP_COMMIT();

    float mrow[2] = {-1e30f, -1e30f};
    float o[8][4], ol[4];
#pragma unroll
    for (int i = 0; i < 8; i++)
#pragma unroll
        for (int j = 0; j < 4; j++) o[i][j] = 0.f;
#pragma unroll
    for (int j = 0; j < 4; j++) ol[j] = 0.f;

    for (int it = 0; it < 16; it++) {
        const int buf = it & 1;
        const int s0 = it * 128;
        __syncthreads();
        if (it + 1 < 16) {
            attn_stage_kv(swb, buf ^ 1, tid, kfp, vfp, (it + 1) * 128);
            CP_COMMIT();
            CP_WAIT(1);
        } else {
            CP_WAIT(0);
        }
        __syncthreads();

        uint32_t* Ksh = sw + buf * ABUFW;
        uint32_t* Vth = Ksh + KW;

        // ---- S = Q K^T, fragments prefetched one group ahead
        float sc[16][4];
#pragma unroll
        for (int nt = 0; nt < 16; nt++)
#pragma unroll
            for (int j = 0; j < 4; j++) sc[nt][j] = 0.f;
        {
            uint32_t kb0[2][4], kb1[2][4];
#pragma unroll
            for (int q = 0; q < 4; q++) {
                int base = (q * 8 + g) * 36 + t;
                kb0[0][q] = Ksh[base]; kb1[0][q] = Ksh[base + 4];
            }
#pragma unroll
            for (int idx = 0; idx < 16; idx++) {     // idx = ks*4 + ng
                const int cur = idx & 1;
                if (idx + 1 < 16) {
                    int ks1 = (idx + 1) >> 2, ng1 = (idx + 1) & 3;
#pragma unroll
                    for (int q = 0; q < 4; q++) {
                        int base = ((ng1 * 4 + q) * 8 + g) * 36 + ks1 * 8 + t;
                        kb0[cur ^ 1][q] = Ksh[base];
                        kb1[cur ^ 1][q] = Ksh[base + 4];
                    }
                }
                int ks = idx >> 2, ng = idx & 3;
#pragma unroll
                for (int q = 0; q < 4; q++)
                    MMAF16(sc[ng * 4 + q], qh[ks], kb0[cur][q], kb1[cur][q]);
            }
        }

        // ---- mask
#pragma unroll
        for (int nt = 0; nt < 16; nt++) {
            float2 mv = *reinterpret_cast<float2*>(&mskf[s0 + nt * 8 + 2 * t]);
            if (mv.x == 0.f) { sc[nt][0] = -1e30f; sc[nt][2] = -1e30f; }
            if (mv.y == 0.f) { sc[nt][1] = -1e30f; sc[nt][3] = -1e30f; }
        }

        // ---- online max + rescale
        float alpha[2];
#pragma unroll
        for (int rh = 0; rh < 2; rh++) {
            float mt_ = -1e30f;
#pragma unroll
            for (int nt = 0; nt < 16; nt++)
                mt_ = fmaxf(mt_, fmaxf(sc[nt][rh * 2 + 0], sc[nt][rh * 2 + 1]));
            mt_ = fmaxf(mt_, __shfl_xor_sync(0xffffffffu, mt_, 1));
            mt_ = fmaxf(mt_, __shfl_xor_sync(0xffffffffu, mt_, 2));
            float mn = fmaxf(mrow[rh], mt_);
            alpha[rh] = ex2(mrow[rh] - mn);
            mrow[rh] = mn;
        }
#pragma unroll
        for (int dt = 0; dt < 8; dt++) {
            o[dt][0] *= alpha[0]; o[dt][1] *= alpha[0];
            o[dt][2] *= alpha[1]; o[dt][3] *= alpha[1];
        }
        ol[0] *= alpha[0]; ol[1] *= alpha[0];
        ol[2] *= alpha[1]; ol[3] *= alpha[1];

        // ---- exp work up front (sc dies into ph)
        uint32_t ph[8][4];
#pragma unroll
        for (int j = 0; j < 8; j++)
#pragma unroll
            for (int p = 0; p < 4; p++) {
                int nt = 2 * j + (p >> 1);
                int rh = p & 1;
                int ix = rh * 2;
                ph[j][p] = ex2h2(pk2h(sc[nt][ix]     - mrow[rh],
                                      sc[nt][ix + 1] - mrow[rh]));
            }

        // ---- O += P V, fragments prefetched one group ahead
        {
            uint32_t vb0[2][4], vb1[2][4];
#pragma unroll
            for (int q = 0; q < 4; q++) {
                int base = (q * 8 + g) * 68 + t;
                vb0[0][q] = Vth[base]; vb1[0][q] = Vth[base + 4];
            }
#pragma unroll
            for (int idx = 0; idx < 16; idx++) {     // idx = j*2 + dg
                const int cur = idx & 1;
                if (idx + 1 < 16) {
                    int j1 = (idx + 1) >> 1, dg1 = (idx + 1) & 1;
#pragma unroll
                    for (int q = 0; q < 4; q++) {
                        int base = ((dg1 * 4 + q) * 8 + g) * 68 + j1 * 8 + t;
                        vb0[cur ^ 1][q] = Vth[base];
                        vb1[cur ^ 1][q] = Vth[base + 4];
                    }
                }
                int j = idx >> 1, dg = idx & 1;
#pragma unroll
                for (int q = 0; q < 4; q++)
                    MMAF16(o[dg * 4 + q], ph[j], vb0[cur][q], vb1[cur][q]);
            }
        }
        // ---- l tiles (ones-row at 64)
#pragma unroll
        for (int j = 0; j < 8; j++) {
            int base = (64 + g) * 68 + j * 8 + t;
            MMAF16(ol, ph[j], Vth[base], Vth[base + 4]);
        }
    }

    // ---- epilogue
    float l0 = __shfl_sync(0xffffffffu, ol[0], lane & 28);
    float l1 = __shfl_sync(0xffffffffu, ol[2], lane & 28);
    float inv0 = (l0 > 0.f) ? (1.f / l0) : 0.f;
    float inv1 = (l1 > 0.f) ? (1.f / l1) : 0.f;
    int r0 = q0 + qw + g, r1 = r0 + 8;
#pragma unroll
    for (int dt = 0; dt < 8; dt++) {
        int e = h * HDIM + dt * 8 + 2 * t;
        *reinterpret_cast<uint32_t*>(&g_cf[(size_t)(b * SEQ + r0) * EMBED + e]) =
            pk2h(o[dt][0] * inv0, o[dt][1] * inv0);
        *reinterpret_cast<uint32_t*>(&g_cf[(size_t)(b * SEQ + r1) * EMBED + e]) =
            pk2h(o[dt][2] * inv1, o[dt][3] * inv1);
    }
}

// ---------------------------------------------------------------------------
extern "C" void kernel_launch(void* const* d_in, const int* in_sizes, int n_in,
                              void* d_out, int out_size)
{
    const float* x    = (const float*)d_in[0];
    const int*   mask = (const int*)d_in[1];
    const float* Wq   = (const float*)d_in[2];
    const float* bq   = (const float*)d_in[3];
    const float* Wk   = (const float*)d_in[4];
    const float* bk   = (const float*)d_in[5];
    const float* Wv   = (const float*)d_in[6];
    const float* bv   = (const float*)d_in[7];
    const float* Wo   = (const float*)d_in[8];
    const float* bo   = (const float*)d_in[9];
    float* out = (float*)d_out;
    (void)in_sizes; (void)n_in; (void)out_size;

    cudaFuncSetAttribute(qkv_mma_kernel,
                         cudaFuncAttributeMaxDynamicSharedMemorySize, GSMEM2);
    cudaFuncSetAttribute(oproj_mma_kernel,
                         cudaFuncAttributeMaxDynamicSharedMemorySize, GSMEM2);
    cudaFuncSetAttribute(attn_mma_kernel,
                         cudaFuncAttributeMaxDynamicSharedMemorySize, ASMEM2);

    cvt_x_kernel<<<(MROWS * EMBED) / 1024, 256>>>(x);
    cvt_w_kernel<<<dim3(32, 32, 4), dim3(32, 8)>>>(Wq, Wk, Wv, Wo);

    dim3 gq(EMBED / 128, MROWS / 256, 3);   // 8 x 16 x 3
    qkv_mma_kernel<<<gq, 256, GSMEM2>>>(bq, bk, bv);

    dim3 ga(SEQ / 64, NHEAD, BATCH);        // 32 x 16 x 2 = 1024 CTAs
    attn_mma_kernel<<<ga, ATH, ASMEM2>>>(mask);

    dim3 go(EMBED / 128, MROWS / 256, 1);   // 8 x 16
    oproj_mma_kernel<<<go, 256, GSMEM2>>>(bo, out);
}

// round 14
// speedup vs baseline: 2.8865x; 1.0071x over previous
#include <cuda_runtime.h>
#include <cuda_bf16.h>
#include <cuda_fp16.h>
#include <cstdint>

#define EMBED 1024
#define NHEAD 16
#define HDIM  64
#define BATCH 2
#define SEQ   2048
#define MROWS (BATCH*SEQ)   // 4096

// ---------------------------------------------------------------------------
// Device-global scratch — single fp16 everywhere.
// Q pre-scaled by 0.125*log2(e) (base-2 softmax domain).
// ---------------------------------------------------------------------------
__device__ __half g_xf [MROWS*EMBED];                           // x  [m][k]
__device__ __half g_wf [4*EMBED*EMBED];                         // W^T [4][n][k]
__device__ __half g_qf [BATCH*NHEAD*SEQ*HDIM];                  // [b,h,s,d]
__device__ __half g_kf [BATCH*NHEAD*SEQ*HDIM];                  // [b,h,s,d]
__device__ __half g_vf [BATCH*NHEAD*HDIM*SEQ];                  // [b,h,d,s]
__device__ __half g_cf [MROWS*EMBED];                           // ctx [m][e]

// ---------------------------------------------------------------------------
// Helpers
// ---------------------------------------------------------------------------
__device__ __forceinline__ uint32_t smem_u32(const void* p) {
    uint32_t a;
    asm("{ .reg .u64 t; cvta.to.shared.u64 t, %1; cvt.u32.u64 %0, t; }"
        : "=r"(a) : "l"(p));
    return a;
}
__device__ __forceinline__ uint32_t pk2h(float e0, float e1) {  // f16x2, e0 low
    uint32_t d;
    asm("cvt.rn.f16x2.f32 %0, %1, %2;" : "=r"(d) : "f"(e1), "f"(e0));
    return d;
}
__device__ __forceinline__ float ex2(float x) {
    float r;
    asm("ex2.approx.f32 %0, %1;" : "=f"(r) : "f"(x));
    return r;
}
__device__ __forceinline__ uint32_t ex2h2(uint32_t x) {         // 2x fp16 exp2
    uint32_t d;
    asm("ex2.approx.f16x2 %0, %1;" : "=r"(d) : "r"(x));
    return d;
}

#define MMAF16(c, a, b0, b1)                                                \
    asm("mma.sync.aligned.m16n8k16.row.col.f32.f16.f16.f32 "                \
        "{%0,%1,%2,%3}, {%4,%5,%6,%7}, {%8,%9}, {%0,%1,%2,%3};"             \
        : "+f"((c)[0]), "+f"((c)[1]), "+f"((c)[2]), "+f"((c)[3])            \
        : "r"((a)[0]), "r"((a)[1]), "r"((a)[2]), "r"((a)[3]),               \
          "r"(b0), "r"(b1))

#define CP_ASYNC16(dst, src)                                                \
    asm volatile("cp.async.cg.shared.global [%0], [%1], 16;"                \
        :: "r"(dst), "l"(src) : "memory")
#define CP_COMMIT() asm volatile("cp.async.commit_group;" ::: "memory")
#define CP_WAIT(n)  asm volatile("cp.async.wait_group %0;" :: "n"(n) : "memory")

#define QSCALE 0.180336880111120419f   // 0.125 * log2(e)

// ---------------------------------------------------------------------------
// Conversion kernels
// ---------------------------------------------------------------------------
extern "C" __global__ void __launch_bounds__(256)
cvt_x_kernel(const float* __restrict__ src)
{
    int i = (blockIdx.x * 256 + threadIdx.x) * 4;
    float4 v = *reinterpret_cast<const float4*>(src + i);
    *reinterpret_cast<uint2*>(g_xf + i) =
        make_uint2(pk2h(v.x, v.y), pk2h(v.z, v.w));
}

extern "C" __global__ void __launch_bounds__(256)
cvt_w_kernel(const float* __restrict__ Wq, const float* __restrict__ Wk,
             const float* __restrict__ Wv, const float* __restrict__ Wo)
{
    __shared__ float t[32][33];
    const float* W = (blockIdx.z == 0) ? Wq : (blockIdx.z == 1) ? Wk :
                     (blockIdx.z == 2) ? Wv : Wo;
    __half* of = g_wf + (size_t)blockIdx.z * EMBED * EMBED;
    int bx = blockIdx.x * 32;  // n base
    int by = blockIdx.y * 32;  // k base
    int tx = threadIdx.x, ty = threadIdx.y;
#pragma unroll
    for (int i = 0; i < 4; i++) {
        int r = ty + i * 8;
        t[r][tx] = W[(size_t)(by + r) * EMBED + bx + tx];
    }
    __syncthreads();
#pragma unroll
    for (int i = 0; i < 4; i++) {
        int r = ty + i * 8;
        of[(size_t)(bx + r) * EMBED + by + tx] = __float2half_rn(t[tx][r]);
    }
}

// ---------------------------------------------------------------------------
// fp16 GEMM (projections): 128x128 block tile, 128 threads (2x2 warps),
// warp tile 64x64, 2 CTAs per SM (phase decoupling).
// Per-output accumulation order identical to R12/R13 -> bit-identical result.
// ---------------------------------------------------------------------------
#define GTH 128
#define GWT (128*36)                     // words per array (A or B) per buffer
#define GBUF (2*GWT)                     // 9216 words per buffer
#define GSMEM2 (2*GBUF*4)                // 73728 B (x2 CTAs = 147456)

__device__ __forceinline__ void gemm_stage(
    uint32_t swb, int buf, int tid,
    const __half* sA, const __half* sB, int k0)
{
    const uint32_t dbase = swb + (uint32_t)(buf * GBUF) * 4;
#pragma unroll
    for (int j = 0; j < 8; j++) {        // A: 128 rows x 8 chunks = 1024
        int idx = tid + j * GTH;
        int r = idx >> 3, c = idx & 7;
        uint32_t doff = (uint32_t)(r * 36 + c * 4) * 4;
        CP_ASYNC16(dbase + doff, sA + (size_t)r * EMBED + k0 + c * 8);
    }
#pragma unroll
    for (int j = 0; j < 8; j++) {        // B: 128 rows x 8 chunks = 1024
        int idx = tid + j * GTH;
        int r = idx >> 3, c = idx & 7;
        uint32_t doff = (uint32_t)(GWT + r * 36 + c * 4) * 4;
        CP_ASYNC16(dbase + doff, sB + (size_t)r * EMBED + k0 + c * 8);
    }
}

__device__ __forceinline__ void gemm_mma_body(
    const __half* __restrict__ A, const __half* __restrict__ B,
    const float* __restrict__ bias, int mode, float* __restrict__ outf, float scale)
{
    extern __shared__ uint32_t sw[];
    const uint32_t swb = smem_u32(sw);
    const int tid = threadIdx.x;
    const int lane = tid & 31, wid = tid >> 5;
    const int g = lane >> 2, t = lane & 3;
    const int wm = wid & 1, wn = wid >> 1;          // 2x2 warp grid
    const int m0 = blockIdx.y * 128, n0 = blockIdx.x * 128;

    const __half* sA = A + (size_t)m0 * EMBED;
    const __half* sB = B + (size_t)n0 * EMBED;

    float acc[4][8][4];
#pragma unroll
    for (int a = 0; a < 4; a++)
#pragma unroll
        for (int b = 0; b < 8; b++)
#pragma unroll
            for (int c = 0; c < 4; c++) acc[a][b][c] = 0.f;

    gemm_stage(swb, 0, tid, sA, sB, 0);
    CP_COMMIT();

    for (int it = 0; it < 16; it++) {
        const int buf = it & 1;
        __syncthreads();
        if (it + 1 < 16) {
            gemm_stage(swb, buf ^ 1, tid, sA, sB, (it + 1) * 64);
            CP_COMMIT();
            CP_WAIT(1);
        } else {
            CP_WAIT(0);
        }
        __syncthreads();

        uint32_t* As = sw + buf * GBUF;
        uint32_t* Bs = As + GWT;

#pragma unroll
        for (int ks = 0; ks < 4; ks++) {
            uint32_t ah[4][4];
#pragma unroll
            for (int mt = 0; mt < 4; mt++) {
                int r = wm * 64 + mt * 16 + g;
                int base = r * 36 + ks * 8 + t;
                ah[mt][0] = As[base];     ah[mt][1] = As[base + 8*36];
                ah[mt][2] = As[base + 4]; ah[mt][3] = As[base + 8*36 + 4];
            }
#pragma unroll
            for (int ntp = 0; ntp < 4; ntp++) {
                uint32_t b0[2], b1[2];
#pragma unroll
                for (int q = 0; q < 2; q++) {
                    int n = wn * 64 + (2 * ntp + q) * 8 + g;
                    int base = n * 36 + ks * 8 + t;
                    b0[q] = Bs[base]; b1[q] = Bs[base + 4];
                }
#pragma unroll
                for (int q = 0; q < 2; q++)
#pragma unroll
                    for (int mt = 0; mt < 4; mt++)
                        MMAF16(acc[mt][2*ntp+q], ah[mt], b0[q], b1[q]);
            }
        }
    }

    // epilogue
#pragma unroll
    for (int mt = 0; mt < 4; mt++) {
#pragma unroll
        for (int nt = 0; nt < 8; nt++) {
            int r0 = m0 + wm * 64 + mt * 16 + g;
            int r1 = r0 + 8;
            int c0 = n0 + wn * 64 + nt * 8 + 2 * t;
            float2 bb = *reinterpret_cast<const float2*>(&bias[c0]);
            float v0 = (acc[mt][nt][0] + bb.x) * scale;
            float v1 = (acc[mt][nt][1] + bb.y) * scale;
            float v2 = (acc[mt][nt][2] + bb.x) * scale;
            float v3 = (acc[mt][nt][3] + bb.y) * scale;
            if (mode == 0) {
                *reinterpret_cast<float2*>(&outf[(size_t)r0 * EMBED + c0]) = make_float2(v0, v1);
                *reinterpret_cast<float2*>(&outf[(size_t)r1 * EMBED + c0]) = make_float2(v2, v3);
            } else {
                int hh = c0 >> 6, d = c0 & 63;
                int b0i = r0 >> 11, s0i = r0 & (SEQ - 1);
                int b1i = r1 >> 11, s1i = r1 & (SEQ - 1);
                if (mode <= 2) {
                    __half* dst = (mode == 1) ? g_qf : g_kf;
                    size_t o0 = ((size_t)(b0i*NHEAD+hh)*SEQ + s0i)*HDIM + d;
                    size_t o1 = ((size_t)(b1i*NHEAD+hh)*SEQ + s1i)*HDIM + d;
                    *reinterpret_cast<uint32_t*>(dst + o0) = pk2h(v0, v1);
                    *reinterpret_cast<uint32_t*>(dst + o1) = pk2h(v2, v3);
                } else {
                    size_t base0 = (size_t)(b0i*NHEAD+hh)*HDIM*SEQ;
                    size_t base1 = (size_t)(b1i*NHEAD+hh)*HDIM*SEQ;
                    g_vf[base0 + (size_t)d * SEQ + s0i]     = __float2half_rn(v0);
                    g_vf[base0 + (size_t)(d+1) * SEQ + s0i] = __float2half_rn(v1);
                    g_vf[base1 + (size_t)d * SEQ + s1i]     = __float2half_rn(v2);
                    g_vf[base1 + (size_t)(d+1) * SEQ + s1i] = __float2half_rn(v3);
                }
            }
        }
    }
}

extern "C" __global__ void __launch_bounds__(GTH, 2)
qkv_mma_kernel(const float* __restrict__ bq, const float* __restrict__ bk,
               const float* __restrict__ bv)
{
    const int z = blockIdx.z;
    const __half* B = g_wf + (size_t)z * EMBED * EMBED;
    const float* bias = (z == 0) ? bq : (z == 1) ? bk : bv;
    int mode = (z == 0) ? 1 : (z == 1) ? 2 : 3;
    float scale = (z == 0) ? QSCALE : 1.0f;
    gemm_mma_body(g_xf, B, bias, mode, nullptr, scale);
}

extern "C" __global__ void __launch_bounds__(GTH, 2)
oproj_mma_kernel(const float* __restrict__ bo, float* __restrict__ out)
{
    gemm_mma_body(g_cf, g_wf + (size_t)3 * EMBED * EMBED, bo, 0, out, 1.0f);
}

// ---------------------------------------------------------------------------
// Flash attention — unchanged from R13 (128-thread CTAs, 2/SM, q-tile 64)
// ---------------------------------------------------------------------------
#define ATH 128
#define KW (128*36)
#define VW2 (72*68)
#define ABUFW (KW + VW2)
#define ASMEM2 ((2*ABUFW + SEQ)*4)       // 84224 B

__device__ __forceinline__ void attn_stage_kv(
    uint32_t swb, int buf, int tid,
    const __half* kf, const __half* vf, int s0)
{
    const uint32_t dbase = swb + (uint32_t)(buf * ABUFW) * 4;
#pragma unroll
    for (int j = 0; j < 8; j++) {
        int idx = tid + j * ATH;
        {
            int r = idx >> 3, c = idx & 7;
            uint32_t doff = (uint32_t)(r * 36 + c * 4) * 4;
            CP_ASYNC16(dbase + doff, kf + (size_t)(s0 + r) * HDIM + c * 8);
        }
        {
            int d = idx >> 4, c = idx & 15;
            uint32_t doff = (uint32_t)(KW + d * 68 + c * 4) * 4;
            CP_ASYNC16(dbase + doff, vf + (size_t)d * SEQ + s0 + c * 8);
        }
    }
}

extern "C" __global__ void __launch_bounds__(ATH, 2)
attn_mma_kernel(const int* __restrict__ mask)
{
    extern __shared__ uint32_t sw[];
    const uint32_t swb = smem_u32(sw);
    float* mskf = reinterpret_cast<float*>(sw + 2 * ABUFW);

    const int tid = threadIdx.x, lane = tid & 31, wid = tid >> 5;
    const int g = lane >> 2, t = lane & 3;
    const int b = blockIdx.z, h = blockIdx.y;
    const int q0 = blockIdx.x * 64;
    const int qw = wid * 16;
    const size_t bh = (size_t)(b * NHEAD + h);
    const __half* qfp = g_qf + bh * SEQ * HDIM;
    const __half* kfp = g_kf + bh * SEQ * HDIM;
    const __half* vfp = g_vf + bh * HDIM * SEQ;
    const int* mb = mask + b * SEQ;

#pragma unroll
    for (int i = 0; i < SEQ / ATH; i++)
        mskf[tid + i * ATH] = (float)mb[tid + i * ATH];

    for (int i = tid; i < 2 * 8 * 68; i += ATH) {
        int bufi = i / (8 * 68);
        int rr = (i / 68) % 8;
        int cc = i % 68;
        sw[bufi * ABUFW + KW + (64 + rr) * 68 + cc] =
            (rr == 0) ? 0x3C003C00u : 0u;
    }

#pragma unroll
    for (int j = 0; j < 4; j++) {
        int idx = tid + j * ATH;
        int r = idx >> 3, c = idx & 7;
        uint32_t doff = (uint32_t)(r * 36 + c * 4) * 4;
        CP_ASYNC16(swb + doff, qfp + (size_t)(q0 + r) * HDIM + c * 8);
    }
    CP_COMMIT();
    CP_WAIT(0);
    __syncthreads();

    uint32_t qh[4][4];
#pragma unroll
    for (int ks = 0; ks < 4; ks++) {
#pragma unroll
        for (int p = 0; p < 4; p++) {
            int row = qw + g + ((p & 1) ? 8 : 0);
            int col = ks * 8 + t + ((p >= 2) ? 4 : 0);
            qh[ks][p] = sw[row * 36 + col];
        }
    }
    __syncthreads();

    attn_stage_kv(swb, 0, tid, kfp, vfp, 0);
    CP_COMMIT();

    float mrow[2] = {-1e30f, -1e30f};
    float o[8][4], ol[4];
#pragma unroll
    for (int i = 0; i < 8; i++)
#pragma unroll
        for (int j = 0; j < 4; j++) o[i][j] = 0.f;
#pragma unroll
    for (int j = 0; j < 4; j++) ol[j] = 0.f;

    for (int it = 0; it < 16; it++) {
        const int buf = it & 1;
        const int s0 = it * 128;
        __syncthreads();
        if (it + 1 < 16) {
            attn_stage_kv(swb, buf ^ 1, tid, kfp, vfp, (it + 1) * 128);
            CP_COMMIT();
            CP_WAIT(1);
        } else {
            CP_WAIT(0);
        }
        __syncthreads();

        uint32_t* Ksh = sw + buf * ABUFW;
        uint32_t* Vth = Ksh + KW;

        float sc[16][4];
#pragma unroll
        for (int nt = 0; nt < 16; nt++)
#pragma unroll
            for (int j = 0; j < 4; j++) sc[nt][j] = 0.f;
        {
            uint32_t kb0[2][4], kb1[2][4];
#pragma unroll
            for (int q = 0; q < 4; q++) {
                int base = (q * 8 + g) * 36 + t;
                kb0[0][q] = Ksh[base]; kb1[0][q] = Ksh[base + 4];
            }
#pragma unroll
            for (int idx = 0; idx < 16; idx++) {
                const int cur = idx & 1;
                if (idx + 1 < 16) {
                    int ks1 = (idx + 1) >> 2, ng1 = (idx + 1) & 3;
#pragma unroll
                    for (int q = 0; q < 4; q++) {
                        int base = ((ng1 * 4 + q) * 8 + g) * 36 + ks1 * 8 + t;
                        kb0[cur ^ 1][q] = Ksh[base];
                        kb1[cur ^ 1][q] = Ksh[base + 4];
                    }
                }
                int ks = idx >> 2, ng = idx & 3;
#pragma unroll
                for (int q = 0; q < 4; q++)
                    MMAF16(sc[ng * 4 + q], qh[ks], kb0[cur][q], kb1[cur][q]);
            }
        }

#pragma unroll
        for (int nt = 0; nt < 16; nt++) {
            float2 mv = *reinterpret_cast<float2*>(&mskf[s0 + nt * 8 + 2 * t]);
            if (mv.x == 0.f) { sc[nt][0] = -1e30f; sc[nt][2] = -1e30f; }
            if (mv.y == 0.f) { sc[nt][1] = -1e30f; sc[nt][3] = -1e30f; }
        }

        float alpha[2];
#pragma unroll
        for (int rh = 0; rh < 2; rh++) {
            float mt_ = -1e30f;
#pragma unroll
            for (int nt = 0; nt < 16; nt++)
                mt_ = fmaxf(mt_, fmaxf(sc[nt][rh * 2 + 0], sc[nt][rh * 2 + 1]));
            mt_ = fmaxf(mt_, __shfl_xor_sync(0xffffffffu, mt_, 1));
            mt_ = fmaxf(mt_, __shfl_xor_sync(0xffffffffu, mt_, 2));
            float mn = fmaxf(mrow[rh], mt_);
            alpha[rh] = ex2(mrow[rh] - mn);
            mrow[rh] = mn;
        }
#pragma unroll
        for (int dt = 0; dt < 8; dt++) {
            o[dt][0] *= alpha[0]; o[dt][1] *= alpha[0];
            o[dt][2] *= alpha[1]; o[dt][3] *= alpha[1];
        }
        ol[0] *= alpha[0]; ol[1] *= alpha[0];
        ol[2] *= alpha[1]; ol[3] *= alpha[1];

        uint32_t ph[8][4];
#pragma unroll
        for (int j = 0; j < 8; j++)
#pragma unroll
            for (int p = 0; p < 4; p++) {
                int nt = 2 * j + (p >> 1);
                int rh = p & 1;
                int ix = rh * 2;
                ph[j][p] = ex2h2(pk2h(sc[nt][ix]     - mrow[rh],
                                      sc[nt][ix + 1] - mrow[rh]));
            }

        {
            uint32_t vb0[2][4], vb1[2][4];
#pragma unroll
            for (int q = 0; q < 4; q++) {
                int base = (q * 8 + g) * 68 + t;
                vb0[0][q] = Vth[base]; vb1[0][q] = Vth[base + 4];
            }
#pragma unroll
            for (int idx = 0; idx < 16; idx++) {
                const int cur = idx & 1;
                if (idx + 1 < 16) {
                    int j1 = (idx + 1) >> 1, dg1 = (idx + 1) & 1;
#pragma unroll
                    for (int q = 0; q < 4; q++) {
                        int base = ((dg1 * 4 + q) * 8 + g) * 68 + j1 * 8 + t;
                        vb0[cur ^ 1][q] = Vth[base];
                        vb1[cur ^ 1][q] = Vth[base + 4];
                    }
                }
                int j = idx >> 1, dg = idx & 1;
#pragma unroll
                for (int q = 0; q < 4; q++)
                    MMAF16(o[dg * 4 + q], ph[j], vb0[cur][q], vb1[cur][q]);
            }
        }
#pragma unroll
        for (int j = 0; j < 8; j++) {
            int base = (64 + g) * 68 + j * 8 + t;
            MMAF16(ol, ph[j], Vth[base], Vth[base + 4]);
        }
    }

    float l0 = __shfl_sync(0xffffffffu, ol[0], lane & 28);
    float l1 = __shfl_sync(0xffffffffu, ol[2], lane & 28);
    float inv0 = (l0 > 0.f) ? (1.f / l0) : 0.f;
    float inv1 = (l1 > 0.f) ? (1.f / l1) : 0.f;
    int r0 = q0 + qw + g, r1 = r0 + 8;
#pragma unroll
    for (int dt = 0; dt < 8; dt++) {
        int e = h * HDIM + dt * 8 + 2 * t;
        *reinterpret_cast<uint32_t*>(&g_cf[(size_t)(b * SEQ + r0) * EMBED + e]) =
            pk2h(o[dt][0] * inv0, o[dt][1] * inv0);
        *reinterpret_cast<uint32_t*>(&g_cf[(size_t)(b * SEQ + r1) * EMBED + e]) =
            pk2h(o[dt][2] * inv1, o[dt][3] * inv1);
    }
}

// ---------------------------------------------------------------------------
extern "C" void kernel_launch(void* const* d_in, const int* in_sizes, int n_in,
                              void* d_out, int out_size)
{
    const float* x    = (const float*)d_in[0];
    const int*   mask = (const int*)d_in[1];
    const float* Wq   = (const float*)d_in[2];
    const float* bq   = (const float*)d_in[3];
    const float* Wk   = (const float*)d_in[4];
    const float* bk   = (const float*)d_in[5];
    const float* Wv   = (const float*)d_in[6];
    const float* bv   = (const float*)d_in[7];
    const float* Wo   = (const float*)d_in[8];
    const float* bo   = (const float*)d_in[9];
    float* out = (float*)d_out;
    (void)in_sizes; (void)n_in; (void)out_size;

    cudaFuncSetAttribute(qkv_mma_kernel,
                         cudaFuncAttributeMaxDynamicSharedMemorySize, GSMEM2);
    cudaFuncSetAttribute(oproj_mma_kernel,
                         cudaFuncAttributeMaxDynamicSharedMemorySize, GSMEM2);
    cudaFuncSetAttribute(attn_mma_kernel,
                         cudaFuncAttributeMaxDynamicSharedMemorySize, ASMEM2);

    cvt_x_kernel<<<(MROWS * EMBED) / 1024, 256>>>(x);
    cvt_w_kernel<<<dim3(32, 32, 4), dim3(32, 8)>>>(Wq, Wk, Wv, Wo);

    dim3 gq(EMBED / 128, MROWS / 128, 3);   // 8 x 32 x 3 = 768 CTAs
    qkv_mma_kernel<<<gq, GTH, GSMEM2>>>(bq, bk, bv);

    dim3 ga(SEQ / 64, NHEAD, BATCH);        // 32 x 16 x 2 = 1024 CTAs
    attn_mma_kernel<<<ga, ATH, ASMEM2>>>(mask);

    dim3 go(EMBED / 128, MROWS / 128, 1);   // 8 x 32 = 256 CTAs
    oproj_mma_kernel<<<go, GTH, GSMEM2>>>(bo, out);
}